// round 2
// baseline (speedup 1.0000x reference)
#include <cuda_runtime.h>
#include <math.h>

#define LSEQ 16384
#define DIN  256
#define DD   768
#define D2   1536
#define NL   8
#define NCHUNK 128
#define CLEN   128

// ---------------- scratch (static device globals; no allocation) ----------------
__device__ float g_x[(size_t)LSEQ * DD];
__device__ float g_h[(size_t)LSEQ * DD];
__device__ float g_u[(size_t)LSEQ * DD];
__device__ float g_gate[(size_t)LSEQ * DD];
__device__ float g_s[(size_t)LSEQ * DD];
__device__ float g_t[(size_t)LSEQ * D2];
__device__ float g_S[NCHUNK * DD];
__device__ float g_carry[NCHUNK * DD];

__device__ __forceinline__ float sigmoidf_(float z) {
    return 1.0f / (1.0f + __expf(-z));
}

// ---------------- SGEMM: C[M,N] = act(A[M,K] @ B[K,N] + bias) (+= if RESID) ----
// BM=128, BN=128, BK=8, 256 threads, 8x8 per thread, double-buffered smem.
// ACT: 0 none, 1 sigmoid, 2 silu
template<int ACT, bool RESID>
__global__ __launch_bounds__(256) void sgemm_kernel(
    const float* __restrict__ A, const float* __restrict__ B,
    const float* __restrict__ bias, float* __restrict__ C,
    int M, int N, int K)
{
    __shared__ float As[2][8][128];
    __shared__ float Bs[2][8][128];

    const int tid = threadIdx.x;
    const int row0 = blockIdx.y * 128;
    const int col0 = blockIdx.x * 128;
    const int tx = tid & 15;      // 0..15
    const int ty = tid >> 4;      // 0..15

    // A tile loader: 128 rows x 8 cols -> one float4 per thread
    const int aRow = tid >> 1;            // 0..127
    const int aCol = (tid & 1) * 4;       // 0 or 4
    // B tile loader: 8 rows x 128 cols -> one float4 per thread
    const int bRow = tid >> 5;            // 0..7
    const int bCol = (tid & 31) * 4;      // 0..124

    const float* Aptr = A + (size_t)(row0 + aRow) * K + aCol;
    const float* Bptr = B + (size_t)bRow * N + col0 + bCol;

    float acc[8][8];
#pragma unroll
    for (int i = 0; i < 8; i++)
#pragma unroll
        for (int j = 0; j < 8; j++) acc[i][j] = 0.0f;

    // preload tile 0 into buffer 0
    {
        float4 a = *(const float4*)(Aptr);
        As[0][aCol + 0][aRow] = a.x;
        As[0][aCol + 1][aRow] = a.y;
        As[0][aCol + 2][aRow] = a.z;
        As[0][aCol + 3][aRow] = a.w;
        float4 b = *(const float4*)(Bptr);
        *(float4*)&Bs[0][bRow][bCol] = b;
    }
    __syncthreads();

    int buf = 0;
    for (int k0 = 8; k0 <= K; k0 += 8) {
        // prefetch next tile into registers (overlaps with compute below)
        float4 an, bn;
        const bool has = (k0 < K);
        if (has) {
            an = *(const float4*)(Aptr + k0);
            bn = *(const float4*)(Bptr + (size_t)k0 * N);
        }

        // compute on current buffer
#pragma unroll
        for (int k = 0; k < 8; k++) {
            float ar[8], br[8];
#pragma unroll
            for (int i = 0; i < 8; i++) ar[i] = As[buf][k][ty * 8 + i];
#pragma unroll
            for (int j = 0; j < 8; j++) br[j] = Bs[buf][k][tx * 8 + j];
#pragma unroll
            for (int i = 0; i < 8; i++)
#pragma unroll
                for (int j = 0; j < 8; j++)
                    acc[i][j] = fmaf(ar[i], br[j], acc[i][j]);
        }

        // stage prefetched tile into the other buffer
        if (has) {
            const int nb = buf ^ 1;
            As[nb][aCol + 0][aRow] = an.x;
            As[nb][aCol + 1][aRow] = an.y;
            As[nb][aCol + 2][aRow] = an.z;
            As[nb][aCol + 3][aRow] = an.w;
            *(float4*)&Bs[nb][bRow][bCol] = bn;
            __syncthreads();
            buf = nb;
        }
    }

#pragma unroll
    for (int i = 0; i < 8; i++) {
        const int r = row0 + ty * 8 + i;
        float* Crow = C + (size_t)r * N + col0 + tx * 8;
#pragma unroll
        for (int j = 0; j < 8; j++) {
            const int c = col0 + tx * 8 + j;
            float v = acc[i][j] + bias[c];
            if (ACT == 1) v = sigmoidf_(v);
            else if (ACT == 2) v = v * sigmoidf_(v);
            if (RESID) Crow[j] += v;
            else       Crow[j] = v;
        }
    }
}

// ---------------- LayerNorm over D=768, one block (256 thr) per row -----------
__global__ __launch_bounds__(256) void ln_kernel(
    const float* __restrict__ x, const float* __restrict__ gam,
    const float* __restrict__ bet, float* __restrict__ out)
{
    __shared__ float red[8];
    __shared__ float bcast;
    const int tid = threadIdx.x;
    const float* xr = x + (size_t)blockIdx.x * DD;

    float v0 = xr[tid], v1 = xr[tid + 256], v2 = xr[tid + 512];

    float sum = v0 + v1 + v2;
#pragma unroll
    for (int o = 16; o > 0; o >>= 1) sum += __shfl_xor_sync(0xffffffffu, sum, o);
    if ((tid & 31) == 0) red[tid >> 5] = sum;
    __syncthreads();
    if (tid == 0) {
        float t = 0.f;
#pragma unroll
        for (int i = 0; i < 8; i++) t += red[i];
        bcast = t * (1.0f / DD);
    }
    __syncthreads();
    const float mu = bcast;

    float d0 = v0 - mu, d1 = v1 - mu, d2 = v2 - mu;
    float sq = d0 * d0 + d1 * d1 + d2 * d2;
#pragma unroll
    for (int o = 16; o > 0; o >>= 1) sq += __shfl_xor_sync(0xffffffffu, sq, o);
    __syncthreads();                       // protect red reuse
    if ((tid & 31) == 0) red[tid >> 5] = sq;
    __syncthreads();
    if (tid == 0) {
        float t = 0.f;
#pragma unroll
        for (int i = 0; i < 8; i++) t += red[i];
        bcast = rsqrtf(t * (1.0f / DD) + 1e-5f);
    }
    __syncthreads();
    const float inv = bcast;

    float* orow = out + (size_t)blockIdx.x * DD;
    orow[tid]       = d0 * inv * gam[tid]       + bet[tid];
    orow[tid + 256] = d1 * inv * gam[tid + 256] + bet[tid + 256];
    orow[tid + 512] = d2 * inv * gam[tid + 512] + bet[tid + 512];
}

// ---------------- Scan pass 1: per-(chunk, channel) local scan, zero carry ----
__global__ __launch_bounds__(256) void scan_chunk_kernel(
    const float* __restrict__ u, const float* __restrict__ dlogit,
    float* __restrict__ Sout)
{
    const int d = blockIdx.x * 256 + threadIdx.x;   // channel
    const int c = blockIdx.y;                       // chunk
    const float decay = sigmoidf_(dlogit[d]);
    const float* p = u + ((size_t)c * CLEN) * DD + d;
    float s = 0.0f;
#pragma unroll 8
    for (int t = 0; t < CLEN; t++) s = fmaf(decay, s, p[(size_t)t * DD]);
    Sout[c * DD + d] = s;
}

// ---------------- Scan pass 2: serial carry across 128 chunks (768 threads) ---
__global__ __launch_bounds__(768) void scan_carry_kernel(
    const float* __restrict__ Sin, const float* __restrict__ dlogit,
    float* __restrict__ carry)
{
    const int d = threadIdx.x;
    const float decay = sigmoidf_(dlogit[d]);
    float A = decay;
#pragma unroll
    for (int i = 0; i < 7; i++) A = A * A;          // decay^128
    float c = 0.0f;
    for (int k = 0; k < NCHUNK; k++) {
        carry[k * DD + d] = c;
        c = fmaf(A, c, Sin[k * DD + d]);
    }
}

// ---------------- Scan pass 3: re-scan with carry, multiply by gate -----------
__global__ __launch_bounds__(256) void scan_apply_kernel(
    const float* __restrict__ u, const float* __restrict__ gate,
    const float* __restrict__ dlogit, const float* __restrict__ carry,
    float* __restrict__ out)
{
    const int d = blockIdx.x * 256 + threadIdx.x;
    const int c = blockIdx.y;
    const float decay = sigmoidf_(dlogit[d]);
    const size_t base = ((size_t)c * CLEN) * DD + d;
    float s = carry[c * DD + d];
#pragma unroll 8
    for (int t = 0; t < CLEN; t++) {
        const size_t idx = base + (size_t)t * DD;
        s = fmaf(decay, s, u[idx]);
        out[idx] = s * gate[idx];
    }
}

// ---------------- host ---------------------------------------------------------
extern "C" void kernel_launch(void* const* d_in, const int* in_sizes, int n_in,
                              void* d_out, int out_size)
{
    const float* node    = (const float*)d_in[0];
    const float* W_proj  = (const float*)d_in[1];
    const float* b_proj  = (const float*)d_in[2];
    const float* ln_s_g  = (const float*)d_in[3];
    const float* ln_s_b  = (const float*)d_in[4];
    const float* W_in    = (const float*)d_in[5];
    const float* b_in    = (const float*)d_in[6];
    const float* W_gate  = (const float*)d_in[7];
    const float* b_gate  = (const float*)d_in[8];
    const float* W_out   = (const float*)d_in[9];
    const float* b_out   = (const float*)d_in[10];
    const float* dlogit  = (const float*)d_in[11];
    const float* ln_f_g  = (const float*)d_in[12];
    const float* ln_f_b  = (const float*)d_in[13];
    const float* W_ff1   = (const float*)d_in[14];
    const float* b_ff1   = (const float*)d_in[15];
    const float* W_ff2   = (const float*)d_in[16];
    const float* b_ff2   = (const float*)d_in[17];
    const float* ln_o_g  = (const float*)d_in[18];
    const float* ln_o_b  = (const float*)d_in[19];

    float *x, *h, *u, *gate, *s, *t, *S, *carry;
    cudaGetSymbolAddress((void**)&x,     g_x);
    cudaGetSymbolAddress((void**)&h,     g_h);
    cudaGetSymbolAddress((void**)&u,     g_u);
    cudaGetSymbolAddress((void**)&gate,  g_gate);
    cudaGetSymbolAddress((void**)&s,     g_s);
    cudaGetSymbolAddress((void**)&t,     g_t);
    cudaGetSymbolAddress((void**)&S,     g_S);
    cudaGetSymbolAddress((void**)&carry, g_carry);

    const dim3 blk(256);
    const dim3 gD (DD / 128, LSEQ / 128);    // N=768
    const dim3 gD2(D2 / 128, LSEQ / 128);    // N=1536
    const dim3 gScan(DD / 256, NCHUNK);

    // x = node @ W_proj + b_proj
    sgemm_kernel<0, false><<<gD, blk>>>(node, W_proj, b_proj, x, LSEQ, DD, DIN);

    for (int l = 0; l < NL; l++) {
        const size_t wo = (size_t)l * DD * DD;
        const size_t vo = (size_t)l * DD;
        const size_t w1 = (size_t)l * DD * D2;
        const size_t v1 = (size_t)l * D2;
        const size_t w2 = (size_t)l * D2 * DD;

        // h = LN_s(x)
        ln_kernel<<<LSEQ, blk>>>(x, ln_s_g + vo, ln_s_b + vo, h);
        // u = h @ W_in + b_in ; gate = sigmoid(h @ W_gate + b_gate)
        sgemm_kernel<0, false><<<gD, blk>>>(h, W_in   + wo, b_in   + vo, u,    LSEQ, DD, DD);
        sgemm_kernel<1, false><<<gD, blk>>>(h, W_gate + wo, b_gate + vo, gate, LSEQ, DD, DD);
        // chunked scan: states*gate -> s
        scan_chunk_kernel<<<gScan, blk>>>(u, dlogit + vo, S);
        scan_carry_kernel<<<1, DD>>>(S, dlogit + vo, carry);
        scan_apply_kernel<<<gScan, blk>>>(u, gate, dlogit + vo, carry, s);
        // x += s @ W_out + b_out
        sgemm_kernel<0, true><<<gD, blk>>>(s, W_out + wo, b_out + vo, x, LSEQ, DD, DD);
        // hf = LN_f(x)
        ln_kernel<<<LSEQ, blk>>>(x, ln_f_g + vo, ln_f_b + vo, h);
        // t = silu(hf @ W_ff1 + b_ff1) ; x += t @ W_ff2 + b_ff2
        sgemm_kernel<2, false><<<gD2, blk>>>(h, W_ff1 + w1, b_ff1 + v1, t, LSEQ, D2, DD);
        sgemm_kernel<0, true><<<gD,  blk>>>(t, W_ff2 + w2, b_ff2 + vo, x, LSEQ, DD, D2);
    }

    // out = LN_o(x)
    ln_kernel<<<LSEQ, blk>>>(x, ln_o_g, ln_o_b, (float*)d_out);
}

// round 4
// speedup vs baseline: 1.5430x; 1.5430x over previous
#include <cuda_runtime.h>
#include <cuda_bf16.h>
#include <math.h>

#define LSEQ 16384
#define DIN  256
#define DD   768
#define D2   1536
#define NL   8
#define NCHUNK 128
#define CLEN   128

// ---------------- fp32 scratch ----------------
__device__ float g_x[(size_t)LSEQ * DD];
__device__ float g_u[(size_t)LSEQ * DD];
__device__ float g_gate[(size_t)LSEQ * DD];
__device__ float g_S[NCHUNK * DD];
__device__ float g_carry[NCHUNK * DD];

// ---- bf16 split activations: A-layout [hi | lo | hi], row stride 3K ----
__device__ __nv_bfloat16 ab_node[(size_t)LSEQ * 3 * DIN];
__device__ __nv_bfloat16 ab_h[(size_t)LSEQ * 3 * DD];
__device__ __nv_bfloat16 ab_s[(size_t)LSEQ * 3 * DD];
__device__ __nv_bfloat16 ab_t[(size_t)LSEQ * 3 * D2];

// ---- bf16 split weights: B-layout [N, 3K] K-major, [hi | hi | lo] ----
__device__ __nv_bfloat16 wb_proj[(size_t)DD * 3 * DIN];
__device__ __nv_bfloat16 wb_in  [(size_t)NL * DD * 3 * DD];
__device__ __nv_bfloat16 wb_gate[(size_t)NL * DD * 3 * DD];
__device__ __nv_bfloat16 wb_out [(size_t)NL * DD * 3 * DD];
__device__ __nv_bfloat16 wb_ff1 [(size_t)NL * D2 * 3 * DD];
__device__ __nv_bfloat16 wb_ff2 [(size_t)NL * DD * 3 * D2];

// ================= helpers =================
__device__ __forceinline__ float sigmoidf_(float z) {
    return 1.0f / (1.0f + __expf(-z));
}

__device__ __forceinline__ unsigned smem_u32(const void* p) {
    unsigned a;
    asm("{ .reg .u64 t; cvta.to.shared.u64 t, %1; cvt.u32.u64 %0, t; }"
        : "=r"(a) : "l"(p));
    return a;
}

__device__ __forceinline__ void cpasync16(unsigned s, const void* g) {
    asm volatile("cp.async.cg.shared.global [%0], [%1], 16;"
                 :: "r"(s), "l"(g) : "memory");
}
__device__ __forceinline__ void cp_commit() {
    asm volatile("cp.async.commit_group;" ::: "memory");
}
__device__ __forceinline__ void cp_wait1() {
    asm volatile("cp.async.wait_group 1;" ::: "memory");
}
__device__ __forceinline__ void cp_wait0() {
    asm volatile("cp.async.wait_group 0;" ::: "memory");
}

__device__ __forceinline__ void ldsm4(unsigned* r, unsigned addr) {
    asm volatile("ldmatrix.sync.aligned.m8n8.x4.shared.b16 {%0,%1,%2,%3}, [%4];"
                 : "=r"(r[0]), "=r"(r[1]), "=r"(r[2]), "=r"(r[3]) : "r"(addr));
}

__device__ __forceinline__ void mma16816(float* d, const unsigned* a,
                                         unsigned b0, unsigned b1) {
    asm volatile(
        "mma.sync.aligned.m16n8k16.row.col.f32.bf16.bf16.f32 "
        "{%0,%1,%2,%3}, {%4,%5,%6,%7}, {%8,%9}, {%0,%1,%2,%3};"
        : "+f"(d[0]), "+f"(d[1]), "+f"(d[2]), "+f"(d[3])
        : "r"(a[0]), "r"(a[1]), "r"(a[2]), "r"(a[3]), "r"(b0), "r"(b1));
}

__device__ __forceinline__ void split_bf16(float v, __nv_bfloat16& hi, __nv_bfloat16& lo) {
    hi = __float2bfloat16(v);
    lo = __float2bfloat16(v - __bfloat162float(hi));
}

// ================= tensor-core GEMM (mma.sync bf16) =================
// C[M,N] = epilogue(A'[M,Kp] @ B'[N,Kp]^T + bias), Kp = 3*K split layout.
// Tile 128x128xBK64, 256 threads, 8 warps 4(M)x2(N), warp tile 32x64.
// Smem rows 128B, chunk swizzle c^(row&7). 2-stage cp.async pipeline.
// ACT: 0 none, 1 sigmoid, 2 silu.  RESID: Cf += v.  SPLIT: bf16 [hi|lo|hi] to Cs.
#define GEMM_SMEM_BYTES 65536

template<int ACT, bool RESID, bool SPLIT>
__global__ __launch_bounds__(256) void tc_gemm(
    const __nv_bfloat16* __restrict__ A, const __nv_bfloat16* __restrict__ B,
    const float* __restrict__ bias, float* __restrict__ Cf,
    __nv_bfloat16* __restrict__ Cs, int Kp, int N)
{
    extern __shared__ __align__(1024) char smem[];
    const unsigned sbase = smem_u32(smem);
    const int tid  = threadIdx.x;
    const int wid  = tid >> 5;
    const int lane = tid & 31;

    const int row0 = blockIdx.y * 128;
    const int col0 = blockIdx.x * 128;
    const __nv_bfloat16* Ab = A + (size_t)row0 * Kp;
    const __nv_bfloat16* Bb = B + (size_t)col0 * Kp;

    const int m0 = (wid & 3) * 32;   // warp M offset
    const int n0 = (wid >> 2) * 64;  // warp N offset

    float acc[2][8][4];
#pragma unroll
    for (int i = 0; i < 2; i++)
#pragma unroll
        for (int j = 0; j < 8; j++)
#pragma unroll
            for (int q = 0; q < 4; q++) acc[i][j][q] = 0.0f;

    // loader mapping: row = tid>>1 (0..127), chunks (tid&1)*4 + 0..3
    const int lrow = tid >> 1;
    const int lc0  = (tid & 1) * 4;
    const __nv_bfloat16* agp = Ab + (size_t)lrow * Kp;
    const __nv_bfloat16* bgp = Bb + (size_t)lrow * Kp;

    const int NC = Kp / 64;

#define ISSUE_TILE(ct, s) do {                                              \
        const unsigned sA_ = sbase + (unsigned)(s) * 32768u;                \
        const unsigned sB_ = sA_ + 16384u;                                  \
        const int kb_ = (ct) * 64;                                          \
        _Pragma("unroll")                                                   \
        for (int i_ = 0; i_ < 4; i_++) {                                    \
            const int c_ = lc0 + i_;                                        \
            const unsigned off_ = (unsigned)(lrow * 128 + ((c_ ^ (lrow & 7)) << 4)); \
            cpasync16(sA_ + off_, agp + kb_ + c_ * 8);                      \
            cpasync16(sB_ + off_, bgp + kb_ + c_ * 8);                      \
        }                                                                   \
    } while (0)

    ISSUE_TILE(0, 0);
    cp_commit();

    for (int c = 0; c < NC; c++) {
        const int buf = c & 1;
        const bool more = (c + 1 < NC);
        if (more) { ISSUE_TILE(c + 1, buf ^ 1); cp_commit(); }
        if (more) cp_wait1(); else cp_wait0();
        __syncthreads();

        const unsigned sA = sbase + (unsigned)buf * 32768u;
        const unsigned sB = sA + 16384u;

#pragma unroll
        for (int kk4 = 0; kk4 < 4; kk4++) {      // k16 steps within tile
            const int cb = kk4 * 2;              // chunk base (8-elem chunks)
            unsigned afr[2][4], bfr[4][4];
#pragma unroll
            for (int mt = 0; mt < 2; mt++) {
                const int r = m0 + mt * 16 + (lane & 15);
                const int ch = cb + (lane >> 4);
                ldsm4(afr[mt], sA + r * 128 + ((ch ^ (r & 7)) << 4));
            }
#pragma unroll
            for (int jp = 0; jp < 4; jp++) {
                const int rn = n0 + jp * 16 + ((lane >> 4) << 3) + (lane & 7);
                const int ch = cb + ((lane >> 3) & 1);
                ldsm4(bfr[jp], sB + rn * 128 + ((ch ^ (rn & 7)) << 4));
            }
#pragma unroll
            for (int mt = 0; mt < 2; mt++)
#pragma unroll
                for (int nt = 0; nt < 8; nt++)
                    mma16816(acc[mt][nt], afr[mt],
                             bfr[nt >> 1][(nt & 1) * 2],
                             bfr[nt >> 1][(nt & 1) * 2 + 1]);
        }
        __syncthreads();
    }
#undef ISSUE_TILE

    // ---------------- epilogue ----------------
    const int g  = lane >> 2;
    const int t4 = lane & 3;
#pragma unroll
    for (int nt = 0; nt < 8; nt++) {
        const int col = col0 + n0 + nt * 8 + 2 * t4;
        const float b0 = bias[col];
        const float b1 = bias[col + 1];
#pragma unroll
        for (int mt = 0; mt < 2; mt++) {
            const int rtop = row0 + m0 + mt * 16 + g;
#pragma unroll
            for (int half = 0; half < 2; half++) {
                const int r = rtop + half * 8;
                float v0 = acc[mt][nt][half * 2 + 0] + b0;
                float v1 = acc[mt][nt][half * 2 + 1] + b1;
                if (ACT == 1) { v0 = sigmoidf_(v0); v1 = sigmoidf_(v1); }
                else if (ACT == 2) { v0 = v0 * sigmoidf_(v0); v1 = v1 * sigmoidf_(v1); }
                if (SPLIT) {
                    __nv_bfloat16* orow = Cs + (size_t)r * (3 * N);
                    __nv_bfloat16 h0, l0, h1, l1;
                    split_bf16(v0, h0, l0);
                    split_bf16(v1, h1, l1);
                    *(__nv_bfloat162*)(orow + col)         = __nv_bfloat162(h0, h1);
                    *(__nv_bfloat162*)(orow + N + col)     = __nv_bfloat162(l0, l1);
                    *(__nv_bfloat162*)(orow + 2 * N + col) = __nv_bfloat162(h0, h1);
                } else {
                    float* orow = Cf + (size_t)r * N;
                    if (RESID) {
                        float2 old = *(float2*)(orow + col);
                        v0 += old.x; v1 += old.y;
                    }
                    *(float2*)(orow + col) = make_float2(v0, v1);
                }
            }
        }
    }
}

// ================= weight prep: W[K,N] fp32 -> B'[N,3K] bf16 [hi|hi|lo] =========
__global__ __launch_bounds__(256) void prep_weight(
    const float* __restrict__ W, __nv_bfloat16* __restrict__ Bp, int K, int N)
{
    const int n  = blockIdx.x * 32 + (threadIdx.x & 31);
    const int k0 = blockIdx.y * 128 + (threadIdx.x >> 5) * 16;
    __nv_bfloat16* orow = Bp + (size_t)n * 3 * K;
#pragma unroll
    for (int i = 0; i < 16; i++) {
        float v = W[(size_t)(k0 + i) * N + n];
        __nv_bfloat16 hi, lo;
        split_bf16(v, hi, lo);
        orow[k0 + i]         = hi;
        orow[K + k0 + i]     = hi;
        orow[2 * K + k0 + i] = lo;
    }
}

// ================= node prep: fp32 [L,DIN] -> bf16 [L,3*DIN] [hi|lo|hi] ==========
__global__ __launch_bounds__(256) void prep_node(
    const float* __restrict__ X, __nv_bfloat16* __restrict__ Ap)
{
    const int idx = blockIdx.x * 256 + threadIdx.x;
    const int r = idx / DIN, k = idx % DIN;
    float v = X[idx];
    __nv_bfloat16 hi, lo;
    split_bf16(v, hi, lo);
    __nv_bfloat16* orow = Ap + (size_t)r * 3 * DIN;
    orow[k]           = hi;
    orow[DIN + k]     = lo;
    orow[2 * DIN + k] = hi;
}

// ================= LayerNorm -> split bf16 A' [L, 3*DD] =========================
__global__ __launch_bounds__(256) void ln_split_kernel(
    const float* __restrict__ x, const float* __restrict__ gam,
    const float* __restrict__ bet, __nv_bfloat16* __restrict__ out)
{
    __shared__ float red[8];
    __shared__ float bcast;
    const int tid = threadIdx.x;
    const float* xr = x + (size_t)blockIdx.x * DD;

    float v0 = xr[tid], v1 = xr[tid + 256], v2 = xr[tid + 512];
    float sum = v0 + v1 + v2;
#pragma unroll
    for (int o = 16; o > 0; o >>= 1) sum += __shfl_xor_sync(0xffffffffu, sum, o);
    if ((tid & 31) == 0) red[tid >> 5] = sum;
    __syncthreads();
    if (tid == 0) {
        float t = 0.f;
#pragma unroll
        for (int i = 0; i < 8; i++) t += red[i];
        bcast = t * (1.0f / DD);
    }
    __syncthreads();
    const float mu = bcast;
    float d0 = v0 - mu, d1 = v1 - mu, d2 = v2 - mu;
    float sq = d0 * d0 + d1 * d1 + d2 * d2;
#pragma unroll
    for (int o = 16; o > 0; o >>= 1) sq += __shfl_xor_sync(0xffffffffu, sq, o);
    __syncthreads();
    if ((tid & 31) == 0) red[tid >> 5] = sq;
    __syncthreads();
    if (tid == 0) {
        float t = 0.f;
#pragma unroll
        for (int i = 0; i < 8; i++) t += red[i];
        bcast = rsqrtf(t * (1.0f / DD) + 1e-5f);
    }
    __syncthreads();
    const float inv = bcast;

    __nv_bfloat16* orow = out + (size_t)blockIdx.x * (3 * DD);
#pragma unroll
    for (int q = 0; q < 3; q++) {
        const int j = tid + q * 256;
        const float dv = (q == 0 ? d0 : (q == 1 ? d1 : d2));
        float v = dv * inv * gam[j] + bet[j];
        __nv_bfloat16 hi, lo;
        split_bf16(v, hi, lo);
        orow[j]          = hi;
        orow[DD + j]     = lo;
        orow[2 * DD + j] = hi;
    }
}

// ================= final LayerNorm (fp32 out) ===================================
__global__ __launch_bounds__(256) void ln_final_kernel(
    const float* __restrict__ x, const float* __restrict__ gam,
    const float* __restrict__ bet, float* __restrict__ out)
{
    __shared__ float red[8];
    __shared__ float bcast;
    const int tid = threadIdx.x;
    const float* xr = x + (size_t)blockIdx.x * DD;

    float v0 = xr[tid], v1 = xr[tid + 256], v2 = xr[tid + 512];
    float sum = v0 + v1 + v2;
#pragma unroll
    for (int o = 16; o > 0; o >>= 1) sum += __shfl_xor_sync(0xffffffffu, sum, o);
    if ((tid & 31) == 0) red[tid >> 5] = sum;
    __syncthreads();
    if (tid == 0) {
        float t = 0.f;
#pragma unroll
        for (int i = 0; i < 8; i++) t += red[i];
        bcast = t * (1.0f / DD);
    }
    __syncthreads();
    const float mu = bcast;
    float d0 = v0 - mu, d1 = v1 - mu, d2 = v2 - mu;
    float sq = d0 * d0 + d1 * d1 + d2 * d2;
#pragma unroll
    for (int o = 16; o > 0; o >>= 1) sq += __shfl_xor_sync(0xffffffffu, sq, o);
    __syncthreads();
    if ((tid & 31) == 0) red[tid >> 5] = sq;
    __syncthreads();
    if (tid == 0) {
        float t = 0.f;
#pragma unroll
        for (int i = 0; i < 8; i++) t += red[i];
        bcast = rsqrtf(t * (1.0f / DD) + 1e-5f);
    }
    __syncthreads();
    const float inv = bcast;

    float* orow = out + (size_t)blockIdx.x * DD;
    orow[tid]       = d0 * inv * gam[tid]       + bet[tid];
    orow[tid + 256] = d1 * inv * gam[tid + 256] + bet[tid + 256];
    orow[tid + 512] = d2 * inv * gam[tid + 512] + bet[tid + 512];
}

// ================= scan kernels =================================================
__global__ __launch_bounds__(256) void scan_chunk_kernel(
    const float* __restrict__ u, const float* __restrict__ dlogit,
    float* __restrict__ Sout)
{
    const int d = blockIdx.x * 256 + threadIdx.x;
    const int c = blockIdx.y;
    const float decay = sigmoidf_(dlogit[d]);
    const float* p = u + ((size_t)c * CLEN) * DD + d;
    float s = 0.0f;
#pragma unroll 8
    for (int t = 0; t < CLEN; t++) s = fmaf(decay, s, p[(size_t)t * DD]);
    Sout[c * DD + d] = s;
}

__global__ __launch_bounds__(768) void scan_carry_kernel(
    const float* __restrict__ Sin, const float* __restrict__ dlogit,
    float* __restrict__ carry)
{
    const int d = threadIdx.x;
    const float decay = sigmoidf_(dlogit[d]);
    float A = decay;
#pragma unroll
    for (int i = 0; i < 7; i++) A = A * A;   // decay^128
    float c = 0.0f;
    for (int k = 0; k < NCHUNK; k++) {
        carry[k * DD + d] = c;
        c = fmaf(A, c, Sin[k * DD + d]);
    }
}

// re-scan with carry, gate-multiply, emit split bf16 A' [L, 3*DD]
__global__ __launch_bounds__(256) void scan_apply_split_kernel(
    const float* __restrict__ u, const float* __restrict__ gate,
    const float* __restrict__ dlogit, const float* __restrict__ carry,
    __nv_bfloat16* __restrict__ out)
{
    const int d = blockIdx.x * 256 + threadIdx.x;
    const int c = blockIdx.y;
    const float decay = sigmoidf_(dlogit[d]);
    const size_t base = ((size_t)c * CLEN) * DD + d;
    float s = carry[c * DD + d];
#pragma unroll 4
    for (int t = 0; t < CLEN; t++) {
        const size_t idx = base + (size_t)t * DD;
        s = fmaf(decay, s, u[idx]);
        float v = s * gate[idx];
        __nv_bfloat16 hi, lo;
        split_bf16(v, hi, lo);
        __nv_bfloat16* orow = out + (size_t)(c * CLEN + t) * (3 * DD);
        orow[d]          = hi;
        orow[DD + d]     = lo;
        orow[2 * DD + d] = hi;
    }
}

// ================= host =========================================================
extern "C" void kernel_launch(void* const* d_in, const int* in_sizes, int n_in,
                              void* d_out, int out_size)
{
    const float* node    = (const float*)d_in[0];
    const float* W_proj  = (const float*)d_in[1];
    const float* b_proj  = (const float*)d_in[2];
    const float* ln_s_g  = (const float*)d_in[3];
    const float* ln_s_b  = (const float*)d_in[4];
    const float* W_in    = (const float*)d_in[5];
    const float* b_in    = (const float*)d_in[6];
    const float* W_gate  = (const float*)d_in[7];
    const float* b_gate  = (const float*)d_in[8];
    const float* W_out   = (const float*)d_in[9];
    const float* b_out   = (const float*)d_in[10];
    const float* dlogit  = (const float*)d_in[11];
    const float* ln_f_g  = (const float*)d_in[12];
    const float* ln_f_b  = (const float*)d_in[13];
    const float* W_ff1   = (const float*)d_in[14];
    const float* b_ff1   = (const float*)d_in[15];
    const float* W_ff2   = (const float*)d_in[16];
    const float* b_ff2   = (const float*)d_in[17];
    const float* ln_o_g  = (const float*)d_in[18];
    const float* ln_o_b  = (const float*)d_in[19];

    float *x, *u, *gate, *S, *carry;
    __nv_bfloat16 *a_node, *a_h, *a_s, *a_t;
    __nv_bfloat16 *w_proj, *w_in, *w_gt, *w_ot, *w_f1, *w_f2;
    cudaGetSymbolAddress((void**)&x,     g_x);
    cudaGetSymbolAddress((void**)&u,     g_u);
    cudaGetSymbolAddress((void**)&gate,  g_gate);
    cudaGetSymbolAddress((void**)&S,     g_S);
    cudaGetSymbolAddress((void**)&carry, g_carry);
    cudaGetSymbolAddress((void**)&a_node, ab_node);
    cudaGetSymbolAddress((void**)&a_h,    ab_h);
    cudaGetSymbolAddress((void**)&a_s,    ab_s);
    cudaGetSymbolAddress((void**)&a_t,    ab_t);
    cudaGetSymbolAddress((void**)&w_proj, wb_proj);
    cudaGetSymbolAddress((void**)&w_in,   wb_in);
    cudaGetSymbolAddress((void**)&w_gt,   wb_gate);
    cudaGetSymbolAddress((void**)&w_ot,   wb_out);
    cudaGetSymbolAddress((void**)&w_f1,   wb_ff1);
    cudaGetSymbolAddress((void**)&w_f2,   wb_ff2);

    cudaFuncSetAttribute(tc_gemm<0, false, false>, cudaFuncAttributeMaxDynamicSharedMemorySize, GEMM_SMEM_BYTES);
    cudaFuncSetAttribute(tc_gemm<1, false, false>, cudaFuncAttributeMaxDynamicSharedMemorySize, GEMM_SMEM_BYTES);
    cudaFuncSetAttribute(tc_gemm<0, true,  false>, cudaFuncAttributeMaxDynamicSharedMemorySize, GEMM_SMEM_BYTES);
    cudaFuncSetAttribute(tc_gemm<2, false, true >, cudaFuncAttributeMaxDynamicSharedMemorySize, GEMM_SMEM_BYTES);

    const dim3 blk(256);
    const dim3 gScan(DD / 256, NCHUNK);
    const dim3 gG6 (DD / 128, LSEQ / 128);   // N=768
    const dim3 gG12(D2 / 128, LSEQ / 128);   // N=1536

    // ---- prep: split/transposed weights + node activations ----
    prep_node<<<(LSEQ * DIN) / 256, blk>>>(node, a_node);
    prep_weight<<<dim3(DD / 32, DIN / 128), blk>>>(W_proj, w_proj, DIN, DD);
    for (int l = 0; l < NL; l++) {
        prep_weight<<<dim3(DD / 32, DD / 128), blk>>>(W_in   + (size_t)l * DD * DD, w_in + (size_t)l * DD * 3 * DD, DD, DD);
        prep_weight<<<dim3(DD / 32, DD / 128), blk>>>(W_gate + (size_t)l * DD * DD, w_gt + (size_t)l * DD * 3 * DD, DD, DD);
        prep_weight<<<dim3(DD / 32, DD / 128), blk>>>(W_out  + (size_t)l * DD * DD, w_ot + (size_t)l * DD * 3 * DD, DD, DD);
        prep_weight<<<dim3(D2 / 32, DD / 128), blk>>>(W_ff1  + (size_t)l * DD * D2, w_f1 + (size_t)l * D2 * 3 * DD, DD, D2);
        prep_weight<<<dim3(DD / 32, D2 / 128), blk>>>(W_ff2  + (size_t)l * D2 * DD, w_f2 + (size_t)l * DD * 3 * D2, D2, DD);
    }

    // ---- x = node @ W_proj + b_proj ----
    tc_gemm<0, false, false><<<gG6, blk, GEMM_SMEM_BYTES>>>(
        a_node, w_proj, b_proj, x, nullptr, 3 * DIN, DD);

    for (int l = 0; l < NL; l++) {
        const size_t vo = (size_t)l * DD;
        const size_t v1 = (size_t)l * D2;
        const __nv_bfloat16* wi = w_in + (size_t)l * DD * 3 * DD;
        const __nv_bfloat16* wg = w_gt + (size_t)l * DD * 3 * DD;
        const __nv_bfloat16* wo = w_ot + (size_t)l * DD * 3 * DD;
        const __nv_bfloat16* w1 = w_f1 + (size_t)l * D2 * 3 * DD;
        const __nv_bfloat16* w2 = w_f2 + (size_t)l * DD * 3 * D2;

        ln_split_kernel<<<LSEQ, blk>>>(x, ln_s_g + vo, ln_s_b + vo, a_h);
        tc_gemm<0, false, false><<<gG6, blk, GEMM_SMEM_BYTES>>>(
            a_h, wi, b_in + vo, u, nullptr, 3 * DD, DD);
        tc_gemm<1, false, false><<<gG6, blk, GEMM_SMEM_BYTES>>>(
            a_h, wg, b_gate + vo, gate, nullptr, 3 * DD, DD);
        scan_chunk_kernel<<<gScan, blk>>>(u, dlogit + vo, S);
        scan_carry_kernel<<<1, DD>>>(S, dlogit + vo, carry);
        scan_apply_split_kernel<<<gScan, blk>>>(u, gate, dlogit + vo, carry, a_s);
        tc_gemm<0, true, false><<<gG6, blk, GEMM_SMEM_BYTES>>>(
            a_s, wo, b_out + vo, x, nullptr, 3 * DD, DD);
        ln_split_kernel<<<LSEQ, blk>>>(x, ln_f_g + vo, ln_f_b + vo, a_h);
        tc_gemm<2, false, true><<<gG12, blk, GEMM_SMEM_BYTES>>>(
            a_h, w1, b_ff1 + v1, nullptr, a_t, 3 * DD, D2);
        tc_gemm<0, true, false><<<gG6, blk, GEMM_SMEM_BYTES>>>(
            a_t, w2, b_ff2 + vo, x, nullptr, 3 * D2, DD);
    }

    ln_final_kernel<<<LSEQ, blk>>>(x, ln_o_g, ln_o_b, (float*)d_out);
}

// round 5
// speedup vs baseline: 1.5764x; 1.0217x over previous
#include <cuda_runtime.h>
#include <cuda_bf16.h>
#include <math.h>

#define LSEQ 16384
#define DIN  256
#define DD   768
#define D2   1536
#define NL   8
#define NCHUNK 128
#define CLEN   128

// ---------------- fp32 scratch ----------------
__device__ float g_x[(size_t)LSEQ * DD];
__device__ float g_u[(size_t)LSEQ * DD];
__device__ float g_gate[(size_t)LSEQ * DD];
__device__ float g_S[NCHUNK * DD];
__device__ float g_carry[NCHUNK * DD];

// ---- bf16 split activations: A-layout [hi | lo | hi], row stride 3K ----
__device__ __nv_bfloat16 ab_node[(size_t)LSEQ * 3 * DIN];
__device__ __nv_bfloat16 ab_h[(size_t)LSEQ * 3 * DD];
__device__ __nv_bfloat16 ab_s[(size_t)LSEQ * 3 * DD];
__device__ __nv_bfloat16 ab_t[(size_t)LSEQ * 3 * D2];

// ---- bf16 split weights: B-layout [N, 3K] K-major, [hi | hi | lo] ----
__device__ __nv_bfloat16 wb_proj[(size_t)DD * 3 * DIN];
__device__ __nv_bfloat16 wb_in  [(size_t)NL * DD * 3 * DD];
__device__ __nv_bfloat16 wb_gate[(size_t)NL * DD * 3 * DD];
__device__ __nv_bfloat16 wb_out [(size_t)NL * DD * 3 * DD];
__device__ __nv_bfloat16 wb_ff1 [(size_t)NL * D2 * 3 * DD];
__device__ __nv_bfloat16 wb_ff2 [(size_t)NL * DD * 3 * D2];

// ================= helpers =================
__device__ __forceinline__ float sigmoidf_(float z) {
    return 1.0f / (1.0f + __expf(-z));
}

__device__ __forceinline__ unsigned smem_u32(const void* p) {
    unsigned a;
    asm("{ .reg .u64 t; cvta.to.shared.u64 t, %1; cvt.u32.u64 %0, t; }"
        : "=r"(a) : "l"(p));
    return a;
}

__device__ __forceinline__ void cpasync16(unsigned s, const void* g) {
    asm volatile("cp.async.cg.shared.global [%0], [%1], 16;"
                 :: "r"(s), "l"(g) : "memory");
}
__device__ __forceinline__ void cp_commit() {
    asm volatile("cp.async.commit_group;" ::: "memory");
}
__device__ __forceinline__ void cp_wait1() {
    asm volatile("cp.async.wait_group 1;" ::: "memory");
}
__device__ __forceinline__ void cp_wait0() {
    asm volatile("cp.async.wait_group 0;" ::: "memory");
}

__device__ __forceinline__ void ldsm4(unsigned* r, unsigned addr) {
    asm volatile("ldmatrix.sync.aligned.m8n8.x4.shared.b16 {%0,%1,%2,%3}, [%4];"
                 : "=r"(r[0]), "=r"(r[1]), "=r"(r[2]), "=r"(r[3]) : "r"(addr));
}

__device__ __forceinline__ void mma16816(float* d, const unsigned* a,
                                         unsigned b0, unsigned b1) {
    asm volatile(
        "mma.sync.aligned.m16n8k16.row.col.f32.bf16.bf16.f32 "
        "{%0,%1,%2,%3}, {%4,%5,%6,%7}, {%8,%9}, {%0,%1,%2,%3};"
        : "+f"(d[0]), "+f"(d[1]), "+f"(d[2]), "+f"(d[3])
        : "r"(a[0]), "r"(a[1]), "r"(a[2]), "r"(a[3]), "r"(b0), "r"(b1));
}

__device__ __forceinline__ void split_bf16(float v, __nv_bfloat16& hi, __nv_bfloat16& lo) {
    hi = __float2bfloat16(v);
    lo = __float2bfloat16(v - __bfloat162float(hi));
}

// ================= tensor-core GEMM (mma.sync bf16) =================
// C[M,N] = epilogue(A'[M,Kp] @ B'[N,Kp]^T + bias), Kp = 3*K split layout.
// Tile 128x128xBK64, 256 threads, 8 warps 4(M)x2(N), warp tile 32x64.
// Smem rows 128B, chunk swizzle c^(row&7). 3-stage cp.async pipeline,
// single __syncthreads per K-tile.
// ACT: 0 none, 1 sigmoid, 2 silu.  RESID: Cf += v.  SPLIT: bf16 [hi|lo|hi] to Cs.
#define GEMM_SMEM_BYTES (3 * 32768)

template<int ACT, bool RESID, bool SPLIT>
__global__ __launch_bounds__(256) void tc_gemm(
    const __nv_bfloat16* __restrict__ A, const __nv_bfloat16* __restrict__ B,
    const float* __restrict__ bias, float* __restrict__ Cf,
    __nv_bfloat16* __restrict__ Cs, int Kp, int N)
{
    extern __shared__ __align__(1024) char smem[];
    const unsigned sbase = smem_u32(smem);
    const int tid  = threadIdx.x;
    const int wid  = tid >> 5;
    const int lane = tid & 31;

    const int row0 = blockIdx.y * 128;
    const int col0 = blockIdx.x * 128;
    const __nv_bfloat16* Ab = A + (size_t)row0 * Kp;
    const __nv_bfloat16* Bb = B + (size_t)col0 * Kp;

    const int m0 = (wid & 3) * 32;   // warp M offset
    const int n0 = (wid >> 2) * 64;  // warp N offset

    float acc[2][8][4];
#pragma unroll
    for (int i = 0; i < 2; i++)
#pragma unroll
        for (int j = 0; j < 8; j++)
#pragma unroll
            for (int q = 0; q < 4; q++) acc[i][j][q] = 0.0f;

    // loader mapping: row = tid>>1 (0..127), chunks (tid&1)*4 + 0..3
    const int lrow = tid >> 1;
    const int lc0  = (tid & 1) * 4;
    const __nv_bfloat16* agp = Ab + (size_t)lrow * Kp;
    const __nv_bfloat16* bgp = Bb + (size_t)lrow * Kp;

    const int NC = Kp / 64;      // >= 12 always

#define ISSUE_TILE(ct, s) do {                                              \
        const unsigned sA_ = sbase + (unsigned)(s) * 32768u;                \
        const unsigned sB_ = sA_ + 16384u;                                  \
        const int kb_ = (ct) * 64;                                          \
        _Pragma("unroll")                                                   \
        for (int i_ = 0; i_ < 4; i_++) {                                    \
            const int c_ = lc0 + i_;                                        \
            const unsigned off_ = (unsigned)(lrow * 128 + ((c_ ^ (lrow & 7)) << 4)); \
            cpasync16(sA_ + off_, agp + kb_ + c_ * 8);                      \
            cpasync16(sB_ + off_, bgp + kb_ + c_ * 8);                      \
        }                                                                   \
    } while (0)

    // prologue: stages 0 and 1 in flight
    ISSUE_TILE(0, 0);
    cp_commit();
    ISSUE_TILE(1, 1);
    cp_commit();

    int sidx = 0;                // buffer index of tile c
    for (int c = 0; c < NC; c++) {
        // tile c ready?
        if (c + 1 < NC) cp_wait1(); else cp_wait0();
        __syncthreads();         // data visible to all + buffer (c-1)%3 free

        // refill the freed buffer with tile c+2
        if (c + 2 < NC) {
            int fs = sidx + 2; if (fs >= 3) fs -= 3;
            ISSUE_TILE(c + 2, fs);
            cp_commit();
        }

        const unsigned sA = sbase + (unsigned)sidx * 32768u;
        const unsigned sB = sA + 16384u;

#pragma unroll
        for (int kk4 = 0; kk4 < 4; kk4++) {      // k16 steps within tile
            const int cb = kk4 * 2;              // chunk base (8-elem chunks)
            unsigned afr[2][4], bfr[4][4];
#pragma unroll
            for (int mt = 0; mt < 2; mt++) {
                const int r = m0 + mt * 16 + (lane & 15);
                const int ch = cb + (lane >> 4);
                ldsm4(afr[mt], sA + r * 128 + ((ch ^ (r & 7)) << 4));
            }
#pragma unroll
            for (int jp = 0; jp < 4; jp++) {
                const int rn = n0 + jp * 16 + ((lane >> 4) << 3) + (lane & 7);
                const int ch = cb + ((lane >> 3) & 1);
                ldsm4(bfr[jp], sB + rn * 128 + ((ch ^ (rn & 7)) << 4));
            }
#pragma unroll
            for (int mt = 0; mt < 2; mt++)
#pragma unroll
                for (int nt = 0; nt < 8; nt++)
                    mma16816(acc[mt][nt], afr[mt],
                             bfr[nt >> 1][(nt & 1) * 2],
                             bfr[nt >> 1][(nt & 1) * 2 + 1]);
        }
        sidx++; if (sidx >= 3) sidx -= 3;
    }
#undef ISSUE_TILE

    // ---------------- epilogue ----------------
    const int g  = lane >> 2;
    const int t4 = lane & 3;
#pragma unroll
    for (int nt = 0; nt < 8; nt++) {
        const int col = col0 + n0 + nt * 8 + 2 * t4;
        const float b0 = bias[col];
        const float b1 = bias[col + 1];
#pragma unroll
        for (int mt = 0; mt < 2; mt++) {
            const int rtop = row0 + m0 + mt * 16 + g;
#pragma unroll
            for (int half = 0; half < 2; half++) {
                const int r = rtop + half * 8;
                float v0 = acc[mt][nt][half * 2 + 0] + b0;
                float v1 = acc[mt][nt][half * 2 + 1] + b1;
                if (ACT == 1) { v0 = sigmoidf_(v0); v1 = sigmoidf_(v1); }
                else if (ACT == 2) { v0 = v0 * sigmoidf_(v0); v1 = v1 * sigmoidf_(v1); }
                if (SPLIT) {
                    __nv_bfloat16* orow = Cs + (size_t)r * (3 * N);
                    __nv_bfloat16 h0, l0, h1, l1;
                    split_bf16(v0, h0, l0);
                    split_bf16(v1, h1, l1);
                    *(__nv_bfloat162*)(orow + col)         = __nv_bfloat162(h0, h1);
                    *(__nv_bfloat162*)(orow + N + col)     = __nv_bfloat162(l0, l1);
                    *(__nv_bfloat162*)(orow + 2 * N + col) = __nv_bfloat162(h0, h1);
                } else {
                    float* orow = Cf + (size_t)r * N;
                    if (RESID) {
                        float2 old = *(float2*)(orow + col);
                        v0 += old.x; v1 += old.y;
                    }
                    *(float2*)(orow + col) = make_float2(v0, v1);
                }
            }
        }
    }
}

// ========== batched weight prep: ALL weights in one launch ======================
// z in [0, 5*NL]: z<5*NL -> layer l=z/5, type z%5 in {in, gate, out, ff1, ff2};
// z==5*NL -> W_proj.  Each block: 32 n-cols x 128 k-rows.
__global__ __launch_bounds__(256) void prep_all(
    const float* __restrict__ W_proj, const float* __restrict__ W_in,
    const float* __restrict__ W_gate, const float* __restrict__ W_out,
    const float* __restrict__ W_ff1,  const float* __restrict__ W_ff2,
    __nv_bfloat16* __restrict__ o_proj, __nv_bfloat16* __restrict__ o_in,
    __nv_bfloat16* __restrict__ o_gate, __nv_bfloat16* __restrict__ o_out,
    __nv_bfloat16* __restrict__ o_ff1,  __nv_bfloat16* __restrict__ o_ff2)
{
    const int z = blockIdx.z;
    const float* W; __nv_bfloat16* Bp; int K, N;
    if (z < 5 * NL) {
        const int l = z / 5, t = z - l * 5;
        switch (t) {
            case 0: W = W_in   + (size_t)l * DD * DD; Bp = o_in   + (size_t)l * DD * 3 * DD; K = DD; N = DD; break;
            case 1: W = W_gate + (size_t)l * DD * DD; Bp = o_gate + (size_t)l * DD * 3 * DD; K = DD; N = DD; break;
            case 2: W = W_out  + (size_t)l * DD * DD; Bp = o_out  + (size_t)l * DD * 3 * DD; K = DD; N = DD; break;
            case 3: W = W_ff1  + (size_t)l * DD * D2; Bp = o_ff1  + (size_t)l * D2 * 3 * DD; K = DD; N = D2; break;
            default:W = W_ff2  + (size_t)l * D2 * DD; Bp = o_ff2  + (size_t)l * DD * 3 * D2; K = D2; N = DD; break;
        }
    } else {
        W = W_proj; Bp = o_proj; K = DIN; N = DD;
    }
    const int n = blockIdx.x * 32 + (threadIdx.x & 31);
    if (n >= N) return;
    const int k0 = blockIdx.y * 128 + (threadIdx.x >> 5) * 16;
    if (k0 >= K) return;
    __nv_bfloat16* orow = Bp + (size_t)n * 3 * K;
#pragma unroll
    for (int i = 0; i < 16; i++) {
        float v = W[(size_t)(k0 + i) * N + n];
        __nv_bfloat16 hi, lo;
        split_bf16(v, hi, lo);
        orow[k0 + i]         = hi;
        orow[K + k0 + i]     = hi;
        orow[2 * K + k0 + i] = lo;
    }
}

// ================= node prep: fp32 [L,DIN] -> bf16 [L,3*DIN] [hi|lo|hi] ==========
__global__ __launch_bounds__(256) void prep_node(
    const float* __restrict__ X, __nv_bfloat16* __restrict__ Ap)
{
    const int idx = blockIdx.x * 256 + threadIdx.x;
    const int r = idx / DIN, k = idx % DIN;
    float v = X[idx];
    __nv_bfloat16 hi, lo;
    split_bf16(v, hi, lo);
    __nv_bfloat16* orow = Ap + (size_t)r * 3 * DIN;
    orow[k]           = hi;
    orow[DIN + k]     = lo;
    orow[2 * DIN + k] = hi;
}

// ================= LayerNorm -> split bf16 A' [L, 3*DD] =========================
__global__ __launch_bounds__(256) void ln_split_kernel(
    const float* __restrict__ x, const float* __restrict__ gam,
    const float* __restrict__ bet, __nv_bfloat16* __restrict__ out)
{
    __shared__ float red[8];
    __shared__ float bcast;
    const int tid = threadIdx.x;
    const float* xr = x + (size_t)blockIdx.x * DD;

    float v0 = xr[tid], v1 = xr[tid + 256], v2 = xr[tid + 512];
    float sum = v0 + v1 + v2;
#pragma unroll
    for (int o = 16; o > 0; o >>= 1) sum += __shfl_xor_sync(0xffffffffu, sum, o);
    if ((tid & 31) == 0) red[tid >> 5] = sum;
    __syncthreads();
    if (tid == 0) {
        float t = 0.f;
#pragma unroll
        for (int i = 0; i < 8; i++) t += red[i];
        bcast = t * (1.0f / DD);
    }
    __syncthreads();
    const float mu = bcast;
    float d0 = v0 - mu, d1 = v1 - mu, d2 = v2 - mu;
    float sq = d0 * d0 + d1 * d1 + d2 * d2;
#pragma unroll
    for (int o = 16; o > 0; o >>= 1) sq += __shfl_xor_sync(0xffffffffu, sq, o);
    __syncthreads();
    if ((tid & 31) == 0) red[tid >> 5] = sq;
    __syncthreads();
    if (tid == 0) {
        float t = 0.f;
#pragma unroll
        for (int i = 0; i < 8; i++) t += red[i];
        bcast = rsqrtf(t * (1.0f / DD) + 1e-5f);
    }
    __syncthreads();
    const float inv = bcast;

    __nv_bfloat16* orow = out + (size_t)blockIdx.x * (3 * DD);
#pragma unroll
    for (int q = 0; q < 3; q++) {
        const int j = tid + q * 256;
        const float dv = (q == 0 ? d0 : (q == 1 ? d1 : d2));
        float v = dv * inv * gam[j] + bet[j];
        __nv_bfloat16 hi, lo;
        split_bf16(v, hi, lo);
        orow[j]          = hi;
        orow[DD + j]     = lo;
        orow[2 * DD + j] = hi;
    }
}

// ================= final LayerNorm (fp32 out) ===================================
__global__ __launch_bounds__(256) void ln_final_kernel(
    const float* __restrict__ x, const float* __restrict__ gam,
    const float* __restrict__ bet, float* __restrict__ out)
{
    __shared__ float red[8];
    __shared__ float bcast;
    const int tid = threadIdx.x;
    const float* xr = x + (size_t)blockIdx.x * DD;

    float v0 = xr[tid], v1 = xr[tid + 256], v2 = xr[tid + 512];
    float sum = v0 + v1 + v2;
#pragma unroll
    for (int o = 16; o > 0; o >>= 1) sum += __shfl_xor_sync(0xffffffffu, sum, o);
    if ((tid & 31) == 0) red[tid >> 5] = sum;
    __syncthreads();
    if (tid == 0) {
        float t = 0.f;
#pragma unroll
        for (int i = 0; i < 8; i++) t += red[i];
        bcast = t * (1.0f / DD);
    }
    __syncthreads();
    const float mu = bcast;
    float d0 = v0 - mu, d1 = v1 - mu, d2 = v2 - mu;
    float sq = d0 * d0 + d1 * d1 + d2 * d2;
#pragma unroll
    for (int o = 16; o > 0; o >>= 1) sq += __shfl_xor_sync(0xffffffffu, sq, o);
    __syncthreads();
    if ((tid & 31) == 0) red[tid >> 5] = sq;
    __syncthreads();
    if (tid == 0) {
        float t = 0.f;
#pragma unroll
        for (int i = 0; i < 8; i++) t += red[i];
        bcast = rsqrtf(t * (1.0f / DD) + 1e-5f);
    }
    __syncthreads();
    const float inv = bcast;

    float* orow = out + (size_t)blockIdx.x * DD;
    orow[tid]       = d0 * inv * gam[tid]       + bet[tid];
    orow[tid + 256] = d1 * inv * gam[tid + 256] + bet[tid + 256];
    orow[tid + 512] = d2 * inv * gam[tid + 512] + bet[tid + 512];
}

// ================= scan kernels =================================================
__global__ __launch_bounds__(256) void scan_chunk_kernel(
    const float* __restrict__ u, const float* __restrict__ dlogit,
    float* __restrict__ Sout)
{
    const int d = blockIdx.x * 256 + threadIdx.x;
    const int c = blockIdx.y;
    const float decay = sigmoidf_(dlogit[d]);
    const float* p = u + ((size_t)c * CLEN) * DD + d;
    float s = 0.0f;
#pragma unroll 8
    for (int t = 0; t < CLEN; t++) s = fmaf(decay, s, p[(size_t)t * DD]);
    Sout[c * DD + d] = s;
}

__global__ __launch_bounds__(768) void scan_carry_kernel(
    const float* __restrict__ Sin, const float* __restrict__ dlogit,
    float* __restrict__ carry)
{
    const int d = threadIdx.x;
    const float decay = sigmoidf_(dlogit[d]);
    float A = decay;
#pragma unroll
    for (int i = 0; i < 7; i++) A = A * A;   // decay^128
    float c = 0.0f;
    for (int k = 0; k < NCHUNK; k++) {
        carry[k * DD + d] = c;
        c = fmaf(A, c, Sin[k * DD + d]);
    }
}

// re-scan with carry, gate-multiply, emit split bf16 A' [L, 3*DD]
__global__ __launch_bounds__(256) void scan_apply_split_kernel(
    const float* __restrict__ u, const float* __restrict__ gate,
    const float* __restrict__ dlogit, const float* __restrict__ carry,
    __nv_bfloat16* __restrict__ out)
{
    const int d = blockIdx.x * 256 + threadIdx.x;
    const int c = blockIdx.y;
    const float decay = sigmoidf_(dlogit[d]);
    const size_t base = ((size_t)c * CLEN) * DD + d;
    float s = carry[c * DD + d];
#pragma unroll 4
    for (int t = 0; t < CLEN; t++) {
        const size_t idx = base + (size_t)t * DD;
        s = fmaf(decay, s, u[idx]);
        float v = s * gate[idx];
        __nv_bfloat16 hi, lo;
        split_bf16(v, hi, lo);
        __nv_bfloat16* orow = out + (size_t)(c * CLEN + t) * (3 * DD);
        orow[d]          = hi;
        orow[DD + d]     = lo;
        orow[2 * DD + d] = hi;
    }
}

// ================= host =========================================================
extern "C" void kernel_launch(void* const* d_in, const int* in_sizes, int n_in,
                              void* d_out, int out_size)
{
    const float* node    = (const float*)d_in[0];
    const float* W_proj  = (const float*)d_in[1];
    const float* b_proj  = (const float*)d_in[2];
    const float* ln_s_g  = (const float*)d_in[3];
    const float* ln_s_b  = (const float*)d_in[4];
    const float* W_in    = (const float*)d_in[5];
    const float* b_in    = (const float*)d_in[6];
    const float* W_gate  = (const float*)d_in[7];
    const float* b_gate  = (const float*)d_in[8];
    const float* W_out   = (const float*)d_in[9];
    const float* b_out   = (const float*)d_in[10];
    const float* dlogit  = (const float*)d_in[11];
    const float* ln_f_g  = (const float*)d_in[12];
    const float* ln_f_b  = (const float*)d_in[13];
    const float* W_ff1   = (const float*)d_in[14];
    const float* b_ff1   = (const float*)d_in[15];
    const float* W_ff2   = (const float*)d_in[16];
    const float* b_ff2   = (const float*)d_in[17];
    const float* ln_o_g  = (const float*)d_in[18];
    const float* ln_o_b  = (const float*)d_in[19];

    float *x, *u, *gate, *S, *carry;
    __nv_bfloat16 *a_node, *a_h, *a_s, *a_t;
    __nv_bfloat16 *w_proj, *w_in, *w_gt, *w_ot, *w_f1, *w_f2;
    cudaGetSymbolAddress((void**)&x,     g_x);
    cudaGetSymbolAddress((void**)&u,     g_u);
    cudaGetSymbolAddress((void**)&gate,  g_gate);
    cudaGetSymbolAddress((void**)&S,     g_S);
    cudaGetSymbolAddress((void**)&carry, g_carry);
    cudaGetSymbolAddress((void**)&a_node, ab_node);
    cudaGetSymbolAddress((void**)&a_h,    ab_h);
    cudaGetSymbolAddress((void**)&a_s,    ab_s);
    cudaGetSymbolAddress((void**)&a_t,    ab_t);
    cudaGetSymbolAddress((void**)&w_proj, wb_proj);
    cudaGetSymbolAddress((void**)&w_in,   wb_in);
    cudaGetSymbolAddress((void**)&w_gt,   wb_gate);
    cudaGetSymbolAddress((void**)&w_ot,   wb_out);
    cudaGetSymbolAddress((void**)&w_f1,   wb_ff1);
    cudaGetSymbolAddress((void**)&w_f2,   wb_ff2);

    cudaFuncSetAttribute(tc_gemm<0, false, false>, cudaFuncAttributeMaxDynamicSharedMemorySize, GEMM_SMEM_BYTES);
    cudaFuncSetAttribute(tc_gemm<1, false, false>, cudaFuncAttributeMaxDynamicSharedMemorySize, GEMM_SMEM_BYTES);
    cudaFuncSetAttribute(tc_gemm<0, true,  false>, cudaFuncAttributeMaxDynamicSharedMemorySize, GEMM_SMEM_BYTES);
    cudaFuncSetAttribute(tc_gemm<2, false, true >, cudaFuncAttributeMaxDynamicSharedMemorySize, GEMM_SMEM_BYTES);

    const dim3 blk(256);
    const dim3 gScan(DD / 256, NCHUNK);
    const dim3 gG6 (DD / 128, LSEQ / 128);   // N=768
    const dim3 gG12(D2 / 128, LSEQ / 128);   // N=1536

    // ---- prep: activations + ALL weights in one launch each ----
    prep_node<<<(LSEQ * DIN) / 256, blk>>>(node, a_node);
    prep_all<<<dim3(48, 12, 5 * NL + 1), blk>>>(
        W_proj, W_in, W_gate, W_out, W_ff1, W_ff2,
        w_proj, w_in, w_gt, w_ot, w_f1, w_f2);

    // ---- x = node @ W_proj + b_proj ----
    tc_gemm<0, false, false><<<gG6, blk, GEMM_SMEM_BYTES>>>(
        a_node, w_proj, b_proj, x, nullptr, 3 * DIN, DD);

    for (int l = 0; l < NL; l++) {
        const size_t vo = (size_t)l * DD;
        const size_t v1 = (size_t)l * D2;
        const __nv_bfloat16* wi = w_in + (size_t)l * DD * 3 * DD;
        const __nv_bfloat16* wg = w_gt + (size_t)l * DD * 3 * DD;
        const __nv_bfloat16* wo = w_ot + (size_t)l * DD * 3 * DD;
        const __nv_bfloat16* w1 = w_f1 + (size_t)l * D2 * 3 * DD;
        const __nv_bfloat16* w2 = w_f2 + (size_t)l * DD * 3 * D2;

        ln_split_kernel<<<LSEQ, blk>>>(x, ln_s_g + vo, ln_s_b + vo, a_h);
        tc_gemm<0, false, false><<<gG6, blk, GEMM_SMEM_BYTES>>>(
            a_h, wi, b_in + vo, u, nullptr, 3 * DD, DD);
        tc_gemm<1, false, false><<<gG6, blk, GEMM_SMEM_BYTES>>>(
            a_h, wg, b_gate + vo, gate, nullptr, 3 * DD, DD);
        scan_chunk_kernel<<<gScan, blk>>>(u, dlogit + vo, S);
        scan_carry_kernel<<<1, DD>>>(S, dlogit + vo, carry);
        scan_apply_split_kernel<<<gScan, blk>>>(u, gate, dlogit + vo, carry, a_s);
        tc_gemm<0, true, false><<<gG6, blk, GEMM_SMEM_BYTES>>>(
            a_s, wo, b_out + vo, x, nullptr, 3 * DD, DD);
        ln_split_kernel<<<LSEQ, blk>>>(x, ln_f_g + vo, ln_f_b + vo, a_h);
        tc_gemm<2, false, true><<<gG12, blk, GEMM_SMEM_BYTES>>>(
            a_h, w1, b_ff1 + v1, nullptr, a_t, 3 * DD, D2);
        tc_gemm<0, true, false><<<gG6, blk, GEMM_SMEM_BYTES>>>(
            a_t, w2, b_ff2 + vo, x, nullptr, 3 * D2, DD);
    }

    ln_final_kernel<<<LSEQ, blk>>>(x, ln_o_g, ln_o_b, (float*)d_out);
}

// round 6
// speedup vs baseline: 1.9647x; 1.2463x over previous
#include <cuda_runtime.h>
#include <cuda_bf16.h>
#include <math.h>

#define LSEQ 16384
#define DIN  256
#define DD   768
#define D2   1536
#define NL   8
#define NCHUNK 128
#define CLEN   128

// ---------------- fp32 scratch ----------------
__device__ float g_x[(size_t)LSEQ * DD];
__device__ float g_u[(size_t)LSEQ * DD];
__device__ float g_gate[(size_t)LSEQ * DD];
__device__ float g_S[NCHUNK * DD];
__device__ float g_carry[NCHUNK * DD];

// ---- bf16 split activations: row layout [hi(K) | lo(K)], stride 2K ----
__device__ __nv_bfloat16 ab_node[(size_t)LSEQ * 2 * DIN];
__device__ __nv_bfloat16 ab_h[(size_t)LSEQ * 2 * DD];
__device__ __nv_bfloat16 ab_s[(size_t)LSEQ * 2 * DD];
__device__ __nv_bfloat16 ab_t[(size_t)LSEQ * 2 * D2];

// ---- bf16 split weights: B[N] rows, layout [hi(K) | lo(K)], stride 2K ----
__device__ __nv_bfloat16 wb_proj[(size_t)DD * 2 * DIN];
__device__ __nv_bfloat16 wb_in  [(size_t)NL * DD * 2 * DD];
__device__ __nv_bfloat16 wb_gate[(size_t)NL * DD * 2 * DD];
__device__ __nv_bfloat16 wb_out [(size_t)NL * DD * 2 * DD];
__device__ __nv_bfloat16 wb_ff1 [(size_t)NL * D2 * 2 * DD];
__device__ __nv_bfloat16 wb_ff2 [(size_t)NL * DD * 2 * D2];

// ================= helpers =================
__device__ __forceinline__ float sigmoidf_(float z) {
    return 1.0f / (1.0f + __expf(-z));
}

__device__ __forceinline__ unsigned smem_u32(const void* p) {
    unsigned a;
    asm("{ .reg .u64 t; cvta.to.shared.u64 t, %1; cvt.u32.u64 %0, t; }"
        : "=r"(a) : "l"(p));
    return a;
}

__device__ __forceinline__ void cpasync16(unsigned s, const void* g) {
    asm volatile("cp.async.cg.shared.global [%0], [%1], 16;"
                 :: "r"(s), "l"(g) : "memory");
}
__device__ __forceinline__ void cp_commit() {
    asm volatile("cp.async.commit_group;" ::: "memory");
}
__device__ __forceinline__ void cp_wait1() {
    asm volatile("cp.async.wait_group 1;" ::: "memory");
}
__device__ __forceinline__ void cp_wait0() {
    asm volatile("cp.async.wait_group 0;" ::: "memory");
}

__device__ __forceinline__ void ldsm4(unsigned* r, unsigned addr) {
    asm volatile("ldmatrix.sync.aligned.m8n8.x4.shared.b16 {%0,%1,%2,%3}, [%4];"
                 : "=r"(r[0]), "=r"(r[1]), "=r"(r[2]), "=r"(r[3]) : "r"(addr));
}

__device__ __forceinline__ void mma16816(float* d, const unsigned* a,
                                         unsigned b0, unsigned b1) {
    asm volatile(
        "mma.sync.aligned.m16n8k16.row.col.f32.bf16.bf16.f32 "
        "{%0,%1,%2,%3}, {%4,%5,%6,%7}, {%8,%9}, {%0,%1,%2,%3};"
        : "+f"(d[0]), "+f"(d[1]), "+f"(d[2]), "+f"(d[3])
        : "r"(a[0]), "r"(a[1]), "r"(a[2]), "r"(a[3]), "r"(b0), "r"(b1));
}

__device__ __forceinline__ void split_bf16(float v, __nv_bfloat16& hi, __nv_bfloat16& lo) {
    hi = __float2bfloat16(v);
    lo = __float2bfloat16(v - __bfloat162float(hi));
}

// ================= tensor-core GEMM (mma.sync bf16, plane-split) =================
// C[M,N] = epilogue(Ahi·Bhi + Alo·Bhi + Ahi·Blo + bias)
// A rows: [hi(K)|lo(K)] stride 2K; B rows likewise. Tile 128x128xBK64.
// 256 threads, 8 warps 4(M)x2(N), warp tile 32x64. 3 MMA passes per k16.
// Stage = 4 sub-tiles x 16KB = 64KB; 3 stages; 1 CTA/SM.
// ACT: 0 none, 1 sigmoid, 2 silu.  RESID: Cf += v.  SPLIT: bf16 [hi|lo] to Cs (stride 2N).
#define GEMM_SMEM_BYTES (3 * 65536)

template<int ACT, bool RESID, bool SPLIT>
__global__ __launch_bounds__(256) void tc_gemm(
    const __nv_bfloat16* __restrict__ A, const __nv_bfloat16* __restrict__ B,
    const float* __restrict__ bias, float* __restrict__ Cf,
    __nv_bfloat16* __restrict__ Cs, int K, int N)
{
    extern __shared__ __align__(1024) char smem[];
    const unsigned sbase = smem_u32(smem);
    const int tid  = threadIdx.x;
    const int wid  = tid >> 5;
    const int lane = tid & 31;
    const int K2 = 2 * K;

    const int row0 = blockIdx.y * 128;
    const int col0 = blockIdx.x * 128;

    const int m0 = (wid & 3) * 32;   // warp M offset
    const int n0 = (wid >> 2) * 64;  // warp N offset

    float acc[2][8][4];
#pragma unroll
    for (int i = 0; i < 2; i++)
#pragma unroll
        for (int j = 0; j < 8; j++)
#pragma unroll
            for (int q = 0; q < 4; q++) acc[i][j][q] = 0.0f;

    // loader mapping: row = tid>>1 (0..127), chunks (tid&1)*4 + 0..3
    const int lrow = tid >> 1;
    const int lc0  = (tid & 1) * 4;
    const __nv_bfloat16* agp = A + (size_t)(row0 + lrow) * K2;
    const __nv_bfloat16* bgp = B + (size_t)(col0 + lrow) * K2;

    const int NC = K / 64;

#define ISSUE_TILE(ct, s) do {                                              \
        const unsigned sb_ = sbase + (unsigned)(s) * 65536u;                \
        const int kb_ = (ct) * 64;                                          \
        _Pragma("unroll")                                                   \
        for (int i_ = 0; i_ < 4; i_++) {                                    \
            const int c_ = lc0 + i_;                                        \
            const unsigned off_ = (unsigned)(lrow * 128 + ((c_ ^ (lrow & 7)) << 4)); \
            cpasync16(sb_ + off_,          agp + kb_ + c_ * 8);             \
            cpasync16(sb_ + 16384u + off_, agp + K + kb_ + c_ * 8);         \
            cpasync16(sb_ + 32768u + off_, bgp + kb_ + c_ * 8);             \
            cpasync16(sb_ + 49152u + off_, bgp + K + kb_ + c_ * 8);         \
        }                                                                   \
    } while (0)

    // prologue: stages 0 and 1 in flight
    ISSUE_TILE(0, 0);
    cp_commit();
    if (NC > 1) { ISSUE_TILE(1, 1); }
    cp_commit();

    int sidx = 0;                // buffer index of tile c
    for (int c = 0; c < NC; c++) {
        if (c + 1 < NC) cp_wait1(); else cp_wait0();
        __syncthreads();         // data visible + previous buffer free

        if (c + 2 < NC) {
            int fs = sidx + 2; if (fs >= 3) fs -= 3;
            ISSUE_TILE(c + 2, fs);
            cp_commit();
        }

        const unsigned sAhi = sbase + (unsigned)sidx * 65536u;
        const unsigned sAlo = sAhi + 16384u;
        const unsigned sBhi = sAhi + 32768u;
        const unsigned sBlo = sAhi + 49152u;

#pragma unroll
        for (int kk4 = 0; kk4 < 4; kk4++) {      // k16 steps within tile
            const int cb = kk4 * 2;              // chunk base (8-elem chunks)
            unsigned ahi[2][4], alo[2][4], bfr[4][4];
            unsigned boff[4];
#pragma unroll
            for (int mt = 0; mt < 2; mt++) {
                const int r = m0 + mt * 16 + (lane & 15);
                const int ch = cb + (lane >> 4);
                const unsigned off = (unsigned)(r * 128 + ((ch ^ (r & 7)) << 4));
                ldsm4(ahi[mt], sAhi + off);
                ldsm4(alo[mt], sAlo + off);
            }
#pragma unroll
            for (int jp = 0; jp < 4; jp++) {
                const int rn = n0 + jp * 16 + ((lane >> 4) << 3) + (lane & 7);
                const int ch = cb + ((lane >> 3) & 1);
                boff[jp] = (unsigned)(rn * 128 + ((ch ^ (rn & 7)) << 4));
                ldsm4(bfr[jp], sBhi + boff[jp]);
            }
            // pass 1: Ahi*Bhi ; pass 2: Alo*Bhi
#pragma unroll
            for (int mt = 0; mt < 2; mt++)
#pragma unroll
                for (int nt = 0; nt < 8; nt++) {
                    mma16816(acc[mt][nt], ahi[mt],
                             bfr[nt >> 1][(nt & 1) * 2],
                             bfr[nt >> 1][(nt & 1) * 2 + 1]);
                    mma16816(acc[mt][nt], alo[mt],
                             bfr[nt >> 1][(nt & 1) * 2],
                             bfr[nt >> 1][(nt & 1) * 2 + 1]);
                }
            // pass 3: Ahi*Blo
#pragma unroll
            for (int jp = 0; jp < 4; jp++)
                ldsm4(bfr[jp], sBlo + boff[jp]);
#pragma unroll
            for (int mt = 0; mt < 2; mt++)
#pragma unroll
                for (int nt = 0; nt < 8; nt++)
                    mma16816(acc[mt][nt], ahi[mt],
                             bfr[nt >> 1][(nt & 1) * 2],
                             bfr[nt >> 1][(nt & 1) * 2 + 1]);
        }
        sidx++; if (sidx >= 3) sidx -= 3;
    }
#undef ISSUE_TILE

    // ---------------- epilogue ----------------
    const int g  = lane >> 2;
    const int t4 = lane & 3;
#pragma unroll
    for (int nt = 0; nt < 8; nt++) {
        const int col = col0 + n0 + nt * 8 + 2 * t4;
        const float b0 = bias[col];
        const float b1 = bias[col + 1];
#pragma unroll
        for (int mt = 0; mt < 2; mt++) {
            const int rtop = row0 + m0 + mt * 16 + g;
#pragma unroll
            for (int half = 0; half < 2; half++) {
                const int r = rtop + half * 8;
                float v0 = acc[mt][nt][half * 2 + 0] + b0;
                float v1 = acc[mt][nt][half * 2 + 1] + b1;
                if (ACT == 1) { v0 = sigmoidf_(v0); v1 = sigmoidf_(v1); }
                else if (ACT == 2) { v0 = v0 * sigmoidf_(v0); v1 = v1 * sigmoidf_(v1); }
                if (SPLIT) {
                    __nv_bfloat16* orow = Cs + (size_t)r * (2 * N);
                    __nv_bfloat16 h0, l0, h1, l1;
                    split_bf16(v0, h0, l0);
                    split_bf16(v1, h1, l1);
                    *(__nv_bfloat162*)(orow + col)     = __nv_bfloat162(h0, h1);
                    *(__nv_bfloat162*)(orow + N + col) = __nv_bfloat162(l0, l1);
                } else {
                    float* orow = Cf + (size_t)r * N;
                    if (RESID) {
                        float2 old = *(float2*)(orow + col);
                        v0 += old.x; v1 += old.y;
                    }
                    *(float2*)(orow + col) = make_float2(v0, v1);
                }
            }
        }
    }
}

// ========== batched weight prep: ALL weights in one launch ======================
// z in [0, 5*NL]: z<5*NL -> layer l=z/5, type z%5; z==5*NL -> W_proj.
__global__ __launch_bounds__(256) void prep_all(
    const float* __restrict__ W_proj, const float* __restrict__ W_in,
    const float* __restrict__ W_gate, const float* __restrict__ W_out,
    const float* __restrict__ W_ff1,  const float* __restrict__ W_ff2,
    __nv_bfloat16* __restrict__ o_proj, __nv_bfloat16* __restrict__ o_in,
    __nv_bfloat16* __restrict__ o_gate, __nv_bfloat16* __restrict__ o_out,
    __nv_bfloat16* __restrict__ o_ff1,  __nv_bfloat16* __restrict__ o_ff2)
{
    const int z = blockIdx.z;
    const float* W; __nv_bfloat16* Bp; int K, N;
    if (z < 5 * NL) {
        const int l = z / 5, t = z - l * 5;
        switch (t) {
            case 0: W = W_in   + (size_t)l * DD * DD; Bp = o_in   + (size_t)l * DD * 2 * DD; K = DD; N = DD; break;
            case 1: W = W_gate + (size_t)l * DD * DD; Bp = o_gate + (size_t)l * DD * 2 * DD; K = DD; N = DD; break;
            case 2: W = W_out  + (size_t)l * DD * DD; Bp = o_out  + (size_t)l * DD * 2 * DD; K = DD; N = DD; break;
            case 3: W = W_ff1  + (size_t)l * DD * D2; Bp = o_ff1  + (size_t)l * D2 * 2 * DD; K = DD; N = D2; break;
            default:W = W_ff2  + (size_t)l * D2 * DD; Bp = o_ff2  + (size_t)l * DD * 2 * D2; K = D2; N = DD; break;
        }
    } else {
        W = W_proj; Bp = o_proj; K = DIN; N = DD;
    }
    const int n = blockIdx.x * 32 + (threadIdx.x & 31);
    if (n >= N) return;
    const int k0 = blockIdx.y * 128 + (threadIdx.x >> 5) * 16;
    if (k0 >= K) return;
    __nv_bfloat16* orow = Bp + (size_t)n * 2 * K;
#pragma unroll
    for (int i = 0; i < 16; i++) {
        float v = W[(size_t)(k0 + i) * N + n];
        __nv_bfloat16 hi, lo;
        split_bf16(v, hi, lo);
        orow[k0 + i]     = hi;
        orow[K + k0 + i] = lo;
    }
}

// ================= node prep: fp32 [L,DIN] -> bf16 [L,2*DIN] [hi|lo] ============
__global__ __launch_bounds__(256) void prep_node(
    const float* __restrict__ X, __nv_bfloat16* __restrict__ Ap)
{
    const int idx = blockIdx.x * 256 + threadIdx.x;
    const int r = idx / DIN, k = idx % DIN;
    float v = X[idx];
    __nv_bfloat16 hi, lo;
    split_bf16(v, hi, lo);
    __nv_bfloat16* orow = Ap + (size_t)r * 2 * DIN;
    orow[k]       = hi;
    orow[DIN + k] = lo;
}

// ================= LayerNorm -> split bf16 A' [L, 2*DD] =========================
__global__ __launch_bounds__(256) void ln_split_kernel(
    const float* __restrict__ x, const float* __restrict__ gam,
    const float* __restrict__ bet, __nv_bfloat16* __restrict__ out)
{
    __shared__ float red[8];
    __shared__ float bcast;
    const int tid = threadIdx.x;
    const float* xr = x + (size_t)blockIdx.x * DD;

    float v0 = xr[tid], v1 = xr[tid + 256], v2 = xr[tid + 512];
    float sum = v0 + v1 + v2;
#pragma unroll
    for (int o = 16; o > 0; o >>= 1) sum += __shfl_xor_sync(0xffffffffu, sum, o);
    if ((tid & 31) == 0) red[tid >> 5] = sum;
    __syncthreads();
    if (tid == 0) {
        float t = 0.f;
#pragma unroll
        for (int i = 0; i < 8; i++) t += red[i];
        bcast = t * (1.0f / DD);
    }
    __syncthreads();
    const float mu = bcast;
    float d0 = v0 - mu, d1 = v1 - mu, d2 = v2 - mu;
    float sq = d0 * d0 + d1 * d1 + d2 * d2;
#pragma unroll
    for (int o = 16; o > 0; o >>= 1) sq += __shfl_xor_sync(0xffffffffu, sq, o);
    __syncthreads();
    if ((tid & 31) == 0) red[tid >> 5] = sq;
    __syncthreads();
    if (tid == 0) {
        float t = 0.f;
#pragma unroll
        for (int i = 0; i < 8; i++) t += red[i];
        bcast = rsqrtf(t * (1.0f / DD) + 1e-5f);
    }
    __syncthreads();
    const float inv = bcast;

    __nv_bfloat16* orow = out + (size_t)blockIdx.x * (2 * DD);
#pragma unroll
    for (int q = 0; q < 3; q++) {
        const int j = tid + q * 256;
        const float dv = (q == 0 ? d0 : (q == 1 ? d1 : d2));
        float v = dv * inv * gam[j] + bet[j];
        __nv_bfloat16 hi, lo;
        split_bf16(v, hi, lo);
        orow[j]      = hi;
        orow[DD + j] = lo;
    }
}

// ================= final LayerNorm (fp32 out) ===================================
__global__ __launch_bounds__(256) void ln_final_kernel(
    const float* __restrict__ x, const float* __restrict__ gam,
    const float* __restrict__ bet, float* __restrict__ out)
{
    __shared__ float red[8];
    __shared__ float bcast;
    const int tid = threadIdx.x;
    const float* xr = x + (size_t)blockIdx.x * DD;

    float v0 = xr[tid], v1 = xr[tid + 256], v2 = xr[tid + 512];
    float sum = v0 + v1 + v2;
#pragma unroll
    for (int o = 16; o > 0; o >>= 1) sum += __shfl_xor_sync(0xffffffffu, sum, o);
    if ((tid & 31) == 0) red[tid >> 5] = sum;
    __syncthreads();
    if (tid == 0) {
        float t = 0.f;
#pragma unroll
        for (int i = 0; i < 8; i++) t += red[i];
        bcast = t * (1.0f / DD);
    }
    __syncthreads();
    const float mu = bcast;
    float d0 = v0 - mu, d1 = v1 - mu, d2 = v2 - mu;
    float sq = d0 * d0 + d1 * d1 + d2 * d2;
#pragma unroll
    for (int o = 16; o > 0; o >>= 1) sq += __shfl_xor_sync(0xffffffffu, sq, o);
    __syncthreads();
    if ((tid & 31) == 0) red[tid >> 5] = sq;
    __syncthreads();
    if (tid == 0) {
        float t = 0.f;
#pragma unroll
        for (int i = 0; i < 8; i++) t += red[i];
        bcast = rsqrtf(t * (1.0f / DD) + 1e-5f);
    }
    __syncthreads();
    const float inv = bcast;

    float* orow = out + (size_t)blockIdx.x * DD;
    orow[tid]       = d0 * inv * gam[tid]       + bet[tid];
    orow[tid + 256] = d1 * inv * gam[tid + 256] + bet[tid + 256];
    orow[tid + 512] = d2 * inv * gam[tid + 512] + bet[tid + 512];
}

// ================= scan kernels =================================================
__global__ __launch_bounds__(256) void scan_chunk_kernel(
    const float* __restrict__ u, const float* __restrict__ dlogit,
    float* __restrict__ Sout)
{
    const int d = blockIdx.x * 256 + threadIdx.x;
    const int c = blockIdx.y;
    const float decay = sigmoidf_(dlogit[d]);
    const float* p = u + ((size_t)c * CLEN) * DD + d;
    float s = 0.0f;
#pragma unroll 8
    for (int t = 0; t < CLEN; t++) s = fmaf(decay, s, p[(size_t)t * DD]);
    Sout[c * DD + d] = s;
}

__global__ __launch_bounds__(768) void scan_carry_kernel(
    const float* __restrict__ Sin, const float* __restrict__ dlogit,
    float* __restrict__ carry)
{
    const int d = threadIdx.x;
    const float decay = sigmoidf_(dlogit[d]);
    float A = decay;
#pragma unroll
    for (int i = 0; i < 7; i++) A = A * A;   // decay^128
    float c = 0.0f;
    for (int k = 0; k < NCHUNK; k++) {
        carry[k * DD + d] = c;
        c = fmaf(A, c, Sin[k * DD + d]);
    }
}

// re-scan with carry, gate-multiply, emit split bf16 A' [L, 2*DD]
__global__ __launch_bounds__(256) void scan_apply_split_kernel(
    const float* __restrict__ u, const float* __restrict__ gate,
    const float* __restrict__ dlogit, const float* __restrict__ carry,
    __nv_bfloat16* __restrict__ out)
{
    const int d = blockIdx.x * 256 + threadIdx.x;
    const int c = blockIdx.y;
    const float decay = sigmoidf_(dlogit[d]);
    const size_t base = ((size_t)c * CLEN) * DD + d;
    float s = carry[c * DD + d];
#pragma unroll 4
    for (int t = 0; t < CLEN; t++) {
        const size_t idx = base + (size_t)t * DD;
        s = fmaf(decay, s, u[idx]);
        float v = s * gate[idx];
        __nv_bfloat16 hi, lo;
        split_bf16(v, hi, lo);
        __nv_bfloat16* orow = out + (size_t)(c * CLEN + t) * (2 * DD);
        orow[d]      = hi;
        orow[DD + d] = lo;
    }
}

// ================= host =========================================================
extern "C" void kernel_launch(void* const* d_in, const int* in_sizes, int n_in,
                              void* d_out, int out_size)
{
    const float* node    = (const float*)d_in[0];
    const float* W_proj  = (const float*)d_in[1];
    const float* b_proj  = (const float*)d_in[2];
    const float* ln_s_g  = (const float*)d_in[3];
    const float* ln_s_b  = (const float*)d_in[4];
    const float* W_in    = (const float*)d_in[5];
    const float* b_in    = (const float*)d_in[6];
    const float* W_gate  = (const float*)d_in[7];
    const float* b_gate  = (const float*)d_in[8];
    const float* W_out   = (const float*)d_in[9];
    const float* b_out   = (const float*)d_in[10];
    const float* dlogit  = (const float*)d_in[11];
    const float* ln_f_g  = (const float*)d_in[12];
    const float* ln_f_b  = (const float*)d_in[13];
    const float* W_ff1   = (const float*)d_in[14];
    const float* b_ff1   = (const float*)d_in[15];
    const float* W_ff2   = (const float*)d_in[16];
    const float* b_ff2   = (const float*)d_in[17];
    const float* ln_o_g  = (const float*)d_in[18];
    const float* ln_o_b  = (const float*)d_in[19];

    float *x, *u, *gate, *S, *carry;
    __nv_bfloat16 *a_node, *a_h, *a_s, *a_t;
    __nv_bfloat16 *w_proj, *w_in, *w_gt, *w_ot, *w_f1, *w_f2;
    cudaGetSymbolAddress((void**)&x,     g_x);
    cudaGetSymbolAddress((void**)&u,     g_u);
    cudaGetSymbolAddress((void**)&gate,  g_gate);
    cudaGetSymbolAddress((void**)&S,     g_S);
    cudaGetSymbolAddress((void**)&carry, g_carry);
    cudaGetSymbolAddress((void**)&a_node, ab_node);
    cudaGetSymbolAddress((void**)&a_h,    ab_h);
    cudaGetSymbolAddress((void**)&a_s,    ab_s);
    cudaGetSymbolAddress((void**)&a_t,    ab_t);
    cudaGetSymbolAddress((void**)&w_proj, wb_proj);
    cudaGetSymbolAddress((void**)&w_in,   wb_in);
    cudaGetSymbolAddress((void**)&w_gt,   wb_gate);
    cudaGetSymbolAddress((void**)&w_ot,   wb_out);
    cudaGetSymbolAddress((void**)&w_f1,   wb_ff1);
    cudaGetSymbolAddress((void**)&w_f2,   wb_ff2);

    cudaFuncSetAttribute(tc_gemm<0, false, false>, cudaFuncAttributeMaxDynamicSharedMemorySize, GEMM_SMEM_BYTES);
    cudaFuncSetAttribute(tc_gemm<1, false, false>, cudaFuncAttributeMaxDynamicSharedMemorySize, GEMM_SMEM_BYTES);
    cudaFuncSetAttribute(tc_gemm<0, true,  false>, cudaFuncAttributeMaxDynamicSharedMemorySize, GEMM_SMEM_BYTES);
    cudaFuncSetAttribute(tc_gemm<2, false, true >, cudaFuncAttributeMaxDynamicSharedMemorySize, GEMM_SMEM_BYTES);

    const dim3 blk(256);
    const dim3 gScan(DD / 256, NCHUNK);
    const dim3 gG6 (DD / 128, LSEQ / 128);   // N=768
    const dim3 gG12(D2 / 128, LSEQ / 128);   // N=1536

    // ---- prep: activations + ALL weights ----
    prep_node<<<(LSEQ * DIN) / 256, blk>>>(node, a_node);
    prep_all<<<dim3(48, 12, 5 * NL + 1), blk>>>(
        W_proj, W_in, W_gate, W_out, W_ff1, W_ff2,
        w_proj, w_in, w_gt, w_ot, w_f1, w_f2);

    // ---- x = node @ W_proj + b_proj ----
    tc_gemm<0, false, false><<<gG6, blk, GEMM_SMEM_BYTES>>>(
        a_node, w_proj, b_proj, x, nullptr, DIN, DD);

    for (int l = 0; l < NL; l++) {
        const size_t vo = (size_t)l * DD;
        const size_t v1 = (size_t)l * D2;
        const __nv_bfloat16* wi = w_in + (size_t)l * DD * 2 * DD;
        const __nv_bfloat16* wg = w_gt + (size_t)l * DD * 2 * DD;
        const __nv_bfloat16* wo = w_ot + (size_t)l * DD * 2 * DD;
        const __nv_bfloat16* w1 = w_f1 + (size_t)l * D2 * 2 * DD;
        const __nv_bfloat16* w2 = w_f2 + (size_t)l * DD * 2 * D2;

        ln_split_kernel<<<LSEQ, blk>>>(x, ln_s_g + vo, ln_s_b + vo, a_h);
        tc_gemm<0, false, false><<<gG6, blk, GEMM_SMEM_BYTES>>>(
            a_h, wi, b_in + vo, u, nullptr, DD, DD);
        tc_gemm<1, false, false><<<gG6, blk, GEMM_SMEM_BYTES>>>(
            a_h, wg, b_gate + vo, gate, nullptr, DD, DD);
        scan_chunk_kernel<<<gScan, blk>>>(u, dlogit + vo, S);
        scan_carry_kernel<<<1, DD>>>(S, dlogit + vo, carry);
        scan_apply_split_kernel<<<gScan, blk>>>(u, gate, dlogit + vo, carry, a_s);
        tc_gemm<0, true, false><<<gG6, blk, GEMM_SMEM_BYTES>>>(
            a_s, wo, b_out + vo, x, nullptr, DD, DD);
        ln_split_kernel<<<LSEQ, blk>>>(x, ln_f_g + vo, ln_f_b + vo, a_h);
        tc_gemm<2, false, true><<<gG12, blk, GEMM_SMEM_BYTES>>>(
            a_h, w1, b_ff1 + v1, nullptr, a_t, DD, D2);
        tc_gemm<0, true, false><<<gG6, blk, GEMM_SMEM_BYTES>>>(
            a_t, w2, b_ff2 + vo, x, nullptr, D2, DD);
    }

    ln_final_kernel<<<LSEQ, blk>>>(x, ln_o_g, ln_o_b, (float*)d_out);
}

// round 7
// speedup vs baseline: 2.2415x; 1.1409x over previous
#include <cuda_runtime.h>
#include <cuda_bf16.h>
#include <cuda_fp16.h>
#include <math.h>

#define LSEQ 16384
#define DIN  256
#define DD   768
#define D2   1536
#define NL   8
#define NCHUNK 128
#define CLEN   128

// ---------------- fp32 scratch ----------------
__device__ float g_x[(size_t)LSEQ * DD];
__device__ float g_u[(size_t)LSEQ * DD];
__device__ float g_gate[(size_t)LSEQ * DD];
__device__ float g_S[NCHUNK * DD];
__device__ float g_carry[NCHUNK * DD];

// ---- bf16 split activations: row layout [hi(K) | lo(K)], stride 2K ----
__device__ __nv_bfloat16 ab_node[(size_t)LSEQ * 2 * DIN];
__device__ __nv_bfloat16 ab_h[(size_t)LSEQ * 2 * DD];
__device__ __nv_bfloat16 ab_s[(size_t)LSEQ * 2 * DD];
// ---- fp16 split activations for FF branch ----
__device__ __half ah_hf[(size_t)LSEQ * 2 * DD];
__device__ __half ah_t [(size_t)LSEQ * 2 * D2];

// ---- bf16 split weights: [N rows, 2K] [hi|lo] ----
__device__ __nv_bfloat16 wb_proj[(size_t)DD * 2 * DIN];
__device__ __nv_bfloat16 wb_in  [(size_t)NL * DD * 2 * DD];
__device__ __nv_bfloat16 wb_gate[(size_t)NL * DD * 2 * DD];
__device__ __nv_bfloat16 wb_out [(size_t)NL * DD * 2 * DD];
// ---- fp16 single-plane weights for FF branch: [N rows, K] ----
__device__ __half wh_ff1[(size_t)NL * D2 * DD];
__device__ __half wh_ff2[(size_t)NL * DD * D2];

// ================= helpers =================
__device__ __forceinline__ float sigmoidf_(float z) {
    return 1.0f / (1.0f + __expf(-z));
}

__device__ __forceinline__ unsigned smem_u32(const void* p) {
    unsigned a;
    asm("{ .reg .u64 t; cvta.to.shared.u64 t, %1; cvt.u32.u64 %0, t; }"
        : "=r"(a) : "l"(p));
    return a;
}

__device__ __forceinline__ void cpasync16(unsigned s, const void* g) {
    asm volatile("cp.async.cg.shared.global [%0], [%1], 16;"
                 :: "r"(s), "l"(g) : "memory");
}
__device__ __forceinline__ void cp_commit() {
    asm volatile("cp.async.commit_group;" ::: "memory");
}
__device__ __forceinline__ void cp_wait1() {
    asm volatile("cp.async.wait_group 1;" ::: "memory");
}
__device__ __forceinline__ void cp_wait0() {
    asm volatile("cp.async.wait_group 0;" ::: "memory");
}

__device__ __forceinline__ void ldsm4(unsigned* r, unsigned addr) {
    asm volatile("ldmatrix.sync.aligned.m8n8.x4.shared.b16 {%0,%1,%2,%3}, [%4];"
                 : "=r"(r[0]), "=r"(r[1]), "=r"(r[2]), "=r"(r[3]) : "r"(addr));
}

__device__ __forceinline__ void mma16816(float* d, const unsigned* a,
                                         unsigned b0, unsigned b1) {
    asm volatile(
        "mma.sync.aligned.m16n8k16.row.col.f32.bf16.bf16.f32 "
        "{%0,%1,%2,%3}, {%4,%5,%6,%7}, {%8,%9}, {%0,%1,%2,%3};"
        : "+f"(d[0]), "+f"(d[1]), "+f"(d[2]), "+f"(d[3])
        : "r"(a[0]), "r"(a[1]), "r"(a[2]), "r"(a[3]), "r"(b0), "r"(b1));
}

__device__ __forceinline__ void mma16816h(float* d, const unsigned* a,
                                          unsigned b0, unsigned b1) {
    asm volatile(
        "mma.sync.aligned.m16n8k16.row.col.f32.f16.f16.f32 "
        "{%0,%1,%2,%3}, {%4,%5,%6,%7}, {%8,%9}, {%0,%1,%2,%3};"
        : "+f"(d[0]), "+f"(d[1]), "+f"(d[2]), "+f"(d[3])
        : "r"(a[0]), "r"(a[1]), "r"(a[2]), "r"(a[3]), "r"(b0), "r"(b1));
}

__device__ __forceinline__ void split_bf16(float v, __nv_bfloat16& hi, __nv_bfloat16& lo) {
    hi = __float2bfloat16(v);
    lo = __float2bfloat16(v - __bfloat162float(hi));
}
__device__ __forceinline__ void split_fp16(float v, __half& hi, __half& lo) {
    hi = __float2half_rn(v);
    lo = __float2half_rn(v - __half2float(hi));
}

// ================= 3-pass bf16 GEMM (plane-split both sides) =================
// C = epilogue(Ahi·Bhi + Alo·Bhi + Ahi·Blo + bias)
// Tile 128x128xBK64, 256 thr, 8 warps 4Mx2N (warp 32x64), 3-stage cp.async.
#define GEMM_SMEM_BYTES (3 * 65536)

template<int ACT, bool RESID>
__global__ __launch_bounds__(256) void tc_gemm(
    const __nv_bfloat16* __restrict__ A, const __nv_bfloat16* __restrict__ B,
    const float* __restrict__ bias, float* __restrict__ Cf, int K, int N)
{
    extern __shared__ __align__(1024) char smem[];
    const unsigned sbase = smem_u32(smem);
    const int tid  = threadIdx.x;
    const int wid  = tid >> 5;
    const int lane = tid & 31;
    const int K2 = 2 * K;

    const int row0 = blockIdx.y * 128;
    const int col0 = blockIdx.x * 128;

    const int m0 = (wid & 3) * 32;
    const int n0 = (wid >> 2) * 64;

    float acc[2][8][4];
#pragma unroll
    for (int i = 0; i < 2; i++)
#pragma unroll
        for (int j = 0; j < 8; j++)
#pragma unroll
            for (int q = 0; q < 4; q++) acc[i][j][q] = 0.0f;

    const int lrow = tid >> 1;
    const int lc0  = (tid & 1) * 4;
    const __nv_bfloat16* agp = A + (size_t)(row0 + lrow) * K2;
    const __nv_bfloat16* bgp = B + (size_t)(col0 + lrow) * K2;

    const int NC = K / 64;

#define ISSUE_TILE(ct, s) do {                                              \
        const unsigned sb_ = sbase + (unsigned)(s) * 65536u;                \
        const int kb_ = (ct) * 64;                                          \
        _Pragma("unroll")                                                   \
        for (int i_ = 0; i_ < 4; i_++) {                                    \
            const int c_ = lc0 + i_;                                        \
            const unsigned off_ = (unsigned)(lrow * 128 + ((c_ ^ (lrow & 7)) << 4)); \
            cpasync16(sb_ + off_,          agp + kb_ + c_ * 8);             \
            cpasync16(sb_ + 16384u + off_, agp + K + kb_ + c_ * 8);         \
            cpasync16(sb_ + 32768u + off_, bgp + kb_ + c_ * 8);             \
            cpasync16(sb_ + 49152u + off_, bgp + K + kb_ + c_ * 8);         \
        }                                                                   \
    } while (0)

    ISSUE_TILE(0, 0);
    cp_commit();
    if (NC > 1) { ISSUE_TILE(1, 1); }
    cp_commit();

    int sidx = 0;
    for (int c = 0; c < NC; c++) {
        if (c + 1 < NC) cp_wait1(); else cp_wait0();
        __syncthreads();

        if (c + 2 < NC) {
            int fs = sidx + 2; if (fs >= 3) fs -= 3;
            ISSUE_TILE(c + 2, fs);
            cp_commit();
        }

        const unsigned sAhi = sbase + (unsigned)sidx * 65536u;
        const unsigned sAlo = sAhi + 16384u;
        const unsigned sBhi = sAhi + 32768u;
        const unsigned sBlo = sAhi + 49152u;

#pragma unroll
        for (int kk4 = 0; kk4 < 4; kk4++) {
            const int cb = kk4 * 2;
            unsigned ahi[2][4], alo[2][4], bfr[4][4];
            unsigned boff[4];
#pragma unroll
            for (int mt = 0; mt < 2; mt++) {
                const int r = m0 + mt * 16 + (lane & 15);
                const int ch = cb + (lane >> 4);
                const unsigned off = (unsigned)(r * 128 + ((ch ^ (r & 7)) << 4));
                ldsm4(ahi[mt], sAhi + off);
                ldsm4(alo[mt], sAlo + off);
            }
#pragma unroll
            for (int jp = 0; jp < 4; jp++) {
                const int rn = n0 + jp * 16 + ((lane >> 4) << 3) + (lane & 7);
                const int ch = cb + ((lane >> 3) & 1);
                boff[jp] = (unsigned)(rn * 128 + ((ch ^ (rn & 7)) << 4));
                ldsm4(bfr[jp], sBhi + boff[jp]);
            }
#pragma unroll
            for (int mt = 0; mt < 2; mt++)
#pragma unroll
                for (int nt = 0; nt < 8; nt++) {
                    mma16816(acc[mt][nt], ahi[mt],
                             bfr[nt >> 1][(nt & 1) * 2],
                             bfr[nt >> 1][(nt & 1) * 2 + 1]);
                    mma16816(acc[mt][nt], alo[mt],
                             bfr[nt >> 1][(nt & 1) * 2],
                             bfr[nt >> 1][(nt & 1) * 2 + 1]);
                }
#pragma unroll
            for (int jp = 0; jp < 4; jp++)
                ldsm4(bfr[jp], sBlo + boff[jp]);
#pragma unroll
            for (int mt = 0; mt < 2; mt++)
#pragma unroll
                for (int nt = 0; nt < 8; nt++)
                    mma16816(acc[mt][nt], ahi[mt],
                             bfr[nt >> 1][(nt & 1) * 2],
                             bfr[nt >> 1][(nt & 1) * 2 + 1]);
        }
        sidx++; if (sidx >= 3) sidx -= 3;
    }
#undef ISSUE_TILE

    const int g  = lane >> 2;
    const int t4 = lane & 3;
#pragma unroll
    for (int nt = 0; nt < 8; nt++) {
        const int col = col0 + n0 + nt * 8 + 2 * t4;
        const float b0 = bias[col];
        const float b1 = bias[col + 1];
#pragma unroll
        for (int mt = 0; mt < 2; mt++) {
            const int rtop = row0 + m0 + mt * 16 + g;
#pragma unroll
            for (int half = 0; half < 2; half++) {
                const int r = rtop + half * 8;
                float v0 = acc[mt][nt][half * 2 + 0] + b0;
                float v1 = acc[mt][nt][half * 2 + 1] + b1;
                if (ACT == 1) { v0 = sigmoidf_(v0); v1 = sigmoidf_(v1); }
                float* orow = Cf + (size_t)r * N;
                if (RESID) {
                    float2 old = *(float2*)(orow + col);
                    v0 += old.x; v1 += old.y;
                }
                *(float2*)(orow + col) = make_float2(v0, v1);
            }
        }
    }
}

// ================= 2-pass fp16 GEMM (A split hi/lo, B single plane) =============
// C = epilogue(Ahi·B + Alo·B + bias).  A rows [hi(K)|lo(K)] fp16; B [N,K] fp16.
// Stage = Ahi 16K + Alo 16K + B 16K = 48KB; 3 stages.
#define GEMM2_SMEM_BYTES (3 * 49152)

template<int ACT, bool RESID, bool SPLIT>
__global__ __launch_bounds__(256) void tc_gemm2(
    const __half* __restrict__ A, const __half* __restrict__ B,
    const float* __restrict__ bias, float* __restrict__ Cf,
    __half* __restrict__ Cs, int K, int N)
{
    extern __shared__ __align__(1024) char smem[];
    const unsigned sbase = smem_u32(smem);
    const int tid  = threadIdx.x;
    const int wid  = tid >> 5;
    const int lane = tid & 31;
    const int K2 = 2 * K;

    const int row0 = blockIdx.y * 128;
    const int col0 = blockIdx.x * 128;

    const int m0 = (wid & 3) * 32;
    const int n0 = (wid >> 2) * 64;

    float acc[2][8][4];
#pragma unroll
    for (int i = 0; i < 2; i++)
#pragma unroll
        for (int j = 0; j < 8; j++)
#pragma unroll
            for (int q = 0; q < 4; q++) acc[i][j][q] = 0.0f;

    const int lrow = tid >> 1;
    const int lc0  = (tid & 1) * 4;
    const __half* agp = A + (size_t)(row0 + lrow) * K2;
    const __half* bgp = B + (size_t)(col0 + lrow) * K;

    const int NC = K / 64;

#define ISSUE_TILE2(ct, s) do {                                             \
        const unsigned sb_ = sbase + (unsigned)(s) * 49152u;                \
        const int kb_ = (ct) * 64;                                          \
        _Pragma("unroll")                                                   \
        for (int i_ = 0; i_ < 4; i_++) {                                    \
            const int c_ = lc0 + i_;                                        \
            const unsigned off_ = (unsigned)(lrow * 128 + ((c_ ^ (lrow & 7)) << 4)); \
            cpasync16(sb_ + off_,          agp + kb_ + c_ * 8);             \
            cpasync16(sb_ + 16384u + off_, agp + K + kb_ + c_ * 8);         \
            cpasync16(sb_ + 32768u + off_, bgp + kb_ + c_ * 8);             \
        }                                                                   \
    } while (0)

    ISSUE_TILE2(0, 0);
    cp_commit();
    if (NC > 1) { ISSUE_TILE2(1, 1); }
    cp_commit();

    int sidx = 0;
    for (int c = 0; c < NC; c++) {
        if (c + 1 < NC) cp_wait1(); else cp_wait0();
        __syncthreads();

        if (c + 2 < NC) {
            int fs = sidx + 2; if (fs >= 3) fs -= 3;
            ISSUE_TILE2(c + 2, fs);
            cp_commit();
        }

        const unsigned sAhi = sbase + (unsigned)sidx * 49152u;
        const unsigned sAlo = sAhi + 16384u;
        const unsigned sB   = sAhi + 32768u;

#pragma unroll
        for (int kk4 = 0; kk4 < 4; kk4++) {
            const int cb = kk4 * 2;
            unsigned ahi[2][4], alo[2][4], bfr[4][4];
#pragma unroll
            for (int mt = 0; mt < 2; mt++) {
                const int r = m0 + mt * 16 + (lane & 15);
                const int ch = cb + (lane >> 4);
                const unsigned off = (unsigned)(r * 128 + ((ch ^ (r & 7)) << 4));
                ldsm4(ahi[mt], sAhi + off);
                ldsm4(alo[mt], sAlo + off);
            }
#pragma unroll
            for (int jp = 0; jp < 4; jp++) {
                const int rn = n0 + jp * 16 + ((lane >> 4) << 3) + (lane & 7);
                const int ch = cb + ((lane >> 3) & 1);
                ldsm4(bfr[jp], sB + (unsigned)(rn * 128 + ((ch ^ (rn & 7)) << 4)));
            }
#pragma unroll
            for (int mt = 0; mt < 2; mt++)
#pragma unroll
                for (int nt = 0; nt < 8; nt++) {
                    mma16816h(acc[mt][nt], ahi[mt],
                              bfr[nt >> 1][(nt & 1) * 2],
                              bfr[nt >> 1][(nt & 1) * 2 + 1]);
                    mma16816h(acc[mt][nt], alo[mt],
                              bfr[nt >> 1][(nt & 1) * 2],
                              bfr[nt >> 1][(nt & 1) * 2 + 1]);
                }
        }
        sidx++; if (sidx >= 3) sidx -= 3;
    }
#undef ISSUE_TILE2

    const int g  = lane >> 2;
    const int t4 = lane & 3;
#pragma unroll
    for (int nt = 0; nt < 8; nt++) {
        const int col = col0 + n0 + nt * 8 + 2 * t4;
        const float b0 = bias[col];
        const float b1 = bias[col + 1];
#pragma unroll
        for (int mt = 0; mt < 2; mt++) {
            const int rtop = row0 + m0 + mt * 16 + g;
#pragma unroll
            for (int half = 0; half < 2; half++) {
                const int r = rtop + half * 8;
                float v0 = acc[mt][nt][half * 2 + 0] + b0;
                float v1 = acc[mt][nt][half * 2 + 1] + b1;
                if (ACT == 2) { v0 = v0 * sigmoidf_(v0); v1 = v1 * sigmoidf_(v1); }
                if (SPLIT) {
                    __half* orow = Cs + (size_t)r * (2 * N);
                    __half h0, l0, h1, l1;
                    split_fp16(v0, h0, l0);
                    split_fp16(v1, h1, l1);
                    *(__half2*)(orow + col)     = __halves2half2(h0, h1);
                    *(__half2*)(orow + N + col) = __halves2half2(l0, l1);
                } else {
                    float* orow = Cf + (size_t)r * N;
                    if (RESID) {
                        float2 old = *(float2*)(orow + col);
                        v0 += old.x; v1 += old.y;
                    }
                    *(float2*)(orow + col) = make_float2(v0, v1);
                }
            }
        }
    }
}

// ========== batched prep: ALL weights + node activations in ONE launch ==========
// z<5*NL: layer l=z/5, type z%5 {in,gate,out -> bf16 2-plane; ff1,ff2 -> fp16 1-plane}
// z==5*NL: node activations (transposed read, bf16 2-plane A-layout).
__global__ __launch_bounds__(256) void prep_all(
    const float* __restrict__ node,
    const float* __restrict__ W_proj, const float* __restrict__ W_in,
    const float* __restrict__ W_gate, const float* __restrict__ W_out,
    const float* __restrict__ W_ff1,  const float* __restrict__ W_ff2,
    __nv_bfloat16* __restrict__ o_node, __nv_bfloat16* __restrict__ o_proj,
    __nv_bfloat16* __restrict__ o_in, __nv_bfloat16* __restrict__ o_gate,
    __nv_bfloat16* __restrict__ o_out,
    __half* __restrict__ o_ff1, __half* __restrict__ o_ff2)
{
    const int z = blockIdx.z;
    const int nidx = blockIdx.x * 32 + (threadIdx.x & 31);
    const int k0 = blockIdx.y * 128 + (threadIdx.x >> 5) * 16;

    if (z == 5 * NL + 1) {
        // node: A[L,DIN] -> o_node[L, 2*DIN]
        if (nidx >= LSEQ || k0 >= DIN) return;
        const float* xr = node + (size_t)nidx * DIN;
        __nv_bfloat16* orow = o_node + (size_t)nidx * 2 * DIN;
#pragma unroll
        for (int i = 0; i < 16; i++) {
            __nv_bfloat16 hi, lo;
            split_bf16(xr[k0 + i], hi, lo);
            orow[k0 + i]       = hi;
            orow[DIN + k0 + i] = lo;
        }
        return;
    }

    const float* W; int K, N;
    if (z == 5 * NL) { W = W_proj; K = DIN; N = DD; }
    else {
        const int l = z / 5, t = z - l * 5;
        switch (t) {
            case 0: W = W_in   + (size_t)l * DD * DD; K = DD; N = DD; break;
            case 1: W = W_gate + (size_t)l * DD * DD; K = DD; N = DD; break;
            case 2: W = W_out  + (size_t)l * DD * DD; K = DD; N = DD; break;
            case 3: W = W_ff1  + (size_t)l * DD * D2; K = DD; N = D2; break;
            default:W = W_ff2  + (size_t)l * D2 * DD; K = D2; N = DD; break;
        }
    }
    if (nidx >= N || k0 >= K) return;

    const int t = (z < 5 * NL) ? (z % 5) : -1;
    if (t == 3 || t == 4) {
        const int l = z / 5;
        __half* orow = (t == 3) ? (o_ff1 + (size_t)l * D2 * DD + (size_t)nidx * DD)
                                : (o_ff2 + (size_t)l * DD * D2 + (size_t)nidx * D2);
#pragma unroll
        for (int i = 0; i < 16; i++)
            orow[k0 + i] = __float2half_rn(W[(size_t)(k0 + i) * N + nidx]);
    } else {
        __nv_bfloat16* Bp;
        if (z == 5 * NL) Bp = o_proj;
        else {
            const int l = z / 5;
            Bp = (t == 0) ? o_in + (size_t)l * DD * 2 * DD
               : (t == 1) ? o_gate + (size_t)l * DD * 2 * DD
                          : o_out + (size_t)l * DD * 2 * DD;
        }
        __nv_bfloat16* orow = Bp + (size_t)nidx * 2 * K;
#pragma unroll
        for (int i = 0; i < 16; i++) {
            __nv_bfloat16 hi, lo;
            split_bf16(W[(size_t)(k0 + i) * N + nidx], hi, lo);
            orow[k0 + i]     = hi;
            orow[K + k0 + i] = lo;
        }
    }
}

// ================= LayerNorm -> split bf16 [L, 2*DD] ============================
__global__ __launch_bounds__(256) void ln_split_kernel(
    const float* __restrict__ x, const float* __restrict__ gam,
    const float* __restrict__ bet, __nv_bfloat16* __restrict__ out)
{
    __shared__ float red[8];
    __shared__ float bcast;
    const int tid = threadIdx.x;
    const float* xr = x + (size_t)blockIdx.x * DD;

    float v0 = xr[tid], v1 = xr[tid + 256], v2 = xr[tid + 512];
    float sum = v0 + v1 + v2;
#pragma unroll
    for (int o = 16; o > 0; o >>= 1) sum += __shfl_xor_sync(0xffffffffu, sum, o);
    if ((tid & 31) == 0) red[tid >> 5] = sum;
    __syncthreads();
    if (tid == 0) {
        float t = 0.f;
#pragma unroll
        for (int i = 0; i < 8; i++) t += red[i];
        bcast = t * (1.0f / DD);
    }
    __syncthreads();
    const float mu = bcast;
    float d0 = v0 - mu, d1 = v1 - mu, d2 = v2 - mu;
    float sq = d0 * d0 + d1 * d1 + d2 * d2;
#pragma unroll
    for (int o = 16; o > 0; o >>= 1) sq += __shfl_xor_sync(0xffffffffu, sq, o);
    __syncthreads();
    if ((tid & 31) == 0) red[tid >> 5] = sq;
    __syncthreads();
    if (tid == 0) {
        float t = 0.f;
#pragma unroll
        for (int i = 0; i < 8; i++) t += red[i];
        bcast = rsqrtf(t * (1.0f / DD) + 1e-5f);
    }
    __syncthreads();
    const float inv = bcast;

    __nv_bfloat16* orow = out + (size_t)blockIdx.x * (2 * DD);
#pragma unroll
    for (int q = 0; q < 3; q++) {
        const int j = tid + q * 256;
        const float dv = (q == 0 ? d0 : (q == 1 ? d1 : d2));
        float v = dv * inv * gam[j] + bet[j];
        __nv_bfloat16 hi, lo;
        split_bf16(v, hi, lo);
        orow[j]      = hi;
        orow[DD + j] = lo;
    }
}

// ================= LayerNorm -> split fp16 [L, 2*DD] ============================
__global__ __launch_bounds__(256) void ln_split_f16_kernel(
    const float* __restrict__ x, const float* __restrict__ gam,
    const float* __restrict__ bet, __half* __restrict__ out)
{
    __shared__ float red[8];
    __shared__ float bcast;
    const int tid = threadIdx.x;
    const float* xr = x + (size_t)blockIdx.x * DD;

    float v0 = xr[tid], v1 = xr[tid + 256], v2 = xr[tid + 512];
    float sum = v0 + v1 + v2;
#pragma unroll
    for (int o = 16; o > 0; o >>= 1) sum += __shfl_xor_sync(0xffffffffu, sum, o);
    if ((tid & 31) == 0) red[tid >> 5] = sum;
    __syncthreads();
    if (tid == 0) {
        float t = 0.f;
#pragma unroll
        for (int i = 0; i < 8; i++) t += red[i];
        bcast = t * (1.0f / DD);
    }
    __syncthreads();
    const float mu = bcast;
    float d0 = v0 - mu, d1 = v1 - mu, d2 = v2 - mu;
    float sq = d0 * d0 + d1 * d1 + d2 * d2;
#pragma unroll
    for (int o = 16; o > 0; o >>= 1) sq += __shfl_xor_sync(0xffffffffu, sq, o);
    __syncthreads();
    if ((tid & 31) == 0) red[tid >> 5] = sq;
    __syncthreads();
    if (tid == 0) {
        float t = 0.f;
#pragma unroll
        for (int i = 0; i < 8; i++) t += red[i];
        bcast = rsqrtf(t * (1.0f / DD) + 1e-5f);
    }
    __syncthreads();
    const float inv = bcast;

    __half* orow = out + (size_t)blockIdx.x * (2 * DD);
#pragma unroll
    for (int q = 0; q < 3; q++) {
        const int j = tid + q * 256;
        const float dv = (q == 0 ? d0 : (q == 1 ? d1 : d2));
        float v = dv * inv * gam[j] + bet[j];
        __half hi, lo;
        split_fp16(v, hi, lo);
        orow[j]      = hi;
        orow[DD + j] = lo;
    }
}

// ================= final LayerNorm (fp32 out) ===================================
__global__ __launch_bounds__(256) void ln_final_kernel(
    const float* __restrict__ x, const float* __restrict__ gam,
    const float* __restrict__ bet, float* __restrict__ out)
{
    __shared__ float red[8];
    __shared__ float bcast;
    const int tid = threadIdx.x;
    const float* xr = x + (size_t)blockIdx.x * DD;

    float v0 = xr[tid], v1 = xr[tid + 256], v2 = xr[tid + 512];
    float sum = v0 + v1 + v2;
#pragma unroll
    for (int o = 16; o > 0; o >>= 1) sum += __shfl_xor_sync(0xffffffffu, sum, o);
    if ((tid & 31) == 0) red[tid >> 5] = sum;
    __syncthreads();
    if (tid == 0) {
        float t = 0.f;
#pragma unroll
        for (int i = 0; i < 8; i++) t += red[i];
        bcast = t * (1.0f / DD);
    }
    __syncthreads();
    const float mu = bcast;
    float d0 = v0 - mu, d1 = v1 - mu, d2 = v2 - mu;
    float sq = d0 * d0 + d1 * d1 + d2 * d2;
#pragma unroll
    for (int o = 16; o > 0; o >>= 1) sq += __shfl_xor_sync(0xffffffffu, sq, o);
    __syncthreads();
    if ((tid & 31) == 0) red[tid >> 5] = sq;
    __syncthreads();
    if (tid == 0) {
        float t = 0.f;
#pragma unroll
        for (int i = 0; i < 8; i++) t += red[i];
        bcast = rsqrtf(t * (1.0f / DD) + 1e-5f);
    }
    __syncthreads();
    const float inv = bcast;

    float* orow = out + (size_t)blockIdx.x * DD;
    orow[tid]       = d0 * inv * gam[tid]       + bet[tid];
    orow[tid + 256] = d1 * inv * gam[tid + 256] + bet[tid + 256];
    orow[tid + 512] = d2 * inv * gam[tid + 512] + bet[tid + 512];
}

// ================= scan kernels =================================================
__global__ __launch_bounds__(256) void scan_chunk_kernel(
    const float* __restrict__ u, const float* __restrict__ dlogit,
    float* __restrict__ Sout)
{
    const int d = blockIdx.x * 256 + threadIdx.x;
    const int c = blockIdx.y;
    const float decay = sigmoidf_(dlogit[d]);
    const float* p = u + ((size_t)c * CLEN) * DD + d;
    float s = 0.0f;
#pragma unroll 8
    for (int t = 0; t < CLEN; t++) s = fmaf(decay, s, p[(size_t)t * DD]);
    Sout[c * DD + d] = s;
}

__global__ __launch_bounds__(768) void scan_carry_kernel(
    const float* __restrict__ Sin, const float* __restrict__ dlogit,
    float* __restrict__ carry)
{
    const int d = threadIdx.x;
    const float decay = sigmoidf_(dlogit[d]);
    float A = decay;
#pragma unroll
    for (int i = 0; i < 7; i++) A = A * A;   // decay^128
    float c = 0.0f;
    for (int k = 0; k < NCHUNK; k++) {
        carry[k * DD + d] = c;
        c = fmaf(A, c, Sin[k * DD + d]);
    }
}

__global__ __launch_bounds__(256) void scan_apply_split_kernel(
    const float* __restrict__ u, const float* __restrict__ gate,
    const float* __restrict__ dlogit, const float* __restrict__ carry,
    __nv_bfloat16* __restrict__ out)
{
    const int d = blockIdx.x * 256 + threadIdx.x;
    const int c = blockIdx.y;
    const float decay = sigmoidf_(dlogit[d]);
    const size_t base = ((size_t)c * CLEN) * DD + d;
    float s = carry[c * DD + d];
#pragma unroll 4
    for (int t = 0; t < CLEN; t++) {
        const size_t idx = base + (size_t)t * DD;
        s = fmaf(decay, s, u[idx]);
        float v = s * gate[idx];
        __nv_bfloat16 hi, lo;
        split_bf16(v, hi, lo);
        __nv_bfloat16* orow = out + (size_t)(c * CLEN + t) * (2 * DD);
        orow[d]      = hi;
        orow[DD + d] = lo;
    }
}

// ================= host =========================================================
extern "C" void kernel_launch(void* const* d_in, const int* in_sizes, int n_in,
                              void* d_out, int out_size)
{
    const float* node    = (const float*)d_in[0];
    const float* W_proj  = (const float*)d_in[1];
    const float* b_proj  = (const float*)d_in[2];
    const float* ln_s_g  = (const float*)d_in[3];
    const float* ln_s_b  = (const float*)d_in[4];
    const float* W_in    = (const float*)d_in[5];
    const float* b_in    = (const float*)d_in[6];
    const float* W_gate  = (const float*)d_in[7];
    const float* b_gate  = (const float*)d_in[8];
    const float* W_out   = (const float*)d_in[9];
    const float* b_out   = (const float*)d_in[10];
    const float* dlogit  = (const float*)d_in[11];
    const float* ln_f_g  = (const float*)d_in[12];
    const float* ln_f_b  = (const float*)d_in[13];
    const float* W_ff1   = (const float*)d_in[14];
    const float* b_ff1   = (const float*)d_in[15];
    const float* W_ff2   = (const float*)d_in[16];
    const float* b_ff2   = (const float*)d_in[17];
    const float* ln_o_g  = (const float*)d_in[18];
    const float* ln_o_b  = (const float*)d_in[19];

    float *x, *u, *gate, *S, *carry;
    __nv_bfloat16 *a_node, *a_h, *a_s;
    __nv_bfloat16 *w_proj, *w_in, *w_gt, *w_ot;
    __half *a_hf, *a_t, *w_f1, *w_f2;
    cudaGetSymbolAddress((void**)&x,     g_x);
    cudaGetSymbolAddress((void**)&u,     g_u);
    cudaGetSymbolAddress((void**)&gate,  g_gate);
    cudaGetSymbolAddress((void**)&S,     g_S);
    cudaGetSymbolAddress((void**)&carry, g_carry);
    cudaGetSymbolAddress((void**)&a_node, ab_node);
    cudaGetSymbolAddress((void**)&a_h,    ab_h);
    cudaGetSymbolAddress((void**)&a_s,    ab_s);
    cudaGetSymbolAddress((void**)&a_hf,   ah_hf);
    cudaGetSymbolAddress((void**)&a_t,    ah_t);
    cudaGetSymbolAddress((void**)&w_proj, wb_proj);
    cudaGetSymbolAddress((void**)&w_in,   wb_in);
    cudaGetSymbolAddress((void**)&w_gt,   wb_gate);
    cudaGetSymbolAddress((void**)&w_ot,   wb_out);
    cudaGetSymbolAddress((void**)&w_f1,   wh_ff1);
    cudaGetSymbolAddress((void**)&w_f2,   wh_ff2);

    cudaFuncSetAttribute(tc_gemm<0, false>, cudaFuncAttributeMaxDynamicSharedMemorySize, GEMM_SMEM_BYTES);
    cudaFuncSetAttribute(tc_gemm<1, false>, cudaFuncAttributeMaxDynamicSharedMemorySize, GEMM_SMEM_BYTES);
    cudaFuncSetAttribute(tc_gemm<0, true >, cudaFuncAttributeMaxDynamicSharedMemorySize, GEMM_SMEM_BYTES);
    cudaFuncSetAttribute(tc_gemm2<2, false, true >, cudaFuncAttributeMaxDynamicSharedMemorySize, GEMM2_SMEM_BYTES);
    cudaFuncSetAttribute(tc_gemm2<0, true,  false>, cudaFuncAttributeMaxDynamicSharedMemorySize, GEMM2_SMEM_BYTES);

    const dim3 blk(256);
    const dim3 gScan(DD / 256, NCHUNK);
    const dim3 gG6 (DD / 128, LSEQ / 128);   // N=768
    const dim3 gG12(D2 / 128, LSEQ / 128);   // N=1536

    // ---- launch 0: ALL prep (weights + node) ----
    prep_all<<<dim3(512, 12, 5 * NL + 2), blk>>>(
        node, W_proj, W_in, W_gate, W_out, W_ff1, W_ff2,
        a_node, w_proj, w_in, w_gt, w_ot, w_f1, w_f2);

    // ---- launch 1: x = node @ W_proj + b_proj ----
    tc_gemm<0, false><<<gG6, blk, GEMM_SMEM_BYTES>>>(
        a_node, w_proj, b_proj, x, DIN, DD);

    for (int l = 0; l < NL; l++) {
        const size_t vo = (size_t)l * DD;
        const size_t v1 = (size_t)l * D2;
        const __nv_bfloat16* wi = w_in + (size_t)l * DD * 2 * DD;
        const __nv_bfloat16* wg = w_gt + (size_t)l * DD * 2 * DD;
        const __nv_bfloat16* wo = w_ot + (size_t)l * DD * 2 * DD;
        const __half* w1 = w_f1 + (size_t)l * D2 * DD;
        const __half* w2 = w_f2 + (size_t)l * DD * D2;

        ln_split_kernel<<<LSEQ, blk>>>(x, ln_s_g + vo, ln_s_b + vo, a_h);
        tc_gemm<0, false><<<gG6, blk, GEMM_SMEM_BYTES>>>(
            a_h, wi, b_in + vo, u, DD, DD);
        tc_gemm<1, false><<<gG6, blk, GEMM_SMEM_BYTES>>>(
            a_h, wg, b_gate + vo, gate, DD, DD);
        scan_chunk_kernel<<<gScan, blk>>>(u, dlogit + vo, S);
        scan_carry_kernel<<<1, DD>>>(S, dlogit + vo, carry);
        scan_apply_split_kernel<<<gScan, blk>>>(u, gate, dlogit + vo, carry, a_s);
        tc_gemm<0, true><<<gG6, blk, GEMM_SMEM_BYTES>>>(
            a_s, wo, b_out + vo, x, DD, DD);
        ln_split_f16_kernel<<<LSEQ, blk>>>(x, ln_f_g + vo, ln_f_b + vo, a_hf);
        tc_gemm2<2, false, true><<<gG12, blk, GEMM2_SMEM_BYTES>>>(
            a_hf, w1, b_ff1 + v1, nullptr, a_t, DD, D2);
        tc_gemm2<0, true, false><<<gG6, blk, GEMM2_SMEM_BYTES>>>(
            a_t, w2, b_ff2 + vo, x, nullptr, D2, DD);
    }

    ln_final_kernel<<<LSEQ, blk>>>(x, ln_o_g, ln_o_b, (float*)d_out);
}

// round 8
// speedup vs baseline: 2.7836x; 1.2418x over previous
#include <cuda_runtime.h>
#include <cuda_bf16.h>
#include <cuda_fp16.h>
#include <math.h>

#define LSEQ 16384
#define DIN  256
#define DD   768
#define D2   1536
#define NL   8
#define NCHUNK 128
#define CLEN   128

// ---------------- fp32 scratch ----------------
__device__ float g_x[(size_t)LSEQ * DD];
__device__ float g_u[(size_t)LSEQ * DD];
__device__ float g_gate[(size_t)LSEQ * DD];
__device__ float g_S[NCHUNK * DD];
__device__ float g_carry[NCHUNK * DD];

// ---- bf16 split activations: row layout [hi(K) | lo(K)], stride 2K ----
__device__ __nv_bfloat16 ab_node[(size_t)LSEQ * 2 * DIN];
__device__ __nv_bfloat16 ab_h[(size_t)LSEQ * 2 * DD];
__device__ __nv_bfloat16 ab_s[(size_t)LSEQ * 2 * DD];
// ---- fp16 split activations for FF branch ----
__device__ __half ah_hf[(size_t)LSEQ * 2 * DD];
__device__ __half ah_t [(size_t)LSEQ * 2 * D2];

// ---- bf16 split weights: [N rows, 2K] [hi|lo] ----
__device__ __nv_bfloat16 wb_proj[(size_t)DD * 2 * DIN];
__device__ __nv_bfloat16 wb_in  [(size_t)NL * DD * 2 * DD];
__device__ __nv_bfloat16 wb_gate[(size_t)NL * DD * 2 * DD];
__device__ __nv_bfloat16 wb_out [(size_t)NL * DD * 2 * DD];
// ---- fp16 single-plane weights for FF branch: [N rows, K] ----
__device__ __half wh_ff1[(size_t)NL * D2 * DD];
__device__ __half wh_ff2[(size_t)NL * DD * D2];

// ================= helpers =================
__device__ __forceinline__ float sigmoidf_(float z) {
    return 1.0f / (1.0f + __expf(-z));
}

__device__ __forceinline__ unsigned smem_u32(const void* p) {
    unsigned a;
    asm("{ .reg .u64 t; cvta.to.shared.u64 t, %1; cvt.u32.u64 %0, t; }"
        : "=r"(a) : "l"(p));
    return a;
}

__device__ __forceinline__ void cpasync16(unsigned s, const void* g) {
    asm volatile("cp.async.cg.shared.global [%0], [%1], 16;"
                 :: "r"(s), "l"(g) : "memory");
}
__device__ __forceinline__ void cp_commit() {
    asm volatile("cp.async.commit_group;" ::: "memory");
}
__device__ __forceinline__ void cp_wait1() {
    asm volatile("cp.async.wait_group 1;" ::: "memory");
}
__device__ __forceinline__ void cp_wait0() {
    asm volatile("cp.async.wait_group 0;" ::: "memory");
}

__device__ __forceinline__ void ldsm4(unsigned* r, unsigned addr) {
    asm volatile("ldmatrix.sync.aligned.m8n8.x4.shared.b16 {%0,%1,%2,%3}, [%4];"
                 : "=r"(r[0]), "=r"(r[1]), "=r"(r[2]), "=r"(r[3]) : "r"(addr));
}

__device__ __forceinline__ void mma16816(float* d, const unsigned* a,
                                         unsigned b0, unsigned b1) {
    asm volatile(
        "mma.sync.aligned.m16n8k16.row.col.f32.bf16.bf16.f32 "
        "{%0,%1,%2,%3}, {%4,%5,%6,%7}, {%8,%9}, {%0,%1,%2,%3};"
        : "+f"(d[0]), "+f"(d[1]), "+f"(d[2]), "+f"(d[3])
        : "r"(a[0]), "r"(a[1]), "r"(a[2]), "r"(a[3]), "r"(b0), "r"(b1));
}

__device__ __forceinline__ void mma16816h(float* d, const unsigned* a,
                                          unsigned b0, unsigned b1) {
    asm volatile(
        "mma.sync.aligned.m16n8k16.row.col.f32.f16.f16.f32 "
        "{%0,%1,%2,%3}, {%4,%5,%6,%7}, {%8,%9}, {%0,%1,%2,%3};"
        : "+f"(d[0]), "+f"(d[1]), "+f"(d[2]), "+f"(d[3])
        : "r"(a[0]), "r"(a[1]), "r"(a[2]), "r"(a[3]), "r"(b0), "r"(b1));
}

__device__ __forceinline__ void split_bf16(float v, __nv_bfloat16& hi, __nv_bfloat16& lo) {
    hi = __float2bfloat16(v);
    lo = __float2bfloat16(v - __bfloat162float(hi));
}
__device__ __forceinline__ void split_fp16(float v, __half& hi, __half& lo) {
    hi = __float2half_rn(v);
    lo = __float2half_rn(v - __half2float(hi));
}

// ================= 3-pass bf16 GEMM, tile 64x128, 2 CTAs/SM =================
// C = epilogue(Ahi·Bhi + Alo·Bhi + Ahi·Blo + bias)
// 256 thr, 8 warps 2Mx4N (warp 32x32). Stage 48KB x 2 stages = 96KB.
#define GEMM_SMEM_BYTES (2 * 49152)

template<int ACT, bool RESID>
__global__ __launch_bounds__(256, 2) void tc_gemm(
    const __nv_bfloat16* __restrict__ A, const __nv_bfloat16* __restrict__ B,
    const float* __restrict__ bias, float* __restrict__ Cf, int K, int N)
{
    extern __shared__ __align__(1024) char smem[];
    const unsigned sbase = smem_u32(smem);
    const int tid  = threadIdx.x;
    const int wid  = tid >> 5;
    const int lane = tid & 31;
    const int K2 = 2 * K;

    const int row0 = blockIdx.y * 64;
    const int col0 = blockIdx.x * 128;

    const int m0 = (wid & 1) * 32;
    const int n0 = (wid >> 1) * 32;

    float acc[2][4][4];
#pragma unroll
    for (int i = 0; i < 2; i++)
#pragma unroll
        for (int j = 0; j < 4; j++)
#pragma unroll
            for (int q = 0; q < 4; q++) acc[i][j][q] = 0.0f;

    const int arow = tid >> 2;        // 0..63
    const int ac0  = (tid & 3) * 2;   // 2 chunks per thread
    const int brow = tid >> 1;        // 0..127
    const int bc0  = (tid & 1) * 4;   // 4 chunks per thread
    const __nv_bfloat16* agp = A + (size_t)(row0 + arow) * K2;
    const __nv_bfloat16* bgp = B + (size_t)(col0 + brow) * K2;

    const int NC = K / 64;

#define ISSUE_TILE(ct, s) do {                                              \
        const unsigned sb_ = sbase + (unsigned)(s) * 49152u;                \
        const int kb_ = (ct) * 64;                                          \
        _Pragma("unroll")                                                   \
        for (int i_ = 0; i_ < 2; i_++) {                                    \
            const int c_ = ac0 + i_;                                        \
            const unsigned off_ = (unsigned)(arow * 128 + ((c_ ^ (arow & 7)) << 4)); \
            cpasync16(sb_ + off_,         agp + kb_ + c_ * 8);              \
            cpasync16(sb_ + 8192u + off_, agp + K + kb_ + c_ * 8);          \
        }                                                                   \
        _Pragma("unroll")                                                   \
        for (int i_ = 0; i_ < 4; i_++) {                                    \
            const int c_ = bc0 + i_;                                        \
            const unsigned off_ = (unsigned)(brow * 128 + ((c_ ^ (brow & 7)) << 4)); \
            cpasync16(sb_ + 16384u + off_, bgp + kb_ + c_ * 8);             \
            cpasync16(sb_ + 32768u + off_, bgp + K + kb_ + c_ * 8);         \
        }                                                                   \
    } while (0)

    ISSUE_TILE(0, 0);
    cp_commit();
    if (NC > 1) { ISSUE_TILE(1, 1); }
    cp_commit();

    for (int c = 0; c < NC; c++) {
        if (c + 1 < NC) cp_wait1(); else cp_wait0();
        __syncthreads();

        const unsigned sAhi = sbase + (unsigned)(c & 1) * 49152u;
        const unsigned sAlo = sAhi + 8192u;
        const unsigned sBhi = sAhi + 16384u;
        const unsigned sBlo = sAhi + 32768u;

#pragma unroll
        for (int kk4 = 0; kk4 < 4; kk4++) {
            const int cb = kk4 * 2;
            unsigned ahi[2][4], alo[2][4], bfr[2][4];
            unsigned boff[2];
#pragma unroll
            for (int mt = 0; mt < 2; mt++) {
                const int r = m0 + mt * 16 + (lane & 15);
                const int ch = cb + (lane >> 4);
                const unsigned off = (unsigned)(r * 128 + ((ch ^ (r & 7)) << 4));
                ldsm4(ahi[mt], sAhi + off);
                ldsm4(alo[mt], sAlo + off);
            }
#pragma unroll
            for (int jp = 0; jp < 2; jp++) {
                const int rn = n0 + jp * 16 + ((lane >> 4) << 3) + (lane & 7);
                const int ch = cb + ((lane >> 3) & 1);
                boff[jp] = (unsigned)(rn * 128 + ((ch ^ (rn & 7)) << 4));
                ldsm4(bfr[jp], sBhi + boff[jp]);
            }
#pragma unroll
            for (int mt = 0; mt < 2; mt++)
#pragma unroll
                for (int nt = 0; nt < 4; nt++) {
                    mma16816(acc[mt][nt], ahi[mt],
                             bfr[nt >> 1][(nt & 1) * 2],
                             bfr[nt >> 1][(nt & 1) * 2 + 1]);
                    mma16816(acc[mt][nt], alo[mt],
                             bfr[nt >> 1][(nt & 1) * 2],
                             bfr[nt >> 1][(nt & 1) * 2 + 1]);
                }
#pragma unroll
            for (int jp = 0; jp < 2; jp++)
                ldsm4(bfr[jp], sBlo + boff[jp]);
#pragma unroll
            for (int mt = 0; mt < 2; mt++)
#pragma unroll
                for (int nt = 0; nt < 4; nt++)
                    mma16816(acc[mt][nt], ahi[mt],
                             bfr[nt >> 1][(nt & 1) * 2],
                             bfr[nt >> 1][(nt & 1) * 2 + 1]);
        }
        __syncthreads();   // all warps done with buffer (c&1)
        if (c + 2 < NC) {
            ISSUE_TILE(c + 2, c & 1);
            cp_commit();
        }
    }
#undef ISSUE_TILE

    const int g  = lane >> 2;
    const int t4 = lane & 3;
#pragma unroll
    for (int nt = 0; nt < 4; nt++) {
        const int col = col0 + n0 + nt * 8 + 2 * t4;
        const float b0 = bias[col];
        const float b1 = bias[col + 1];
#pragma unroll
        for (int mt = 0; mt < 2; mt++) {
            const int rtop = row0 + m0 + mt * 16 + g;
#pragma unroll
            for (int half = 0; half < 2; half++) {
                const int r = rtop + half * 8;
                float v0 = acc[mt][nt][half * 2 + 0] + b0;
                float v1 = acc[mt][nt][half * 2 + 1] + b1;
                if (ACT == 1) { v0 = sigmoidf_(v0); v1 = sigmoidf_(v1); }
                float* orow = Cf + (size_t)r * N;
                if (RESID) {
                    float2 old = *(float2*)(orow + col);
                    v0 += old.x; v1 += old.y;
                }
                *(float2*)(orow + col) = make_float2(v0, v1);
            }
        }
    }
}

// ================= 2-pass fp16 GEMM, tile 64x128, 2 CTAs/SM =====================
// C = epilogue(Ahi·B + Alo·B + bias).  Stage 32KB x 3 stages = 96KB.
#define GEMM2_SMEM_BYTES (3 * 32768)

template<int ACT, bool RESID, bool SPLIT>
__global__ __launch_bounds__(256, 2) void tc_gemm2(
    const __half* __restrict__ A, const __half* __restrict__ B,
    const float* __restrict__ bias, float* __restrict__ Cf,
    __half* __restrict__ Cs, int K, int N)
{
    extern __shared__ __align__(1024) char smem[];
    const unsigned sbase = smem_u32(smem);
    const int tid  = threadIdx.x;
    const int wid  = tid >> 5;
    const int lane = tid & 31;
    const int K2 = 2 * K;

    const int row0 = blockIdx.y * 64;
    const int col0 = blockIdx.x * 128;

    const int m0 = (wid & 1) * 32;
    const int n0 = (wid >> 1) * 32;

    float acc[2][4][4];
#pragma unroll
    for (int i = 0; i < 2; i++)
#pragma unroll
        for (int j = 0; j < 4; j++)
#pragma unroll
            for (int q = 0; q < 4; q++) acc[i][j][q] = 0.0f;

    const int arow = tid >> 2;
    const int ac0  = (tid & 3) * 2;
    const int brow = tid >> 1;
    const int bc0  = (tid & 1) * 4;
    const __half* agp = A + (size_t)(row0 + arow) * K2;
    const __half* bgp = B + (size_t)(col0 + brow) * K;

    const int NC = K / 64;

#define ISSUE_TILE2(ct, s) do {                                             \
        const unsigned sb_ = sbase + (unsigned)(s) * 32768u;                \
        const int kb_ = (ct) * 64;                                          \
        _Pragma("unroll")                                                   \
        for (int i_ = 0; i_ < 2; i_++) {                                    \
            const int c_ = ac0 + i_;                                        \
            const unsigned off_ = (unsigned)(arow * 128 + ((c_ ^ (arow & 7)) << 4)); \
            cpasync16(sb_ + off_,         agp + kb_ + c_ * 8);              \
            cpasync16(sb_ + 8192u + off_, agp + K + kb_ + c_ * 8);          \
        }                                                                   \
        _Pragma("unroll")                                                   \
        for (int i_ = 0; i_ < 4; i_++) {                                    \
            const int c_ = bc0 + i_;                                        \
            const unsigned off_ = (unsigned)(brow * 128 + ((c_ ^ (brow & 7)) << 4)); \
            cpasync16(sb_ + 16384u + off_, bgp + kb_ + c_ * 8);             \
        }                                                                   \
    } while (0)

    ISSUE_TILE2(0, 0);
    cp_commit();
    if (NC > 1) { ISSUE_TILE2(1, 1); }
    cp_commit();

    int sidx = 0;
    for (int c = 0; c < NC; c++) {
        if (c + 1 < NC) cp_wait1(); else cp_wait0();
        __syncthreads();

        if (c + 2 < NC) {
            int fs = sidx + 2; if (fs >= 3) fs -= 3;
            ISSUE_TILE2(c + 2, fs);
            cp_commit();
        }

        const unsigned sAhi = sbase + (unsigned)sidx * 32768u;
        const unsigned sAlo = sAhi + 8192u;
        const unsigned sB   = sAhi + 16384u;

#pragma unroll
        for (int kk4 = 0; kk4 < 4; kk4++) {
            const int cb = kk4 * 2;
            unsigned ahi[2][4], alo[2][4], bfr[2][4];
#pragma unroll
            for (int mt = 0; mt < 2; mt++) {
                const int r = m0 + mt * 16 + (lane & 15);
                const int ch = cb + (lane >> 4);
                const unsigned off = (unsigned)(r * 128 + ((ch ^ (r & 7)) << 4));
                ldsm4(ahi[mt], sAhi + off);
                ldsm4(alo[mt], sAlo + off);
            }
#pragma unroll
            for (int jp = 0; jp < 2; jp++) {
                const int rn = n0 + jp * 16 + ((lane >> 4) << 3) + (lane & 7);
                const int ch = cb + ((lane >> 3) & 1);
                ldsm4(bfr[jp], sB + (unsigned)(rn * 128 + ((ch ^ (rn & 7)) << 4)));
            }
#pragma unroll
            for (int mt = 0; mt < 2; mt++)
#pragma unroll
                for (int nt = 0; nt < 4; nt++) {
                    mma16816h(acc[mt][nt], ahi[mt],
                              bfr[nt >> 1][(nt & 1) * 2],
                              bfr[nt >> 1][(nt & 1) * 2 + 1]);
                    mma16816h(acc[mt][nt], alo[mt],
                              bfr[nt >> 1][(nt & 1) * 2],
                              bfr[nt >> 1][(nt & 1) * 2 + 1]);
                }
        }
        sidx++; if (sidx >= 3) sidx -= 3;
    }
#undef ISSUE_TILE2

    const int g  = lane >> 2;
    const int t4 = lane & 3;
#pragma unroll
    for (int nt = 0; nt < 4; nt++) {
        const int col = col0 + n0 + nt * 8 + 2 * t4;
        const float b0 = bias[col];
        const float b1 = bias[col + 1];
#pragma unroll
        for (int mt = 0; mt < 2; mt++) {
            const int rtop = row0 + m0 + mt * 16 + g;
#pragma unroll
            for (int half = 0; half < 2; half++) {
                const int r = rtop + half * 8;
                float v0 = acc[mt][nt][half * 2 + 0] + b0;
                float v1 = acc[mt][nt][half * 2 + 1] + b1;
                if (ACT == 2) { v0 = v0 * sigmoidf_(v0); v1 = v1 * sigmoidf_(v1); }
                if (SPLIT) {
                    __half* orow = Cs + (size_t)r * (2 * N);
                    __half h0, l0, h1, l1;
                    split_fp16(v0, h0, l0);
                    split_fp16(v1, h1, l1);
                    *(__half2*)(orow + col)     = __halves2half2(h0, h1);
                    *(__half2*)(orow + N + col) = __halves2half2(l0, l1);
                } else {
                    float* orow = Cf + (size_t)r * N;
                    if (RESID) {
                        float2 old = *(float2*)(orow + col);
                        v0 += old.x; v1 += old.y;
                    }
                    *(float2*)(orow + col) = make_float2(v0, v1);
                }
            }
        }
    }
}

// ========== batched prep: ALL weights + node activations in ONE launch ==========
__global__ __launch_bounds__(256) void prep_all(
    const float* __restrict__ node,
    const float* __restrict__ W_proj, const float* __restrict__ W_in,
    const float* __restrict__ W_gate, const float* __restrict__ W_out,
    const float* __restrict__ W_ff1,  const float* __restrict__ W_ff2,
    __nv_bfloat16* __restrict__ o_node, __nv_bfloat16* __restrict__ o_proj,
    __nv_bfloat16* __restrict__ o_in, __nv_bfloat16* __restrict__ o_gate,
    __nv_bfloat16* __restrict__ o_out,
    __half* __restrict__ o_ff1, __half* __restrict__ o_ff2)
{
    const int z = blockIdx.z;
    const int nidx = blockIdx.x * 32 + (threadIdx.x & 31);
    const int k0 = blockIdx.y * 128 + (threadIdx.x >> 5) * 16;

    if (z == 5 * NL + 1) {
        if (nidx >= LSEQ || k0 >= DIN) return;
        const float* xr = node + (size_t)nidx * DIN;
        __nv_bfloat16* orow = o_node + (size_t)nidx * 2 * DIN;
#pragma unroll
        for (int i = 0; i < 16; i++) {
            __nv_bfloat16 hi, lo;
            split_bf16(xr[k0 + i], hi, lo);
            orow[k0 + i]       = hi;
            orow[DIN + k0 + i] = lo;
        }
        return;
    }

    const float* W; int K, N;
    if (z == 5 * NL) { W = W_proj; K = DIN; N = DD; }
    else {
        const int l = z / 5, t = z - l * 5;
        switch (t) {
            case 0: W = W_in   + (size_t)l * DD * DD; K = DD; N = DD; break;
            case 1: W = W_gate + (size_t)l * DD * DD; K = DD; N = DD; break;
            case 2: W = W_out  + (size_t)l * DD * DD; K = DD; N = DD; break;
            case 3: W = W_ff1  + (size_t)l * DD * D2; K = DD; N = D2; break;
            default:W = W_ff2  + (size_t)l * D2 * DD; K = D2; N = DD; break;
        }
    }
    if (nidx >= N || k0 >= K) return;

    const int t = (z < 5 * NL) ? (z % 5) : -1;
    if (t == 3 || t == 4) {
        const int l = z / 5;
        __half* orow = (t == 3) ? (o_ff1 + (size_t)l * D2 * DD + (size_t)nidx * DD)
                                : (o_ff2 + (size_t)l * DD * D2 + (size_t)nidx * D2);
#pragma unroll
        for (int i = 0; i < 16; i++)
            orow[k0 + i] = __float2half_rn(W[(size_t)(k0 + i) * N + nidx]);
    } else {
        __nv_bfloat16* Bp;
        if (z == 5 * NL) Bp = o_proj;
        else {
            const int l = z / 5;
            Bp = (t == 0) ? o_in + (size_t)l * DD * 2 * DD
               : (t == 1) ? o_gate + (size_t)l * DD * 2 * DD
                          : o_out + (size_t)l * DD * 2 * DD;
        }
        __nv_bfloat16* orow = Bp + (size_t)nidx * 2 * K;
#pragma unroll
        for (int i = 0; i < 16; i++) {
            __nv_bfloat16 hi, lo;
            split_bf16(W[(size_t)(k0 + i) * N + nidx], hi, lo);
            orow[k0 + i]     = hi;
            orow[K + k0 + i] = lo;
        }
    }
}

// ================= LayerNorm -> split bf16 [L, 2*DD] ============================
__global__ __launch_bounds__(256) void ln_split_kernel(
    const float* __restrict__ x, const float* __restrict__ gam,
    const float* __restrict__ bet, __nv_bfloat16* __restrict__ out)
{
    __shared__ float red[8];
    __shared__ float bcast;
    const int tid = threadIdx.x;
    const float* xr = x + (size_t)blockIdx.x * DD;

    float v0 = xr[tid], v1 = xr[tid + 256], v2 = xr[tid + 512];
    float sum = v0 + v1 + v2;
#pragma unroll
    for (int o = 16; o > 0; o >>= 1) sum += __shfl_xor_sync(0xffffffffu, sum, o);
    if ((tid & 31) == 0) red[tid >> 5] = sum;
    __syncthreads();
    if (tid == 0) {
        float t = 0.f;
#pragma unroll
        for (int i = 0; i < 8; i++) t += red[i];
        bcast = t * (1.0f / DD);
    }
    __syncthreads();
    const float mu = bcast;
    float d0 = v0 - mu, d1 = v1 - mu, d2 = v2 - mu;
    float sq = d0 * d0 + d1 * d1 + d2 * d2;
#pragma unroll
    for (int o = 16; o > 0; o >>= 1) sq += __shfl_xor_sync(0xffffffffu, sq, o);
    __syncthreads();
    if ((tid & 31) == 0) red[tid >> 5] = sq;
    __syncthreads();
    if (tid == 0) {
        float t = 0.f;
#pragma unroll
        for (int i = 0; i < 8; i++) t += red[i];
        bcast = rsqrtf(t * (1.0f / DD) + 1e-5f);
    }
    __syncthreads();
    const float inv = bcast;

    __nv_bfloat16* orow = out + (size_t)blockIdx.x * (2 * DD);
#pragma unroll
    for (int q = 0; q < 3; q++) {
        const int j = tid + q * 256;
        const float dv = (q == 0 ? d0 : (q == 1 ? d1 : d2));
        float v = dv * inv * gam[j] + bet[j];
        __nv_bfloat16 hi, lo;
        split_bf16(v, hi, lo);
        orow[j]      = hi;
        orow[DD + j] = lo;
    }
}

// ================= LayerNorm -> split fp16 [L, 2*DD] ============================
__global__ __launch_bounds__(256) void ln_split_f16_kernel(
    const float* __restrict__ x, const float* __restrict__ gam,
    const float* __restrict__ bet, __half* __restrict__ out)
{
    __shared__ float red[8];
    __shared__ float bcast;
    const int tid = threadIdx.x;
    const float* xr = x + (size_t)blockIdx.x * DD;

    float v0 = xr[tid], v1 = xr[tid + 256], v2 = xr[tid + 512];
    float sum = v0 + v1 + v2;
#pragma unroll
    for (int o = 16; o > 0; o >>= 1) sum += __shfl_xor_sync(0xffffffffu, sum, o);
    if ((tid & 31) == 0) red[tid >> 5] = sum;
    __syncthreads();
    if (tid == 0) {
        float t = 0.f;
#pragma unroll
        for (int i = 0; i < 8; i++) t += red[i];
        bcast = t * (1.0f / DD);
    }
    __syncthreads();
    const float mu = bcast;
    float d0 = v0 - mu, d1 = v1 - mu, d2 = v2 - mu;
    float sq = d0 * d0 + d1 * d1 + d2 * d2;
#pragma unroll
    for (int o = 16; o > 0; o >>= 1) sq += __shfl_xor_sync(0xffffffffu, sq, o);
    __syncthreads();
    if ((tid & 31) == 0) red[tid >> 5] = sq;
    __syncthreads();
    if (tid == 0) {
        float t = 0.f;
#pragma unroll
        for (int i = 0; i < 8; i++) t += red[i];
        bcast = rsqrtf(t * (1.0f / DD) + 1e-5f);
    }
    __syncthreads();
    const float inv = bcast;

    __half* orow = out + (size_t)blockIdx.x * (2 * DD);
#pragma unroll
    for (int q = 0; q < 3; q++) {
        const int j = tid + q * 256;
        const float dv = (q == 0 ? d0 : (q == 1 ? d1 : d2));
        float v = dv * inv * gam[j] + bet[j];
        __half hi, lo;
        split_fp16(v, hi, lo);
        orow[j]      = hi;
        orow[DD + j] = lo;
    }
}

// ================= final LayerNorm (fp32 out) ===================================
__global__ __launch_bounds__(256) void ln_final_kernel(
    const float* __restrict__ x, const float* __restrict__ gam,
    const float* __restrict__ bet, float* __restrict__ out)
{
    __shared__ float red[8];
    __shared__ float bcast;
    const int tid = threadIdx.x;
    const float* xr = x + (size_t)blockIdx.x * DD;

    float v0 = xr[tid], v1 = xr[tid + 256], v2 = xr[tid + 512];
    float sum = v0 + v1 + v2;
#pragma unroll
    for (int o = 16; o > 0; o >>= 1) sum += __shfl_xor_sync(0xffffffffu, sum, o);
    if ((tid & 31) == 0) red[tid >> 5] = sum;
    __syncthreads();
    if (tid == 0) {
        float t = 0.f;
#pragma unroll
        for (int i = 0; i < 8; i++) t += red[i];
        bcast = t * (1.0f / DD);
    }
    __syncthreads();
    const float mu = bcast;
    float d0 = v0 - mu, d1 = v1 - mu, d2 = v2 - mu;
    float sq = d0 * d0 + d1 * d1 + d2 * d2;
#pragma unroll
    for (int o = 16; o > 0; o >>= 1) sq += __shfl_xor_sync(0xffffffffu, sq, o);
    __syncthreads();
    if ((tid & 31) == 0) red[tid >> 5] = sq;
    __syncthreads();
    if (tid == 0) {
        float t = 0.f;
#pragma unroll
        for (int i = 0; i < 8; i++) t += red[i];
        bcast = rsqrtf(t * (1.0f / DD) + 1e-5f);
    }
    __syncthreads();
    const float inv = bcast;

    float* orow = out + (size_t)blockIdx.x * DD;
    orow[tid]       = d0 * inv * gam[tid]       + bet[tid];
    orow[tid + 256] = d1 * inv * gam[tid + 256] + bet[tid + 256];
    orow[tid + 512] = d2 * inv * gam[tid + 512] + bet[tid + 512];
}

// ================= scan kernels =================================================
__global__ __launch_bounds__(256) void scan_chunk_kernel(
    const float* __restrict__ u, const float* __restrict__ dlogit,
    float* __restrict__ Sout)
{
    const int d = blockIdx.x * 256 + threadIdx.x;
    const int c = blockIdx.y;
    const float decay = sigmoidf_(dlogit[d]);
    const float* p = u + ((size_t)c * CLEN) * DD + d;
    float s = 0.0f;
#pragma unroll 8
    for (int t = 0; t < CLEN; t++) s = fmaf(decay, s, p[(size_t)t * DD]);
    Sout[c * DD + d] = s;
}

__global__ __launch_bounds__(768) void scan_carry_kernel(
    const float* __restrict__ Sin, const float* __restrict__ dlogit,
    float* __restrict__ carry)
{
    const int d = threadIdx.x;
    const float decay = sigmoidf_(dlogit[d]);
    float A = decay;
#pragma unroll
    for (int i = 0; i < 7; i++) A = A * A;   // decay^128
    float c = 0.0f;
    for (int k = 0; k < NCHUNK; k++) {
        carry[k * DD + d] = c;
        c = fmaf(A, c, Sin[k * DD + d]);
    }
}

__global__ __launch_bounds__(256) void scan_apply_split_kernel(
    const float* __restrict__ u, const float* __restrict__ gate,
    const float* __restrict__ dlogit, const float* __restrict__ carry,
    __nv_bfloat16* __restrict__ out)
{
    const int d = blockIdx.x * 256 + threadIdx.x;
    const int c = blockIdx.y;
    const float decay = sigmoidf_(dlogit[d]);
    const size_t base = ((size_t)c * CLEN) * DD + d;
    float s = carry[c * DD + d];
#pragma unroll 4
    for (int t = 0; t < CLEN; t++) {
        const size_t idx = base + (size_t)t * DD;
        s = fmaf(decay, s, u[idx]);
        float v = s * gate[idx];
        __nv_bfloat16 hi, lo;
        split_bf16(v, hi, lo);
        __nv_bfloat16* orow = out + (size_t)(c * CLEN + t) * (2 * DD);
        orow[d]      = hi;
        orow[DD + d] = lo;
    }
}

// ================= host =========================================================
extern "C" void kernel_launch(void* const* d_in, const int* in_sizes, int n_in,
                              void* d_out, int out_size)
{
    const float* node    = (const float*)d_in[0];
    const float* W_proj  = (const float*)d_in[1];
    const float* b_proj  = (const float*)d_in[2];
    const float* ln_s_g  = (const float*)d_in[3];
    const float* ln_s_b  = (const float*)d_in[4];
    const float* W_in    = (const float*)d_in[5];
    const float* b_in    = (const float*)d_in[6];
    const float* W_gate  = (const float*)d_in[7];
    const float* b_gate  = (const float*)d_in[8];
    const float* W_out   = (const float*)d_in[9];
    const float* b_out   = (const float*)d_in[10];
    const float* dlogit  = (const float*)d_in[11];
    const float* ln_f_g  = (const float*)d_in[12];
    const float* ln_f_b  = (const float*)d_in[13];
    const float* W_ff1   = (const float*)d_in[14];
    const float* b_ff1   = (const float*)d_in[15];
    const float* W_ff2   = (const float*)d_in[16];
    const float* b_ff2   = (const float*)d_in[17];
    const float* ln_o_g  = (const float*)d_in[18];
    const float* ln_o_b  = (const float*)d_in[19];

    float *x, *u, *gate, *S, *carry;
    __nv_bfloat16 *a_node, *a_h, *a_s;
    __nv_bfloat16 *w_proj, *w_in, *w_gt, *w_ot;
    __half *a_hf, *a_t, *w_f1, *w_f2;
    cudaGetSymbolAddress((void**)&x,     g_x);
    cudaGetSymbolAddress((void**)&u,     g_u);
    cudaGetSymbolAddress((void**)&gate,  g_gate);
    cudaGetSymbolAddress((void**)&S,     g_S);
    cudaGetSymbolAddress((void**)&carry, g_carry);
    cudaGetSymbolAddress((void**)&a_node, ab_node);
    cudaGetSymbolAddress((void**)&a_h,    ab_h);
    cudaGetSymbolAddress((void**)&a_s,    ab_s);
    cudaGetSymbolAddress((void**)&a_hf,   ah_hf);
    cudaGetSymbolAddress((void**)&a_t,    ah_t);
    cudaGetSymbolAddress((void**)&w_proj, wb_proj);
    cudaGetSymbolAddress((void**)&w_in,   wb_in);
    cudaGetSymbolAddress((void**)&w_gt,   wb_gate);
    cudaGetSymbolAddress((void**)&w_ot,   wb_out);
    cudaGetSymbolAddress((void**)&w_f1,   wh_ff1);
    cudaGetSymbolAddress((void**)&w_f2,   wh_ff2);

    cudaFuncSetAttribute(tc_gemm<0, false>, cudaFuncAttributeMaxDynamicSharedMemorySize, GEMM_SMEM_BYTES);
    cudaFuncSetAttribute(tc_gemm<1, false>, cudaFuncAttributeMaxDynamicSharedMemorySize, GEMM_SMEM_BYTES);
    cudaFuncSetAttribute(tc_gemm<0, true >, cudaFuncAttributeMaxDynamicSharedMemorySize, GEMM_SMEM_BYTES);
    cudaFuncSetAttribute(tc_gemm2<2, false, true >, cudaFuncAttributeMaxDynamicSharedMemorySize, GEMM2_SMEM_BYTES);
    cudaFuncSetAttribute(tc_gemm2<0, true,  false>, cudaFuncAttributeMaxDynamicSharedMemorySize, GEMM2_SMEM_BYTES);

    const dim3 blk(256);
    const dim3 gScan(DD / 256, NCHUNK);
    const dim3 gG6 (DD / 128, LSEQ / 64);    // N=768  tiles
    const dim3 gG12(D2 / 128, LSEQ / 64);    // N=1536 tiles

    // ---- launch 0: ALL prep (weights + node) ----
    prep_all<<<dim3(512, 12, 5 * NL + 2), blk>>>(
        node, W_proj, W_in, W_gate, W_out, W_ff1, W_ff2,
        a_node, w_proj, w_in, w_gt, w_ot, w_f1, w_f2);

    // ---- launch 1: x = node @ W_proj + b_proj ----
    tc_gemm<0, false><<<gG6, blk, GEMM_SMEM_BYTES>>>(
        a_node, w_proj, b_proj, x, DIN, DD);

    for (int l = 0; l < NL; l++) {
        const size_t vo = (size_t)l * DD;
        const size_t v1 = (size_t)l * D2;
        const __nv_bfloat16* wi = w_in + (size_t)l * DD * 2 * DD;
        const __nv_bfloat16* wg = w_gt + (size_t)l * DD * 2 * DD;
        const __nv_bfloat16* wo = w_ot + (size_t)l * DD * 2 * DD;
        const __half* w1 = w_f1 + (size_t)l * D2 * DD;
        const __half* w2 = w_f2 + (size_t)l * DD * D2;

        ln_split_kernel<<<LSEQ, blk>>>(x, ln_s_g + vo, ln_s_b + vo, a_h);
        tc_gemm<0, false><<<gG6, blk, GEMM_SMEM_BYTES>>>(
            a_h, wi, b_in + vo, u, DD, DD);
        tc_gemm<1, false><<<gG6, blk, GEMM_SMEM_BYTES>>>(
            a_h, wg, b_gate + vo, gate, DD, DD);
        scan_chunk_kernel<<<gScan, blk>>>(u, dlogit + vo, S);
        scan_carry_kernel<<<1, DD>>>(S, dlogit + vo, carry);
        scan_apply_split_kernel<<<gScan, blk>>>(u, gate, dlogit + vo, carry, a_s);
        tc_gemm<0, true><<<gG6, blk, GEMM_SMEM_BYTES>>>(
            a_s, wo, b_out + vo, x, DD, DD);
        ln_split_f16_kernel<<<LSEQ, blk>>>(x, ln_f_g + vo, ln_f_b + vo, a_hf);
        tc_gemm2<2, false, true><<<gG12, blk, GEMM2_SMEM_BYTES>>>(
            a_hf, w1, b_ff1 + v1, nullptr, a_t, DD, D2);
        tc_gemm2<0, true, false><<<gG6, blk, GEMM2_SMEM_BYTES>>>(
            a_t, w2, b_ff2 + vo, x, nullptr, D2, DD);
    }

    ln_final_kernel<<<LSEQ, blk>>>(x, ln_o_g, ln_o_b, (float*)d_out);
}

// round 9
// speedup vs baseline: 2.8250x; 1.0149x over previous
#include <cuda_runtime.h>
#include <cuda_bf16.h>
#include <cuda_fp16.h>
#include <math.h>

#define LSEQ 16384
#define DIN  256
#define DD   768
#define D2   1536
#define NL   8
#define NCHUNK 128
#define CLEN   128

// ---------------- fp32 scratch ----------------
__device__ float g_x[(size_t)LSEQ * DD];
__device__ float g_u[(size_t)LSEQ * DD];
__device__ float g_gate[(size_t)LSEQ * DD];
__device__ float g_S[NCHUNK * DD];
__device__ float g_carry[NCHUNK * DD];

// ---- bf16 split activations [hi|lo] stride 2K ----
__device__ __nv_bfloat16 ab_node[(size_t)LSEQ * 2 * DIN];
__device__ __nv_bfloat16 ab_h[(size_t)LSEQ * 2 * DD];
__device__ __nv_bfloat16 ab_s[(size_t)LSEQ * 2 * DD];
// ---- fp16 split activations ----
__device__ __half ah_h2[(size_t)LSEQ * 2 * DD];   // ln_s output (for gate GEMM)
__device__ __half ah_hf[(size_t)LSEQ * 2 * DD];   // ln_f output (for ff1)
__device__ __half ah_t [(size_t)LSEQ * 2 * D2];   // silu(ff1) output (for ff2)

// ---- bf16 split weights [N rows, 2K] [hi|lo] ----
__device__ __nv_bfloat16 wb_proj[(size_t)DD * 2 * DIN];
__device__ __nv_bfloat16 wb_in  [(size_t)NL * DD * 2 * DD];
__device__ __nv_bfloat16 wb_out [(size_t)NL * DD * 2 * DD];
// ---- fp16 single-plane weights [N rows, K] ----
__device__ __half wh_gate[(size_t)NL * DD * DD];
__device__ __half wh_ff1 [(size_t)NL * D2 * DD];
__device__ __half wh_ff2 [(size_t)NL * DD * D2];

// ================= helpers =================
__device__ __forceinline__ float sigmoidf_(float z) {
    return 1.0f / (1.0f + __expf(-z));
}

__device__ __forceinline__ unsigned smem_u32(const void* p) {
    unsigned a;
    asm("{ .reg .u64 t; cvta.to.shared.u64 t, %1; cvt.u32.u64 %0, t; }"
        : "=r"(a) : "l"(p));
    return a;
}

__device__ __forceinline__ void cpasync16(unsigned s, const void* g) {
    asm volatile("cp.async.cg.shared.global [%0], [%1], 16;"
                 :: "r"(s), "l"(g) : "memory");
}
__device__ __forceinline__ void cp_commit() {
    asm volatile("cp.async.commit_group;" ::: "memory");
}
__device__ __forceinline__ void cp_wait1() {
    asm volatile("cp.async.wait_group 1;" ::: "memory");
}
__device__ __forceinline__ void cp_wait0() {
    asm volatile("cp.async.wait_group 0;" ::: "memory");
}

__device__ __forceinline__ void ldsm4(unsigned* r, unsigned addr) {
    asm volatile("ldmatrix.sync.aligned.m8n8.x4.shared.b16 {%0,%1,%2,%3}, [%4];"
                 : "=r"(r[0]), "=r"(r[1]), "=r"(r[2]), "=r"(r[3]) : "r"(addr));
}

__device__ __forceinline__ void mma16816(float* d, const unsigned* a,
                                         unsigned b0, unsigned b1) {
    asm volatile(
        "mma.sync.aligned.m16n8k16.row.col.f32.bf16.bf16.f32 "
        "{%0,%1,%2,%3}, {%4,%5,%6,%7}, {%8,%9}, {%0,%1,%2,%3};"
        : "+f"(d[0]), "+f"(d[1]), "+f"(d[2]), "+f"(d[3])
        : "r"(a[0]), "r"(a[1]), "r"(a[2]), "r"(a[3]), "r"(b0), "r"(b1));
}

__device__ __forceinline__ void mma16816h(float* d, const unsigned* a,
                                          unsigned b0, unsigned b1) {
    asm volatile(
        "mma.sync.aligned.m16n8k16.row.col.f32.f16.f16.f32 "
        "{%0,%1,%2,%3}, {%4,%5,%6,%7}, {%8,%9}, {%0,%1,%2,%3};"
        : "+f"(d[0]), "+f"(d[1]), "+f"(d[2]), "+f"(d[3])
        : "r"(a[0]), "r"(a[1]), "r"(a[2]), "r"(a[3]), "r"(b0), "r"(b1));
}

__device__ __forceinline__ void split_bf16(float v, __nv_bfloat16& hi, __nv_bfloat16& lo) {
    hi = __float2bfloat16(v);
    lo = __float2bfloat16(v - __bfloat162float(hi));
}
__device__ __forceinline__ void split_fp16(float v, __half& hi, __half& lo) {
    hi = __float2half_rn(v);
    lo = __float2half_rn(v - __half2float(hi));
}

// ================= 3-pass bf16 GEMM, tile 64x128, 2 CTAs/SM =================
// C = epilogue(Ahi·Bhi + Alo·Bhi + Ahi·Blo + bias)
// 256 thr, 8 warps 2Mx4N (warp 32x32). Stage 48KB x 2 stages = 96KB.
#define GEMM_SMEM_BYTES (2 * 49152)

template<int ACT, bool RESID>
__global__ __launch_bounds__(256, 2) void tc_gemm(
    const __nv_bfloat16* __restrict__ A, const __nv_bfloat16* __restrict__ B,
    const float* __restrict__ bias, float* __restrict__ Cf, int K, int N)
{
    extern __shared__ __align__(1024) char smem[];
    const unsigned sbase = smem_u32(smem);
    const int tid  = threadIdx.x;
    const int wid  = tid >> 5;
    const int lane = tid & 31;
    const int K2 = 2 * K;

    const int row0 = blockIdx.y * 64;
    const int col0 = blockIdx.x * 128;

    const int m0 = (wid & 1) * 32;
    const int n0 = (wid >> 1) * 32;

    float acc[2][4][4];
#pragma unroll
    for (int i = 0; i < 2; i++)
#pragma unroll
        for (int j = 0; j < 4; j++)
#pragma unroll
            for (int q = 0; q < 4; q++) acc[i][j][q] = 0.0f;

    const int arow = tid >> 2;
    const int ac0  = (tid & 3) * 2;
    const int brow = tid >> 1;
    const int bc0  = (tid & 1) * 4;
    const __nv_bfloat16* agp = A + (size_t)(row0 + arow) * K2;
    const __nv_bfloat16* bgp = B + (size_t)(col0 + brow) * K2;

    const int NC = K / 64;

#define ISSUE_TILE(ct, s) do {                                              \
        const unsigned sb_ = sbase + (unsigned)(s) * 49152u;                \
        const int kb_ = (ct) * 64;                                          \
        _Pragma("unroll")                                                   \
        for (int i_ = 0; i_ < 2; i_++) {                                    \
            const int c_ = ac0 + i_;                                        \
            const unsigned off_ = (unsigned)(arow * 128 + ((c_ ^ (arow & 7)) << 4)); \
            cpasync16(sb_ + off_,         agp + kb_ + c_ * 8);              \
            cpasync16(sb_ + 8192u + off_, agp + K + kb_ + c_ * 8);          \
        }                                                                   \
        _Pragma("unroll")                                                   \
        for (int i_ = 0; i_ < 4; i_++) {                                    \
            const int c_ = bc0 + i_;                                        \
            const unsigned off_ = (unsigned)(brow * 128 + ((c_ ^ (brow & 7)) << 4)); \
            cpasync16(sb_ + 16384u + off_, bgp + kb_ + c_ * 8);             \
            cpasync16(sb_ + 32768u + off_, bgp + K + kb_ + c_ * 8);         \
        }                                                                   \
    } while (0)

    ISSUE_TILE(0, 0);
    cp_commit();
    if (NC > 1) { ISSUE_TILE(1, 1); }
    cp_commit();

    for (int c = 0; c < NC; c++) {
        if (c + 1 < NC) cp_wait1(); else cp_wait0();
        __syncthreads();

        const unsigned sAhi = sbase + (unsigned)(c & 1) * 49152u;
        const unsigned sAlo = sAhi + 8192u;
        const unsigned sBhi = sAhi + 16384u;
        const unsigned sBlo = sAhi + 32768u;

#pragma unroll
        for (int kk4 = 0; kk4 < 4; kk4++) {
            const int cb = kk4 * 2;
            unsigned ahi[2][4], alo[2][4], bfr[2][4];
            unsigned boff[2];
#pragma unroll
            for (int mt = 0; mt < 2; mt++) {
                const int r = m0 + mt * 16 + (lane & 15);
                const int ch = cb + (lane >> 4);
                const unsigned off = (unsigned)(r * 128 + ((ch ^ (r & 7)) << 4));
                ldsm4(ahi[mt], sAhi + off);
                ldsm4(alo[mt], sAlo + off);
            }
#pragma unroll
            for (int jp = 0; jp < 2; jp++) {
                const int rn = n0 + jp * 16 + ((lane >> 4) << 3) + (lane & 7);
                const int ch = cb + ((lane >> 3) & 1);
                boff[jp] = (unsigned)(rn * 128 + ((ch ^ (rn & 7)) << 4));
                ldsm4(bfr[jp], sBhi + boff[jp]);
            }
#pragma unroll
            for (int mt = 0; mt < 2; mt++)
#pragma unroll
                for (int nt = 0; nt < 4; nt++) {
                    mma16816(acc[mt][nt], ahi[mt],
                             bfr[nt >> 1][(nt & 1) * 2],
                             bfr[nt >> 1][(nt & 1) * 2 + 1]);
                    mma16816(acc[mt][nt], alo[mt],
                             bfr[nt >> 1][(nt & 1) * 2],
                             bfr[nt >> 1][(nt & 1) * 2 + 1]);
                }
#pragma unroll
            for (int jp = 0; jp < 2; jp++)
                ldsm4(bfr[jp], sBlo + boff[jp]);
#pragma unroll
            for (int mt = 0; mt < 2; mt++)
#pragma unroll
                for (int nt = 0; nt < 4; nt++)
                    mma16816(acc[mt][nt], ahi[mt],
                             bfr[nt >> 1][(nt & 1) * 2],
                             bfr[nt >> 1][(nt & 1) * 2 + 1]);
        }
        __syncthreads();
        if (c + 2 < NC) {
            ISSUE_TILE(c + 2, c & 1);
            cp_commit();
        }
    }
#undef ISSUE_TILE

    const int g  = lane >> 2;
    const int t4 = lane & 3;
#pragma unroll
    for (int nt = 0; nt < 4; nt++) {
        const int col = col0 + n0 + nt * 8 + 2 * t4;
        const float b0 = bias[col];
        const float b1 = bias[col + 1];
#pragma unroll
        for (int mt = 0; mt < 2; mt++) {
            const int rtop = row0 + m0 + mt * 16 + g;
#pragma unroll
            for (int half = 0; half < 2; half++) {
                const int r = rtop + half * 8;
                float v0 = acc[mt][nt][half * 2 + 0] + b0;
                float v1 = acc[mt][nt][half * 2 + 1] + b1;
                if (ACT == 1) { v0 = sigmoidf_(v0); v1 = sigmoidf_(v1); }
                float* orow = Cf + (size_t)r * N;
                if (RESID) {
                    float2 old = *(float2*)(orow + col);
                    v0 += old.x; v1 += old.y;
                }
                *(float2*)(orow + col) = make_float2(v0, v1);
            }
        }
    }
}

// ================= 2-pass fp16 GEMM, tile 128x128, 2 CTAs/SM ====================
// C = epilogue(Ahi·B + Alo·B + bias).  Stage = Ahi16K+Alo16K+B16K = 48KB x 2 = 96KB.
// 8 warps 4Mx2N, warp tile 32x64.
// ACT: 0 none, 1 sigmoid, 2 silu. RESID: Cf += v. SPLIT: fp16 [hi|lo] to Cs.
#define GEMM2_SMEM_BYTES (2 * 49152)

template<int ACT, bool RESID, bool SPLIT>
__global__ __launch_bounds__(256, 2) void tc_gemm2(
    const __half* __restrict__ A, const __half* __restrict__ B,
    const float* __restrict__ bias, float* __restrict__ Cf,
    __half* __restrict__ Cs, int K, int N)
{
    extern __shared__ __align__(1024) char smem[];
    const unsigned sbase = smem_u32(smem);
    const int tid  = threadIdx.x;
    const int wid  = tid >> 5;
    const int lane = tid & 31;
    const int K2 = 2 * K;

    const int row0 = blockIdx.y * 128;
    const int col0 = blockIdx.x * 128;

    const int m0 = (wid & 3) * 32;   // 4 M groups
    const int n0 = (wid >> 2) * 64;  // 2 N groups

    float acc[2][8][4];
#pragma unroll
    for (int i = 0; i < 2; i++)
#pragma unroll
        for (int j = 0; j < 8; j++)
#pragma unroll
            for (int q = 0; q < 4; q++) acc[i][j][q] = 0.0f;

    const int lrow = tid >> 1;        // 0..127
    const int lc0  = (tid & 1) * 4;   // 4 chunks each
    const __half* agp = A + (size_t)(row0 + lrow) * K2;
    const __half* bgp = B + (size_t)(col0 + lrow) * K;

    const int NC = K / 64;

#define ISSUE_TILE2(ct, s) do {                                             \
        const unsigned sb_ = sbase + (unsigned)(s) * 49152u;                \
        const int kb_ = (ct) * 64;                                          \
        _Pragma("unroll")                                                   \
        for (int i_ = 0; i_ < 4; i_++) {                                    \
            const int c_ = lc0 + i_;                                        \
            const unsigned off_ = (unsigned)(lrow * 128 + ((c_ ^ (lrow & 7)) << 4)); \
            cpasync16(sb_ + off_,          agp + kb_ + c_ * 8);             \
            cpasync16(sb_ + 16384u + off_, agp + K + kb_ + c_ * 8);         \
            cpasync16(sb_ + 32768u + off_, bgp + kb_ + c_ * 8);             \
        }                                                                   \
    } while (0)

    ISSUE_TILE2(0, 0);
    cp_commit();
    if (NC > 1) { ISSUE_TILE2(1, 1); }
    cp_commit();

    for (int c = 0; c < NC; c++) {
        if (c + 1 < NC) cp_wait1(); else cp_wait0();
        __syncthreads();

        const unsigned sAhi = sbase + (unsigned)(c & 1) * 49152u;
        const unsigned sAlo = sAhi + 16384u;
        const unsigned sB   = sAhi + 32768u;

#pragma unroll
        for (int kk4 = 0; kk4 < 4; kk4++) {
            const int cb = kk4 * 2;
            unsigned ahi[2][4], alo[2][4], bfr[4][4];
#pragma unroll
            for (int mt = 0; mt < 2; mt++) {
                const int r = m0 + mt * 16 + (lane & 15);
                const int ch = cb + (lane >> 4);
                const unsigned off = (unsigned)(r * 128 + ((ch ^ (r & 7)) << 4));
                ldsm4(ahi[mt], sAhi + off);
                ldsm4(alo[mt], sAlo + off);
            }
#pragma unroll
            for (int jp = 0; jp < 4; jp++) {
                const int rn = n0 + jp * 16 + ((lane >> 4) << 3) + (lane & 7);
                const int ch = cb + ((lane >> 3) & 1);
                ldsm4(bfr[jp], sB + (unsigned)(rn * 128 + ((ch ^ (rn & 7)) << 4)));
            }
#pragma unroll
            for (int mt = 0; mt < 2; mt++)
#pragma unroll
                for (int nt = 0; nt < 8; nt++) {
                    mma16816h(acc[mt][nt], ahi[mt],
                              bfr[nt >> 1][(nt & 1) * 2],
                              bfr[nt >> 1][(nt & 1) * 2 + 1]);
                    mma16816h(acc[mt][nt], alo[mt],
                              bfr[nt >> 1][(nt & 1) * 2],
                              bfr[nt >> 1][(nt & 1) * 2 + 1]);
                }
        }
        __syncthreads();
        if (c + 2 < NC) {
            ISSUE_TILE2(c + 2, c & 1);
            cp_commit();
        }
    }
#undef ISSUE_TILE2

    const int g  = lane >> 2;
    const int t4 = lane & 3;
#pragma unroll
    for (int nt = 0; nt < 8; nt++) {
        const int col = col0 + n0 + nt * 8 + 2 * t4;
        const float b0 = bias[col];
        const float b1 = bias[col + 1];
#pragma unroll
        for (int mt = 0; mt < 2; mt++) {
            const int rtop = row0 + m0 + mt * 16 + g;
#pragma unroll
            for (int half = 0; half < 2; half++) {
                const int r = rtop + half * 8;
                float v0 = acc[mt][nt][half * 2 + 0] + b0;
                float v1 = acc[mt][nt][half * 2 + 1] + b1;
                if (ACT == 1) { v0 = sigmoidf_(v0); v1 = sigmoidf_(v1); }
                else if (ACT == 2) { v0 = v0 * sigmoidf_(v0); v1 = v1 * sigmoidf_(v1); }
                if (SPLIT) {
                    __half* orow = Cs + (size_t)r * (2 * N);
                    __half h0, l0, h1, l1;
                    split_fp16(v0, h0, l0);
                    split_fp16(v1, h1, l1);
                    *(__half2*)(orow + col)     = __halves2half2(h0, h1);
                    *(__half2*)(orow + N + col) = __halves2half2(l0, l1);
                } else {
                    float* orow = Cf + (size_t)r * N;
                    if (RESID) {
                        float2 old = *(float2*)(orow + col);
                        v0 += old.x; v1 += old.y;
                    }
                    *(float2*)(orow + col) = make_float2(v0, v1);
                }
            }
        }
    }
}

// ========== batched prep: ALL weights + node activations in ONE launch ==========
// z<5*NL: layer l=z/5, type z%5 {in,out -> bf16 2-plane; gate,ff1,ff2 -> fp16 1-plane}
__global__ __launch_bounds__(256) void prep_all(
    const float* __restrict__ node,
    const float* __restrict__ W_proj, const float* __restrict__ W_in,
    const float* __restrict__ W_gate, const float* __restrict__ W_out,
    const float* __restrict__ W_ff1,  const float* __restrict__ W_ff2,
    __nv_bfloat16* __restrict__ o_node, __nv_bfloat16* __restrict__ o_proj,
    __nv_bfloat16* __restrict__ o_in, __nv_bfloat16* __restrict__ o_out,
    __half* __restrict__ o_gate, __half* __restrict__ o_ff1, __half* __restrict__ o_ff2)
{
    const int z = blockIdx.z;
    const int nidx = blockIdx.x * 32 + (threadIdx.x & 31);
    const int k0 = blockIdx.y * 128 + (threadIdx.x >> 5) * 16;

    if (z == 5 * NL + 1) {
        if (nidx >= LSEQ || k0 >= DIN) return;
        const float* xr = node + (size_t)nidx * DIN;
        __nv_bfloat16* orow = o_node + (size_t)nidx * 2 * DIN;
#pragma unroll
        for (int i = 0; i < 16; i++) {
            __nv_bfloat16 hi, lo;
            split_bf16(xr[k0 + i], hi, lo);
            orow[k0 + i]       = hi;
            orow[DIN + k0 + i] = lo;
        }
        return;
    }

    const float* W; int K, N;
    if (z == 5 * NL) { W = W_proj; K = DIN; N = DD; }
    else {
        const int l = z / 5, t = z - l * 5;
        switch (t) {
            case 0: W = W_in   + (size_t)l * DD * DD; K = DD; N = DD; break;
            case 1: W = W_gate + (size_t)l * DD * DD; K = DD; N = DD; break;
            case 2: W = W_out  + (size_t)l * DD * DD; K = DD; N = DD; break;
            case 3: W = W_ff1  + (size_t)l * DD * D2; K = DD; N = D2; break;
            default:W = W_ff2  + (size_t)l * D2 * DD; K = D2; N = DD; break;
        }
    }
    if (nidx >= N || k0 >= K) return;

    const int t = (z < 5 * NL) ? (z % 5) : -1;
    if (t == 1 || t == 3 || t == 4) {
        const int l = z / 5;
        __half* orow;
        if (t == 1)      orow = o_gate + (size_t)l * DD * DD + (size_t)nidx * DD;
        else if (t == 3) orow = o_ff1  + (size_t)l * D2 * DD + (size_t)nidx * DD;
        else             orow = o_ff2  + (size_t)l * DD * D2 + (size_t)nidx * D2;
#pragma unroll
        for (int i = 0; i < 16; i++)
            orow[k0 + i] = __float2half_rn(W[(size_t)(k0 + i) * N + nidx]);
    } else {
        __nv_bfloat16* Bp;
        if (z == 5 * NL) Bp = o_proj;
        else {
            const int l = z / 5;
            Bp = (t == 0) ? o_in + (size_t)l * DD * 2 * DD
                          : o_out + (size_t)l * DD * 2 * DD;
        }
        __nv_bfloat16* orow = Bp + (size_t)nidx * 2 * K;
#pragma unroll
        for (int i = 0; i < 16; i++) {
            __nv_bfloat16 hi, lo;
            split_bf16(W[(size_t)(k0 + i) * N + nidx], hi, lo);
            orow[k0 + i]     = hi;
            orow[K + k0 + i] = lo;
        }
    }
}

// ========= LayerNorm -> split bf16 [L,2DD] AND split fp16 [L,2DD] ===============
__global__ __launch_bounds__(256) void ln_split_dual_kernel(
    const float* __restrict__ x, const float* __restrict__ gam,
    const float* __restrict__ bet, __nv_bfloat16* __restrict__ outb,
    __half* __restrict__ outh)
{
    __shared__ float red[8];
    __shared__ float bcast;
    const int tid = threadIdx.x;
    const float* xr = x + (size_t)blockIdx.x * DD;

    float v0 = xr[tid], v1 = xr[tid + 256], v2 = xr[tid + 512];
    float sum = v0 + v1 + v2;
#pragma unroll
    for (int o = 16; o > 0; o >>= 1) sum += __shfl_xor_sync(0xffffffffu, sum, o);
    if ((tid & 31) == 0) red[tid >> 5] = sum;
    __syncthreads();
    if (tid == 0) {
        float t = 0.f;
#pragma unroll
        for (int i = 0; i < 8; i++) t += red[i];
        bcast = t * (1.0f / DD);
    }
    __syncthreads();
    const float mu = bcast;
    float d0 = v0 - mu, d1 = v1 - mu, d2 = v2 - mu;
    float sq = d0 * d0 + d1 * d1 + d2 * d2;
#pragma unroll
    for (int o = 16; o > 0; o >>= 1) sq += __shfl_xor_sync(0xffffffffu, sq, o);
    __syncthreads();
    if ((tid & 31) == 0) red[tid >> 5] = sq;
    __syncthreads();
    if (tid == 0) {
        float t = 0.f;
#pragma unroll
        for (int i = 0; i < 8; i++) t += red[i];
        bcast = rsqrtf(t * (1.0f / DD) + 1e-5f);
    }
    __syncthreads();
    const float inv = bcast;

    __nv_bfloat16* orb = outb + (size_t)blockIdx.x * (2 * DD);
    __half* orh = outh + (size_t)blockIdx.x * (2 * DD);
#pragma unroll
    for (int q = 0; q < 3; q++) {
        const int j = tid + q * 256;
        const float dv = (q == 0 ? d0 : (q == 1 ? d1 : d2));
        float v = dv * inv * gam[j] + bet[j];
        __nv_bfloat16 hi, lo;
        split_bf16(v, hi, lo);
        orb[j]      = hi;
        orb[DD + j] = lo;
        __half hh, hl;
        split_fp16(v, hh, hl);
        orh[j]      = hh;
        orh[DD + j] = hl;
    }
}

// ================= LayerNorm -> split fp16 [L, 2*DD] ============================
__global__ __launch_bounds__(256) void ln_split_f16_kernel(
    const float* __restrict__ x, const float* __restrict__ gam,
    const float* __restrict__ bet, __half* __restrict__ out)
{
    __shared__ float red[8];
    __shared__ float bcast;
    const int tid = threadIdx.x;
    const float* xr = x + (size_t)blockIdx.x * DD;

    float v0 = xr[tid], v1 = xr[tid + 256], v2 = xr[tid + 512];
    float sum = v0 + v1 + v2;
#pragma unroll
    for (int o = 16; o > 0; o >>= 1) sum += __shfl_xor_sync(0xffffffffu, sum, o);
    if ((tid & 31) == 0) red[tid >> 5] = sum;
    __syncthreads();
    if (tid == 0) {
        float t = 0.f;
#pragma unroll
        for (int i = 0; i < 8; i++) t += red[i];
        bcast = t * (1.0f / DD);
    }
    __syncthreads();
    const float mu = bcast;
    float d0 = v0 - mu, d1 = v1 - mu, d2 = v2 - mu;
    float sq = d0 * d0 + d1 * d1 + d2 * d2;
#pragma unroll
    for (int o = 16; o > 0; o >>= 1) sq += __shfl_xor_sync(0xffffffffu, sq, o);
    __syncthreads();
    if ((tid & 31) == 0) red[tid >> 5] = sq;
    __syncthreads();
    if (tid == 0) {
        float t = 0.f;
#pragma unroll
        for (int i = 0; i < 8; i++) t += red[i];
        bcast = rsqrtf(t * (1.0f / DD) + 1e-5f);
    }
    __syncthreads();
    const float inv = bcast;

    __half* orow = out + (size_t)blockIdx.x * (2 * DD);
#pragma unroll
    for (int q = 0; q < 3; q++) {
        const int j = tid + q * 256;
        const float dv = (q == 0 ? d0 : (q == 1 ? d1 : d2));
        float v = dv * inv * gam[j] + bet[j];
        __half hi, lo;
        split_fp16(v, hi, lo);
        orow[j]      = hi;
        orow[DD + j] = lo;
    }
}

// ================= final LayerNorm (fp32 out) ===================================
__global__ __launch_bounds__(256) void ln_final_kernel(
    const float* __restrict__ x, const float* __restrict__ gam,
    const float* __restrict__ bet, float* __restrict__ out)
{
    __shared__ float red[8];
    __shared__ float bcast;
    const int tid = threadIdx.x;
    const float* xr = x + (size_t)blockIdx.x * DD;

    float v0 = xr[tid], v1 = xr[tid + 256], v2 = xr[tid + 512];
    float sum = v0 + v1 + v2;
#pragma unroll
    for (int o = 16; o > 0; o >>= 1) sum += __shfl_xor_sync(0xffffffffu, sum, o);
    if ((tid & 31) == 0) red[tid >> 5] = sum;
    __syncthreads();
    if (tid == 0) {
        float t = 0.f;
#pragma unroll
        for (int i = 0; i < 8; i++) t += red[i];
        bcast = t * (1.0f / DD);
    }
    __syncthreads();
    const float mu = bcast;
    float d0 = v0 - mu, d1 = v1 - mu, d2 = v2 - mu;
    float sq = d0 * d0 + d1 * d1 + d2 * d2;
#pragma unroll
    for (int o = 16; o > 0; o >>= 1) sq += __shfl_xor_sync(0xffffffffu, sq, o);
    __syncthreads();
    if ((tid & 31) == 0) red[tid >> 5] = sq;
    __syncthreads();
    if (tid == 0) {
        float t = 0.f;
#pragma unroll
        for (int i = 0; i < 8; i++) t += red[i];
        bcast = rsqrtf(t * (1.0f / DD) + 1e-5f);
    }
    __syncthreads();
    const float inv = bcast;

    float* orow = out + (size_t)blockIdx.x * DD;
    orow[tid]       = d0 * inv * gam[tid]       + bet[tid];
    orow[tid + 256] = d1 * inv * gam[tid + 256] + bet[tid + 256];
    orow[tid + 512] = d2 * inv * gam[tid + 512] + bet[tid + 512];
}

// ================= scan kernels =================================================
__global__ __launch_bounds__(256) void scan_chunk_kernel(
    const float* __restrict__ u, const float* __restrict__ dlogit,
    float* __restrict__ Sout)
{
    const int d = blockIdx.x * 256 + threadIdx.x;
    const int c = blockIdx.y;
    const float decay = sigmoidf_(dlogit[d]);
    const float* p = u + ((size_t)c * CLEN) * DD + d;
    float s = 0.0f;
#pragma unroll 8
    for (int t = 0; t < CLEN; t++) s = fmaf(decay, s, p[(size_t)t * DD]);
    Sout[c * DD + d] = s;
}

__global__ __launch_bounds__(768) void scan_carry_kernel(
    const float* __restrict__ Sin, const float* __restrict__ dlogit,
    float* __restrict__ carry)
{
    const int d = threadIdx.x;
    const float decay = sigmoidf_(dlogit[d]);
    float A = decay;
#pragma unroll
    for (int i = 0; i < 7; i++) A = A * A;   // decay^128
    float c = 0.0f;
    for (int k = 0; k < NCHUNK; k++) {
        carry[k * DD + d] = c;
        c = fmaf(A, c, Sin[k * DD + d]);
    }
}

__global__ __launch_bounds__(256) void scan_apply_split_kernel(
    const float* __restrict__ u, const float* __restrict__ gate,
    const float* __restrict__ dlogit, const float* __restrict__ carry,
    __nv_bfloat16* __restrict__ out)
{
    const int d = blockIdx.x * 256 + threadIdx.x;
    const int c = blockIdx.y;
    const float decay = sigmoidf_(dlogit[d]);
    const size_t base = ((size_t)c * CLEN) * DD + d;
    float s = carry[c * DD + d];
#pragma unroll 4
    for (int t = 0; t < CLEN; t++) {
        const size_t idx = base + (size_t)t * DD;
        s = fmaf(decay, s, u[idx]);
        float v = s * gate[idx];
        __nv_bfloat16 hi, lo;
        split_bf16(v, hi, lo);
        __nv_bfloat16* orow = out + (size_t)(c * CLEN + t) * (2 * DD);
        orow[d]      = hi;
        orow[DD + d] = lo;
    }
}

// ================= host =========================================================
extern "C" void kernel_launch(void* const* d_in, const int* in_sizes, int n_in,
                              void* d_out, int out_size)
{
    const float* node    = (const float*)d_in[0];
    const float* W_proj  = (const float*)d_in[1];
    const float* b_proj  = (const float*)d_in[2];
    const float* ln_s_g  = (const float*)d_in[3];
    const float* ln_s_b  = (const float*)d_in[4];
    const float* W_in    = (const float*)d_in[5];
    const float* b_in    = (const float*)d_in[6];
    const float* W_gate  = (const float*)d_in[7];
    const float* b_gate  = (const float*)d_in[8];
    const float* W_out   = (const float*)d_in[9];
    const float* b_out   = (const float*)d_in[10];
    const float* dlogit  = (const float*)d_in[11];
    const float* ln_f_g  = (const float*)d_in[12];
    const float* ln_f_b  = (const float*)d_in[13];
    const float* W_ff1   = (const float*)d_in[14];
    const float* b_ff1   = (const float*)d_in[15];
    const float* W_ff2   = (const float*)d_in[16];
    const float* b_ff2   = (const float*)d_in[17];
    const float* ln_o_g  = (const float*)d_in[18];
    const float* ln_o_b  = (const float*)d_in[19];

    float *x, *u, *gate, *S, *carry;
    __nv_bfloat16 *a_node, *a_h, *a_s;
    __nv_bfloat16 *w_proj, *w_in, *w_ot;
    __half *a_h2, *a_hf, *a_t, *w_gt, *w_f1, *w_f2;
    cudaGetSymbolAddress((void**)&x,     g_x);
    cudaGetSymbolAddress((void**)&u,     g_u);
    cudaGetSymbolAddress((void**)&gate,  g_gate);
    cudaGetSymbolAddress((void**)&S,     g_S);
    cudaGetSymbolAddress((void**)&carry, g_carry);
    cudaGetSymbolAddress((void**)&a_node, ab_node);
    cudaGetSymbolAddress((void**)&a_h,    ab_h);
    cudaGetSymbolAddress((void**)&a_s,    ab_s);
    cudaGetSymbolAddress((void**)&a_h2,   ah_h2);
    cudaGetSymbolAddress((void**)&a_hf,   ah_hf);
    cudaGetSymbolAddress((void**)&a_t,    ah_t);
    cudaGetSymbolAddress((void**)&w_proj, wb_proj);
    cudaGetSymbolAddress((void**)&w_in,   wb_in);
    cudaGetSymbolAddress((void**)&w_ot,   wb_out);
    cudaGetSymbolAddress((void**)&w_gt,   wh_gate);
    cudaGetSymbolAddress((void**)&w_f1,   wh_ff1);
    cudaGetSymbolAddress((void**)&w_f2,   wh_ff2);

    cudaFuncSetAttribute(tc_gemm<0, false>, cudaFuncAttributeMaxDynamicSharedMemorySize, GEMM_SMEM_BYTES);
    cudaFuncSetAttribute(tc_gemm<0, true >, cudaFuncAttributeMaxDynamicSharedMemorySize, GEMM_SMEM_BYTES);
    cudaFuncSetAttribute(tc_gemm2<1, false, false>, cudaFuncAttributeMaxDynamicSharedMemorySize, GEMM2_SMEM_BYTES);
    cudaFuncSetAttribute(tc_gemm2<2, false, true >, cudaFuncAttributeMaxDynamicSharedMemorySize, GEMM2_SMEM_BYTES);
    cudaFuncSetAttribute(tc_gemm2<0, true,  false>, cudaFuncAttributeMaxDynamicSharedMemorySize, GEMM2_SMEM_BYTES);

    const dim3 blk(256);
    const dim3 gScan(DD / 256, NCHUNK);
    const dim3 gG6  (DD / 128, LSEQ / 64);    // bf16 kernel, N=768
    const dim3 g2G6 (DD / 128, LSEQ / 128);   // fp16 kernel, N=768
    const dim3 g2G12(D2 / 128, LSEQ / 128);   // fp16 kernel, N=1536

    // ---- launch 0: ALL prep (weights + node) ----
    prep_all<<<dim3(512, 12, 5 * NL + 2), blk>>>(
        node, W_proj, W_in, W_gate, W_out, W_ff1, W_ff2,
        a_node, w_proj, w_in, w_ot, w_gt, w_f1, w_f2);

    // ---- launch 1: x = node @ W_proj + b_proj ----
    tc_gemm<0, false><<<gG6, blk, GEMM_SMEM_BYTES>>>(
        a_node, w_proj, b_proj, x, DIN, DD);

    for (int l = 0; l < NL; l++) {
        const size_t vo = (size_t)l * DD;
        const size_t v1 = (size_t)l * D2;
        const __nv_bfloat16* wi = w_in + (size_t)l * DD * 2 * DD;
        const __nv_bfloat16* wo = w_ot + (size_t)l * DD * 2 * DD;
        const __half* wg = w_gt + (size_t)l * DD * DD;
        const __half* w1 = w_f1 + (size_t)l * D2 * DD;
        const __half* w2 = w_f2 + (size_t)l * DD * D2;

        ln_split_dual_kernel<<<LSEQ, blk>>>(x, ln_s_g + vo, ln_s_b + vo, a_h, a_h2);
        tc_gemm<0, false><<<gG6, blk, GEMM_SMEM_BYTES>>>(
            a_h, wi, b_in + vo, u, DD, DD);
        tc_gemm2<1, false, false><<<g2G6, blk, GEMM2_SMEM_BYTES>>>(
            a_h2, wg, b_gate + vo, gate, nullptr, DD, DD);
        scan_chunk_kernel<<<gScan, blk>>>(u, dlogit + vo, S);
        scan_carry_kernel<<<1, DD>>>(S, dlogit + vo, carry);
        scan_apply_split_kernel<<<gScan, blk>>>(u, gate, dlogit + vo, carry, a_s);
        tc_gemm<0, true><<<gG6, blk, GEMM_SMEM_BYTES>>>(
            a_s, wo, b_out + vo, x, DD, DD);
        ln_split_f16_kernel<<<LSEQ, blk>>>(x, ln_f_g + vo, ln_f_b + vo, a_hf);
        tc_gemm2<2, false, true><<<g2G12, blk, GEMM2_SMEM_BYTES>>>(
            a_hf, w1, b_ff1 + v1, nullptr, a_t, DD, D2);
        tc_gemm2<0, true, false><<<g2G6, blk, GEMM2_SMEM_BYTES>>>(
            a_t, w2, b_ff2 + vo, x, nullptr, D2, DD);
    }

    ln_final_kernel<<<LSEQ, blk>>>(x, ln_o_g, ln_o_b, (float*)d_out);
}

// round 10
// speedup vs baseline: 3.1071x; 1.0999x over previous
#include <cuda_runtime.h>
#include <cuda_bf16.h>
#include <cuda_fp16.h>
#include <math.h>

#define LSEQ 16384
#define DIN  256
#define DD   768
#define D2   1536
#define NL   8
#define NCHUNK 128
#define CLEN   128

// ---------------- fp32 scratch ----------------
__device__ float g_x[(size_t)LSEQ * DD];
__device__ float g_u[(size_t)LSEQ * DD];
__device__ float g_gate[(size_t)LSEQ * DD];
__device__ float g_S[NCHUNK * DD];
__device__ float g_carry[NCHUNK * DD];

// ---- bf16 split activations [hi|lo] stride 2K ----
__device__ __nv_bfloat16 ab_node[(size_t)LSEQ * 2 * DIN];
__device__ __nv_bfloat16 ab_h[(size_t)LSEQ * 2 * DD];
// ---- fp16 split activations ----
__device__ __half ah_h2[(size_t)LSEQ * 2 * DD];   // ln_s output (gate GEMM)
__device__ __half ah_s [(size_t)LSEQ * 2 * DD];   // scan output (out GEMM)
__device__ __half ah_hf[(size_t)LSEQ * 2 * DD];   // ln_f output (ff1)
__device__ __half ah_t [(size_t)LSEQ * 2 * D2];   // silu(ff1) output (ff2)

// ---- bf16 split weights [N rows, 2K] [hi|lo] ----
__device__ __nv_bfloat16 wb_proj[(size_t)DD * 2 * DIN];
__device__ __nv_bfloat16 wb_in  [(size_t)NL * DD * 2 * DD];
// ---- fp16 single-plane weights [N rows, K] ----
__device__ __half wh_gate[(size_t)NL * DD * DD];
__device__ __half wh_out [(size_t)NL * DD * DD];
__device__ __half wh_ff1 [(size_t)NL * D2 * DD];
__device__ __half wh_ff2 [(size_t)NL * DD * D2];

// ================= helpers =================
__device__ __forceinline__ float sigmoidf_(float z) {
    return 1.0f / (1.0f + __expf(-z));
}

__device__ __forceinline__ unsigned smem_u32(const void* p) {
    unsigned a;
    asm("{ .reg .u64 t; cvta.to.shared.u64 t, %1; cvt.u32.u64 %0, t; }"
        : "=r"(a) : "l"(p));
    return a;
}

__device__ __forceinline__ void cpasync16(unsigned s, const void* g) {
    asm volatile("cp.async.cg.shared.global [%0], [%1], 16;"
                 :: "r"(s), "l"(g) : "memory");
}
__device__ __forceinline__ void cp_commit() {
    asm volatile("cp.async.commit_group;" ::: "memory");
}
__device__ __forceinline__ void cp_wait1() {
    asm volatile("cp.async.wait_group 1;" ::: "memory");
}
__device__ __forceinline__ void cp_wait0() {
    asm volatile("cp.async.wait_group 0;" ::: "memory");
}

__device__ __forceinline__ void ldsm4(unsigned* r, unsigned addr) {
    asm volatile("ldmatrix.sync.aligned.m8n8.x4.shared.b16 {%0,%1,%2,%3}, [%4];"
                 : "=r"(r[0]), "=r"(r[1]), "=r"(r[2]), "=r"(r[3]) : "r"(addr));
}

__device__ __forceinline__ void mma16816(float* d, const unsigned* a,
                                         unsigned b0, unsigned b1) {
    asm volatile(
        "mma.sync.aligned.m16n8k16.row.col.f32.bf16.bf16.f32 "
        "{%0,%1,%2,%3}, {%4,%5,%6,%7}, {%8,%9}, {%0,%1,%2,%3};"
        : "+f"(d[0]), "+f"(d[1]), "+f"(d[2]), "+f"(d[3])
        : "r"(a[0]), "r"(a[1]), "r"(a[2]), "r"(a[3]), "r"(b0), "r"(b1));
}

__device__ __forceinline__ void mma16816h(float* d, const unsigned* a,
                                          unsigned b0, unsigned b1) {
    asm volatile(
        "mma.sync.aligned.m16n8k16.row.col.f32.f16.f16.f32 "
        "{%0,%1,%2,%3}, {%4,%5,%6,%7}, {%8,%9}, {%0,%1,%2,%3};"
        : "+f"(d[0]), "+f"(d[1]), "+f"(d[2]), "+f"(d[3])
        : "r"(a[0]), "r"(a[1]), "r"(a[2]), "r"(a[3]), "r"(b0), "r"(b1));
}

__device__ __forceinline__ void split_bf16(float v, __nv_bfloat16& hi, __nv_bfloat16& lo) {
    hi = __float2bfloat16(v);
    lo = __float2bfloat16(v - __bfloat162float(hi));
}
__device__ __forceinline__ void split_fp16(float v, __half& hi, __half& lo) {
    hi = __float2half_rn(v);
    lo = __float2half_rn(v - __half2float(hi));
}

// ================= 3-pass bf16 GEMM, tile 64x128, 2 CTAs/SM =================
// C = epilogue(Ahi·Bhi + Alo·Bhi + Ahi·Blo + bias)
// 256 thr, 8 warps 2Mx4N (warp 32x32). Stage 48KB x 2 stages = 96KB.
#define GEMM_SMEM_BYTES (2 * 49152)

template<int ACT, bool RESID>
__global__ __launch_bounds__(256, 2) void tc_gemm(
    const __nv_bfloat16* __restrict__ A, const __nv_bfloat16* __restrict__ B,
    const float* __restrict__ bias, float* __restrict__ Cf, int K, int N)
{
    extern __shared__ __align__(1024) char smem[];
    const unsigned sbase = smem_u32(smem);
    const int tid  = threadIdx.x;
    const int wid  = tid >> 5;
    const int lane = tid & 31;
    const int K2 = 2 * K;

    const int row0 = blockIdx.y * 64;
    const int col0 = blockIdx.x * 128;

    const int m0 = (wid & 1) * 32;
    const int n0 = (wid >> 1) * 32;

    float acc[2][4][4];
#pragma unroll
    for (int i = 0; i < 2; i++)
#pragma unroll
        for (int j = 0; j < 4; j++)
#pragma unroll
            for (int q = 0; q < 4; q++) acc[i][j][q] = 0.0f;

    const int arow = tid >> 2;
    const int ac0  = (tid & 3) * 2;
    const int brow = tid >> 1;
    const int bc0  = (tid & 1) * 4;
    const __nv_bfloat16* agp = A + (size_t)(row0 + arow) * K2;
    const __nv_bfloat16* bgp = B + (size_t)(col0 + brow) * K2;

    const int NC = K / 64;

#define ISSUE_TILE(ct, s) do {                                              \
        const unsigned sb_ = sbase + (unsigned)(s) * 49152u;                \
        const int kb_ = (ct) * 64;                                          \
        _Pragma("unroll")                                                   \
        for (int i_ = 0; i_ < 2; i_++) {                                    \
            const int c_ = ac0 + i_;                                        \
            const unsigned off_ = (unsigned)(arow * 128 + ((c_ ^ (arow & 7)) << 4)); \
            cpasync16(sb_ + off_,         agp + kb_ + c_ * 8);              \
            cpasync16(sb_ + 8192u + off_, agp + K + kb_ + c_ * 8);          \
        }                                                                   \
        _Pragma("unroll")                                                   \
        for (int i_ = 0; i_ < 4; i_++) {                                    \
            const int c_ = bc0 + i_;                                        \
            const unsigned off_ = (unsigned)(brow * 128 + ((c_ ^ (brow & 7)) << 4)); \
            cpasync16(sb_ + 16384u + off_, bgp + kb_ + c_ * 8);             \
            cpasync16(sb_ + 32768u + off_, bgp + K + kb_ + c_ * 8);         \
        }                                                                   \
    } while (0)

    ISSUE_TILE(0, 0);
    cp_commit();
    if (NC > 1) { ISSUE_TILE(1, 1); }
    cp_commit();

    for (int c = 0; c < NC; c++) {
        if (c + 1 < NC) cp_wait1(); else cp_wait0();
        __syncthreads();

        const unsigned sAhi = sbase + (unsigned)(c & 1) * 49152u;
        const unsigned sAlo = sAhi + 8192u;
        const unsigned sBhi = sAhi + 16384u;
        const unsigned sBlo = sAhi + 32768u;

#pragma unroll
        for (int kk4 = 0; kk4 < 4; kk4++) {
            const int cb = kk4 * 2;
            unsigned ahi[2][4], alo[2][4], bfr[2][4];
            unsigned boff[2];
#pragma unroll
            for (int mt = 0; mt < 2; mt++) {
                const int r = m0 + mt * 16 + (lane & 15);
                const int ch = cb + (lane >> 4);
                const unsigned off = (unsigned)(r * 128 + ((ch ^ (r & 7)) << 4));
                ldsm4(ahi[mt], sAhi + off);
                ldsm4(alo[mt], sAlo + off);
            }
#pragma unroll
            for (int jp = 0; jp < 2; jp++) {
                const int rn = n0 + jp * 16 + ((lane >> 4) << 3) + (lane & 7);
                const int ch = cb + ((lane >> 3) & 1);
                boff[jp] = (unsigned)(rn * 128 + ((ch ^ (rn & 7)) << 4));
                ldsm4(bfr[jp], sBhi + boff[jp]);
            }
#pragma unroll
            for (int mt = 0; mt < 2; mt++)
#pragma unroll
                for (int nt = 0; nt < 4; nt++) {
                    mma16816(acc[mt][nt], ahi[mt],
                             bfr[nt >> 1][(nt & 1) * 2],
                             bfr[nt >> 1][(nt & 1) * 2 + 1]);
                    mma16816(acc[mt][nt], alo[mt],
                             bfr[nt >> 1][(nt & 1) * 2],
                             bfr[nt >> 1][(nt & 1) * 2 + 1]);
                }
#pragma unroll
            for (int jp = 0; jp < 2; jp++)
                ldsm4(bfr[jp], sBlo + boff[jp]);
#pragma unroll
            for (int mt = 0; mt < 2; mt++)
#pragma unroll
                for (int nt = 0; nt < 4; nt++)
                    mma16816(acc[mt][nt], ahi[mt],
                             bfr[nt >> 1][(nt & 1) * 2],
                             bfr[nt >> 1][(nt & 1) * 2 + 1]);
        }
        __syncthreads();
        if (c + 2 < NC) {
            ISSUE_TILE(c + 2, c & 1);
            cp_commit();
        }
    }
#undef ISSUE_TILE

    const int g  = lane >> 2;
    const int t4 = lane & 3;
#pragma unroll
    for (int nt = 0; nt < 4; nt++) {
        const int col = col0 + n0 + nt * 8 + 2 * t4;
        const float b0 = bias[col];
        const float b1 = bias[col + 1];
#pragma unroll
        for (int mt = 0; mt < 2; mt++) {
            const int rtop = row0 + m0 + mt * 16 + g;
#pragma unroll
            for (int half = 0; half < 2; half++) {
                const int r = rtop + half * 8;
                float v0 = acc[mt][nt][half * 2 + 0] + b0;
                float v1 = acc[mt][nt][half * 2 + 1] + b1;
                if (ACT == 1) { v0 = sigmoidf_(v0); v1 = sigmoidf_(v1); }
                float* orow = Cf + (size_t)r * N;
                if (RESID) {
                    float2 old = *(float2*)(orow + col);
                    v0 += old.x; v1 += old.y;
                }
                *(float2*)(orow + col) = make_float2(v0, v1);
            }
        }
    }
}

// ================= 2-pass fp16 GEMM, tile 64x128, 3 stages, 2 CTAs/SM ===========
// C = epilogue(Ahi·B + Alo·B + bias). Stage = Ahi8K+Alo8K+B16K = 32KB x 3 = 96KB.
// 8 warps 2Mx4N, warp tile 32x32. (R8-proven config.)
#define GEMM2_SMEM_BYTES (3 * 32768)

template<int ACT, bool RESID, bool SPLIT>
__global__ __launch_bounds__(256, 2) void tc_gemm2(
    const __half* __restrict__ A, const __half* __restrict__ B,
    const float* __restrict__ bias, float* __restrict__ Cf,
    __half* __restrict__ Cs, int K, int N)
{
    extern __shared__ __align__(1024) char smem[];
    const unsigned sbase = smem_u32(smem);
    const int tid  = threadIdx.x;
    const int wid  = tid >> 5;
    const int lane = tid & 31;
    const int K2 = 2 * K;

    const int row0 = blockIdx.y * 64;
    const int col0 = blockIdx.x * 128;

    const int m0 = (wid & 1) * 32;
    const int n0 = (wid >> 1) * 32;

    float acc[2][4][4];
#pragma unroll
    for (int i = 0; i < 2; i++)
#pragma unroll
        for (int j = 0; j < 4; j++)
#pragma unroll
            for (int q = 0; q < 4; q++) acc[i][j][q] = 0.0f;

    const int arow = tid >> 2;
    const int ac0  = (tid & 3) * 2;
    const int brow = tid >> 1;
    const int bc0  = (tid & 1) * 4;
    const __half* agp = A + (size_t)(row0 + arow) * K2;
    const __half* bgp = B + (size_t)(col0 + brow) * K;

    const int NC = K / 64;

#define ISSUE_TILE2(ct, s) do {                                             \
        const unsigned sb_ = sbase + (unsigned)(s) * 32768u;                \
        const int kb_ = (ct) * 64;                                          \
        _Pragma("unroll")                                                   \
        for (int i_ = 0; i_ < 2; i_++) {                                    \
            const int c_ = ac0 + i_;                                        \
            const unsigned off_ = (unsigned)(arow * 128 + ((c_ ^ (arow & 7)) << 4)); \
            cpasync16(sb_ + off_,         agp + kb_ + c_ * 8);              \
            cpasync16(sb_ + 8192u + off_, agp + K + kb_ + c_ * 8);          \
        }                                                                   \
        _Pragma("unroll")                                                   \
        for (int i_ = 0; i_ < 4; i_++) {                                    \
            const int c_ = bc0 + i_;                                        \
            const unsigned off_ = (unsigned)(brow * 128 + ((c_ ^ (brow & 7)) << 4)); \
            cpasync16(sb_ + 16384u + off_, bgp + kb_ + c_ * 8);             \
        }                                                                   \
    } while (0)

    ISSUE_TILE2(0, 0);
    cp_commit();
    if (NC > 1) { ISSUE_TILE2(1, 1); }
    cp_commit();

    int sidx = 0;
    for (int c = 0; c < NC; c++) {
        if (c + 1 < NC) cp_wait1(); else cp_wait0();
        __syncthreads();

        if (c + 2 < NC) {
            int fs = sidx + 2; if (fs >= 3) fs -= 3;
            ISSUE_TILE2(c + 2, fs);
            cp_commit();
        }

        const unsigned sAhi = sbase + (unsigned)sidx * 32768u;
        const unsigned sAlo = sAhi + 8192u;
        const unsigned sB   = sAhi + 16384u;

#pragma unroll
        for (int kk4 = 0; kk4 < 4; kk4++) {
            const int cb = kk4 * 2;
            unsigned ahi[2][4], alo[2][4], bfr[2][4];
#pragma unroll
            for (int mt = 0; mt < 2; mt++) {
                const int r = m0 + mt * 16 + (lane & 15);
                const int ch = cb + (lane >> 4);
                const unsigned off = (unsigned)(r * 128 + ((ch ^ (r & 7)) << 4));
                ldsm4(ahi[mt], sAhi + off);
                ldsm4(alo[mt], sAlo + off);
            }
#pragma unroll
            for (int jp = 0; jp < 2; jp++) {
                const int rn = n0 + jp * 16 + ((lane >> 4) << 3) + (lane & 7);
                const int ch = cb + ((lane >> 3) & 1);
                ldsm4(bfr[jp], sB + (unsigned)(rn * 128 + ((ch ^ (rn & 7)) << 4)));
            }
#pragma unroll
            for (int mt = 0; mt < 2; mt++)
#pragma unroll
                for (int nt = 0; nt < 4; nt++) {
                    mma16816h(acc[mt][nt], ahi[mt],
                              bfr[nt >> 1][(nt & 1) * 2],
                              bfr[nt >> 1][(nt & 1) * 2 + 1]);
                    mma16816h(acc[mt][nt], alo[mt],
                              bfr[nt >> 1][(nt & 1) * 2],
                              bfr[nt >> 1][(nt & 1) * 2 + 1]);
                }
        }
        sidx++; if (sidx >= 3) sidx -= 3;
    }
#undef ISSUE_TILE2

    const int g  = lane >> 2;
    const int t4 = lane & 3;
#pragma unroll
    for (int nt = 0; nt < 4; nt++) {
        const int col = col0 + n0 + nt * 8 + 2 * t4;
        const float b0 = bias[col];
        const float b1 = bias[col + 1];
#pragma unroll
        for (int mt = 0; mt < 2; mt++) {
            const int rtop = row0 + m0 + mt * 16 + g;
#pragma unroll
            for (int half = 0; half < 2; half++) {
                const int r = rtop + half * 8;
                float v0 = acc[mt][nt][half * 2 + 0] + b0;
                float v1 = acc[mt][nt][half * 2 + 1] + b1;
                if (ACT == 1) { v0 = sigmoidf_(v0); v1 = sigmoidf_(v1); }
                else if (ACT == 2) { v0 = v0 * sigmoidf_(v0); v1 = v1 * sigmoidf_(v1); }
                if (SPLIT) {
                    __half* orow = Cs + (size_t)r * (2 * N);
                    __half h0, l0, h1, l1;
                    split_fp16(v0, h0, l0);
                    split_fp16(v1, h1, l1);
                    *(__half2*)(orow + col)     = __halves2half2(h0, h1);
                    *(__half2*)(orow + N + col) = __halves2half2(l0, l1);
                } else {
                    float* orow = Cf + (size_t)r * N;
                    if (RESID) {
                        float2 old = *(float2*)(orow + col);
                        v0 += old.x; v1 += old.y;
                    }
                    *(float2*)(orow + col) = make_float2(v0, v1);
                }
            }
        }
    }
}

// ========== batched prep: ALL weights + node activations in ONE launch ==========
// type: 0=in (bf16 2-plane), 1=gate 2=out 3=ff1 4=ff2 (fp16 1-plane)
__global__ __launch_bounds__(256) void prep_all(
    const float* __restrict__ node,
    const float* __restrict__ W_proj, const float* __restrict__ W_in,
    const float* __restrict__ W_gate, const float* __restrict__ W_out,
    const float* __restrict__ W_ff1,  const float* __restrict__ W_ff2,
    __nv_bfloat16* __restrict__ o_node, __nv_bfloat16* __restrict__ o_proj,
    __nv_bfloat16* __restrict__ o_in,
    __half* __restrict__ o_gate, __half* __restrict__ o_out,
    __half* __restrict__ o_ff1, __half* __restrict__ o_ff2)
{
    const int z = blockIdx.z;
    const int nidx = blockIdx.x * 32 + (threadIdx.x & 31);
    const int k0 = blockIdx.y * 128 + (threadIdx.x >> 5) * 16;

    if (z == 5 * NL + 1) {
        if (nidx >= LSEQ || k0 >= DIN) return;
        const float* xr = node + (size_t)nidx * DIN;
        __nv_bfloat16* orow = o_node + (size_t)nidx * 2 * DIN;
#pragma unroll
        for (int i = 0; i < 16; i++) {
            __nv_bfloat16 hi, lo;
            split_bf16(xr[k0 + i], hi, lo);
            orow[k0 + i]       = hi;
            orow[DIN + k0 + i] = lo;
        }
        return;
    }

    const float* W; int K, N;
    if (z == 5 * NL) { W = W_proj; K = DIN; N = DD; }
    else {
        const int l = z / 5, t = z - l * 5;
        switch (t) {
            case 0: W = W_in   + (size_t)l * DD * DD; K = DD; N = DD; break;
            case 1: W = W_gate + (size_t)l * DD * DD; K = DD; N = DD; break;
            case 2: W = W_out  + (size_t)l * DD * DD; K = DD; N = DD; break;
            case 3: W = W_ff1  + (size_t)l * DD * D2; K = DD; N = D2; break;
            default:W = W_ff2  + (size_t)l * D2 * DD; K = D2; N = DD; break;
        }
    }
    if (nidx >= N || k0 >= K) return;

    const int t = (z < 5 * NL) ? (z % 5) : -1;
    if (t >= 1) {
        const int l = z / 5;
        __half* orow;
        if (t == 1)      orow = o_gate + (size_t)l * DD * DD + (size_t)nidx * DD;
        else if (t == 2) orow = o_out  + (size_t)l * DD * DD + (size_t)nidx * DD;
        else if (t == 3) orow = o_ff1  + (size_t)l * D2 * DD + (size_t)nidx * DD;
        else             orow = o_ff2  + (size_t)l * DD * D2 + (size_t)nidx * D2;
#pragma unroll
        for (int i = 0; i < 16; i++)
            orow[k0 + i] = __float2half_rn(W[(size_t)(k0 + i) * N + nidx]);
    } else {
        __nv_bfloat16* Bp = (z == 5 * NL) ? o_proj
                           : o_in + (size_t)(z / 5) * DD * 2 * DD;
        __nv_bfloat16* orow = Bp + (size_t)nidx * 2 * K;
#pragma unroll
        for (int i = 0; i < 16; i++) {
            __nv_bfloat16 hi, lo;
            split_bf16(W[(size_t)(k0 + i) * N + nidx], hi, lo);
            orow[k0 + i]     = hi;
            orow[K + k0 + i] = lo;
        }
    }
}

// ========= LayerNorm -> split bf16 [L,2DD] AND split fp16 [L,2DD] ===============
__global__ __launch_bounds__(256) void ln_split_dual_kernel(
    const float* __restrict__ x, const float* __restrict__ gam,
    const float* __restrict__ bet, __nv_bfloat16* __restrict__ outb,
    __half* __restrict__ outh)
{
    __shared__ float red[8];
    __shared__ float bcast;
    const int tid = threadIdx.x;
    const float* xr = x + (size_t)blockIdx.x * DD;

    float v0 = xr[tid], v1 = xr[tid + 256], v2 = xr[tid + 512];
    float sum = v0 + v1 + v2;
#pragma unroll
    for (int o = 16; o > 0; o >>= 1) sum += __shfl_xor_sync(0xffffffffu, sum, o);
    if ((tid & 31) == 0) red[tid >> 5] = sum;
    __syncthreads();
    if (tid == 0) {
        float t = 0.f;
#pragma unroll
        for (int i = 0; i < 8; i++) t += red[i];
        bcast = t * (1.0f / DD);
    }
    __syncthreads();
    const float mu = bcast;
    float d0 = v0 - mu, d1 = v1 - mu, d2 = v2 - mu;
    float sq = d0 * d0 + d1 * d1 + d2 * d2;
#pragma unroll
    for (int o = 16; o > 0; o >>= 1) sq += __shfl_xor_sync(0xffffffffu, sq, o);
    __syncthreads();
    if ((tid & 31) == 0) red[tid >> 5] = sq;
    __syncthreads();
    if (tid == 0) {
        float t = 0.f;
#pragma unroll
        for (int i = 0; i < 8; i++) t += red[i];
        bcast = rsqrtf(t * (1.0f / DD) + 1e-5f);
    }
    __syncthreads();
    const float inv = bcast;

    __nv_bfloat16* orb = outb + (size_t)blockIdx.x * (2 * DD);
    __half* orh = outh + (size_t)blockIdx.x * (2 * DD);
#pragma unroll
    for (int q = 0; q < 3; q++) {
        const int j = tid + q * 256;
        const float dv = (q == 0 ? d0 : (q == 1 ? d1 : d2));
        float v = dv * inv * gam[j] + bet[j];
        __nv_bfloat16 hi, lo;
        split_bf16(v, hi, lo);
        orb[j]      = hi;
        orb[DD + j] = lo;
        __half hh, hl;
        split_fp16(v, hh, hl);
        orh[j]      = hh;
        orh[DD + j] = hl;
    }
}

// ================= LayerNorm -> split fp16 [L, 2*DD] ============================
__global__ __launch_bounds__(256) void ln_split_f16_kernel(
    const float* __restrict__ x, const float* __restrict__ gam,
    const float* __restrict__ bet, __half* __restrict__ out)
{
    __shared__ float red[8];
    __shared__ float bcast;
    const int tid = threadIdx.x;
    const float* xr = x + (size_t)blockIdx.x * DD;

    float v0 = xr[tid], v1 = xr[tid + 256], v2 = xr[tid + 512];
    float sum = v0 + v1 + v2;
#pragma unroll
    for (int o = 16; o > 0; o >>= 1) sum += __shfl_xor_sync(0xffffffffu, sum, o);
    if ((tid & 31) == 0) red[tid >> 5] = sum;
    __syncthreads();
    if (tid == 0) {
        float t = 0.f;
#pragma unroll
        for (int i = 0; i < 8; i++) t += red[i];
        bcast = t * (1.0f / DD);
    }
    __syncthreads();
    const float mu = bcast;
    float d0 = v0 - mu, d1 = v1 - mu, d2 = v2 - mu;
    float sq = d0 * d0 + d1 * d1 + d2 * d2;
#pragma unroll
    for (int o = 16; o > 0; o >>= 1) sq += __shfl_xor_sync(0xffffffffu, sq, o);
    __syncthreads();
    if ((tid & 31) == 0) red[tid >> 5] = sq;
    __syncthreads();
    if (tid == 0) {
        float t = 0.f;
#pragma unroll
        for (int i = 0; i < 8; i++) t += red[i];
        bcast = rsqrtf(t * (1.0f / DD) + 1e-5f);
    }
    __syncthreads();
    const float inv = bcast;

    __half* orow = out + (size_t)blockIdx.x * (2 * DD);
#pragma unroll
    for (int q = 0; q < 3; q++) {
        const int j = tid + q * 256;
        const float dv = (q == 0 ? d0 : (q == 1 ? d1 : d2));
        float v = dv * inv * gam[j] + bet[j];
        __half hi, lo;
        split_fp16(v, hi, lo);
        orow[j]      = hi;
        orow[DD + j] = lo;
    }
}

// ================= final LayerNorm (fp32 out) ===================================
__global__ __launch_bounds__(256) void ln_final_kernel(
    const float* __restrict__ x, const float* __restrict__ gam,
    const float* __restrict__ bet, float* __restrict__ out)
{
    __shared__ float red[8];
    __shared__ float bcast;
    const int tid = threadIdx.x;
    const float* xr = x + (size_t)blockIdx.x * DD;

    float v0 = xr[tid], v1 = xr[tid + 256], v2 = xr[tid + 512];
    float sum = v0 + v1 + v2;
#pragma unroll
    for (int o = 16; o > 0; o >>= 1) sum += __shfl_xor_sync(0xffffffffu, sum, o);
    if ((tid & 31) == 0) red[tid >> 5] = sum;
    __syncthreads();
    if (tid == 0) {
        float t = 0.f;
#pragma unroll
        for (int i = 0; i < 8; i++) t += red[i];
        bcast = t * (1.0f / DD);
    }
    __syncthreads();
    const float mu = bcast;
    float d0 = v0 - mu, d1 = v1 - mu, d2 = v2 - mu;
    float sq = d0 * d0 + d1 * d1 + d2 * d2;
#pragma unroll
    for (int o = 16; o > 0; o >>= 1) sq += __shfl_xor_sync(0xffffffffu, sq, o);
    __syncthreads();
    if ((tid & 31) == 0) red[tid >> 5] = sq;
    __syncthreads();
    if (tid == 0) {
        float t = 0.f;
#pragma unroll
        for (int i = 0; i < 8; i++) t += red[i];
        bcast = rsqrtf(t * (1.0f / DD) + 1e-5f);
    }
    __syncthreads();
    const float inv = bcast;

    float* orow = out + (size_t)blockIdx.x * DD;
    orow[tid]       = d0 * inv * gam[tid]       + bet[tid];
    orow[tid + 256] = d1 * inv * gam[tid + 256] + bet[tid + 256];
    orow[tid + 512] = d2 * inv * gam[tid + 512] + bet[tid + 512];
}

// ================= scan kernels =================================================
__global__ __launch_bounds__(256) void scan_chunk_kernel(
    const float* __restrict__ u, const float* __restrict__ dlogit,
    float* __restrict__ Sout)
{
    const int d = blockIdx.x * 256 + threadIdx.x;
    const int c = blockIdx.y;
    const float decay = sigmoidf_(dlogit[d]);
    const float* p = u + ((size_t)c * CLEN) * DD + d;
    float s = 0.0f;
#pragma unroll 8
    for (int t = 0; t < CLEN; t++) s = fmaf(decay, s, p[(size_t)t * DD]);
    Sout[c * DD + d] = s;
}

__global__ __launch_bounds__(768) void scan_carry_kernel(
    const float* __restrict__ Sin, const float* __restrict__ dlogit,
    float* __restrict__ carry)
{
    const int d = threadIdx.x;
    const float decay = sigmoidf_(dlogit[d]);
    float A = decay;
#pragma unroll
    for (int i = 0; i < 7; i++) A = A * A;   // decay^128
    float c = 0.0f;
    for (int k = 0; k < NCHUNK; k++) {
        carry[k * DD + d] = c;
        c = fmaf(A, c, Sin[k * DD + d]);
    }
}

// re-scan with carry, gate-multiply, emit split fp16 [L, 2*DD]
__global__ __launch_bounds__(256) void scan_apply_split_f16_kernel(
    const float* __restrict__ u, const float* __restrict__ gate,
    const float* __restrict__ dlogit, const float* __restrict__ carry,
    __half* __restrict__ out)
{
    const int d = blockIdx.x * 256 + threadIdx.x;
    const int c = blockIdx.y;
    const float decay = sigmoidf_(dlogit[d]);
    const size_t base = ((size_t)c * CLEN) * DD + d;
    float s = carry[c * DD + d];
#pragma unroll 4
    for (int t = 0; t < CLEN; t++) {
        const size_t idx = base + (size_t)t * DD;
        s = fmaf(decay, s, u[idx]);
        float v = s * gate[idx];
        __half hi, lo;
        split_fp16(v, hi, lo);
        __half* orow = out + (size_t)(c * CLEN + t) * (2 * DD);
        orow[d]      = hi;
        orow[DD + d] = lo;
    }
}

// ================= host =========================================================
extern "C" void kernel_launch(void* const* d_in, const int* in_sizes, int n_in,
                              void* d_out, int out_size)
{
    const float* node    = (const float*)d_in[0];
    const float* W_proj  = (const float*)d_in[1];
    const float* b_proj  = (const float*)d_in[2];
    const float* ln_s_g  = (const float*)d_in[3];
    const float* ln_s_b  = (const float*)d_in[4];
    const float* W_in    = (const float*)d_in[5];
    const float* b_in    = (const float*)d_in[6];
    const float* W_gate  = (const float*)d_in[7];
    const float* b_gate  = (const float*)d_in[8];
    const float* W_out   = (const float*)d_in[9];
    const float* b_out   = (const float*)d_in[10];
    const float* dlogit  = (const float*)d_in[11];
    const float* ln_f_g  = (const float*)d_in[12];
    const float* ln_f_b  = (const float*)d_in[13];
    const float* W_ff1   = (const float*)d_in[14];
    const float* b_ff1   = (const float*)d_in[15];
    const float* W_ff2   = (const float*)d_in[16];
    const float* b_ff2   = (const float*)d_in[17];
    const float* ln_o_g  = (const float*)d_in[18];
    const float* ln_o_b  = (const float*)d_in[19];

    float *x, *u, *gate, *S, *carry;
    __nv_bfloat16 *a_node, *a_h;
    __nv_bfloat16 *w_proj, *w_in;
    __half *a_h2, *a_sf, *a_hf, *a_t, *w_gt, *w_ot, *w_f1, *w_f2;
    cudaGetSymbolAddress((void**)&x,     g_x);
    cudaGetSymbolAddress((void**)&u,     g_u);
    cudaGetSymbolAddress((void**)&gate,  g_gate);
    cudaGetSymbolAddress((void**)&S,     g_S);
    cudaGetSymbolAddress((void**)&carry, g_carry);
    cudaGetSymbolAddress((void**)&a_node, ab_node);
    cudaGetSymbolAddress((void**)&a_h,    ab_h);
    cudaGetSymbolAddress((void**)&a_h2,   ah_h2);
    cudaGetSymbolAddress((void**)&a_sf,   ah_s);
    cudaGetSymbolAddress((void**)&a_hf,   ah_hf);
    cudaGetSymbolAddress((void**)&a_t,    ah_t);
    cudaGetSymbolAddress((void**)&w_proj, wb_proj);
    cudaGetSymbolAddress((void**)&w_in,   wb_in);
    cudaGetSymbolAddress((void**)&w_gt,   wh_gate);
    cudaGetSymbolAddress((void**)&w_ot,   wh_out);
    cudaGetSymbolAddress((void**)&w_f1,   wh_ff1);
    cudaGetSymbolAddress((void**)&w_f2,   wh_ff2);

    cudaFuncSetAttribute(tc_gemm<0, false>, cudaFuncAttributeMaxDynamicSharedMemorySize, GEMM_SMEM_BYTES);
    cudaFuncSetAttribute(tc_gemm2<1, false, false>, cudaFuncAttributeMaxDynamicSharedMemorySize, GEMM2_SMEM_BYTES);
    cudaFuncSetAttribute(tc_gemm2<2, false, true >, cudaFuncAttributeMaxDynamicSharedMemorySize, GEMM2_SMEM_BYTES);
    cudaFuncSetAttribute(tc_gemm2<0, true,  false>, cudaFuncAttributeMaxDynamicSharedMemorySize, GEMM2_SMEM_BYTES);

    const dim3 blk(256);
    const dim3 gScan(DD / 256, NCHUNK);
    const dim3 gG6  (DD / 128, LSEQ / 64);    // 64-row tiles, N=768
    const dim3 gG12 (D2 / 128, LSEQ / 64);    // 64-row tiles, N=1536

    // ---- launch 0: ALL prep (weights + node) ----
    prep_all<<<dim3(512, 12, 5 * NL + 2), blk>>>(
        node, W_proj, W_in, W_gate, W_out, W_ff1, W_ff2,
        a_node, w_proj, w_in, w_gt, w_ot, w_f1, w_f2);

    // ---- launch 1: x = node @ W_proj + b_proj ----
    tc_gemm<0, false><<<gG6, blk, GEMM_SMEM_BYTES>>>(
        a_node, w_proj, b_proj, x, DIN, DD);

    for (int l = 0; l < NL; l++) {
        const size_t vo = (size_t)l * DD;
        const size_t v1 = (size_t)l * D2;
        const __nv_bfloat16* wi = w_in + (size_t)l * DD * 2 * DD;
        const __half* wg = w_gt + (size_t)l * DD * DD;
        const __half* wo = w_ot + (size_t)l * DD * DD;
        const __half* w1 = w_f1 + (size_t)l * D2 * DD;
        const __half* w2 = w_f2 + (size_t)l * DD * D2;

        ln_split_dual_kernel<<<LSEQ, blk>>>(x, ln_s_g + vo, ln_s_b + vo, a_h, a_h2);
        tc_gemm<0, false><<<gG6, blk, GEMM_SMEM_BYTES>>>(
            a_h, wi, b_in + vo, u, DD, DD);
        tc_gemm2<1, false, false><<<gG6, blk, GEMM2_SMEM_BYTES>>>(
            a_h2, wg, b_gate + vo, gate, nullptr, DD, DD);
        scan_chunk_kernel<<<gScan, blk>>>(u, dlogit + vo, S);
        scan_carry_kernel<<<1, DD>>>(S, dlogit + vo, carry);
        scan_apply_split_f16_kernel<<<gScan, blk>>>(u, gate, dlogit + vo, carry, a_sf);
        tc_gemm2<0, true, false><<<gG6, blk, GEMM2_SMEM_BYTES>>>(
            a_sf, wo, b_out + vo, x, nullptr, DD, DD);
        ln_split_f16_kernel<<<LSEQ, blk>>>(x, ln_f_g + vo, ln_f_b + vo, a_hf);
        tc_gemm2<2, false, true><<<gG12, blk, GEMM2_SMEM_BYTES>>>(
            a_hf, w1, b_ff1 + v1, nullptr, a_t, DD, D2);
        tc_gemm2<0, true, false><<<gG6, blk, GEMM2_SMEM_BYTES>>>(
            a_t, w2, b_ff2 + vo, x, nullptr, D2, DD);
    }

    ln_final_kernel<<<LSEQ, blk>>>(x, ln_o_g, ln_o_b, (float*)d_out);
}

// round 11
// speedup vs baseline: 3.3338x; 1.0730x over previous
#include <cuda_runtime.h>
#include <cuda_bf16.h>
#include <cuda_fp16.h>
#include <math.h>

#define LSEQ 16384
#define DIN  256
#define DD   768
#define D2   1536
#define NL   8
#define NCHUNK 128
#define CLEN   128

// ---------------- fp32 scratch ----------------
__device__ float g_x[(size_t)LSEQ * DD];
__device__ float g_u[(size_t)LSEQ * DD];
__device__ float g_gate[(size_t)LSEQ * DD];
__device__ float g_S[NCHUNK * DD];
__device__ float g_carry[NCHUNK * DD];

// ---- bf16 split activations [hi|lo] stride 2K (proj only) ----
__device__ __nv_bfloat16 ab_node[(size_t)LSEQ * 2 * DIN];
// ---- fp16 split activations ----
__device__ __half ah_h2[(size_t)LSEQ * 2 * DD];   // ln_s output (in + gate GEMMs)
__device__ __half ah_s [(size_t)LSEQ * 2 * DD];   // scan output (out GEMM)
__device__ __half ah_hf[(size_t)LSEQ * 2 * DD];   // ln_f output (ff1)
__device__ __half ah_t [(size_t)LSEQ * 2 * D2];   // silu(ff1) output (ff2)

// ---- bf16 split weights [N rows, 2K] [hi|lo] (proj only) ----
__device__ __nv_bfloat16 wb_proj[(size_t)DD * 2 * DIN];
// ---- fp16 single-plane weights [N rows, K] ----
__device__ __half wh_in  [(size_t)NL * DD * DD];
__device__ __half wh_gate[(size_t)NL * DD * DD];
__device__ __half wh_out [(size_t)NL * DD * DD];
__device__ __half wh_ff1 [(size_t)NL * D2 * DD];
__device__ __half wh_ff2 [(size_t)NL * DD * D2];

// ================= helpers =================
__device__ __forceinline__ float sigmoidf_(float z) {
    return 1.0f / (1.0f + __expf(-z));
}

__device__ __forceinline__ unsigned smem_u32(const void* p) {
    unsigned a;
    asm("{ .reg .u64 t; cvta.to.shared.u64 t, %1; cvt.u32.u64 %0, t; }"
        : "=r"(a) : "l"(p));
    return a;
}

__device__ __forceinline__ void cpasync16(unsigned s, const void* g) {
    asm volatile("cp.async.cg.shared.global [%0], [%1], 16;"
                 :: "r"(s), "l"(g) : "memory");
}
__device__ __forceinline__ void cp_commit() {
    asm volatile("cp.async.commit_group;" ::: "memory");
}
__device__ __forceinline__ void cp_wait1() {
    asm volatile("cp.async.wait_group 1;" ::: "memory");
}
__device__ __forceinline__ void cp_wait0() {
    asm volatile("cp.async.wait_group 0;" ::: "memory");
}

__device__ __forceinline__ void ldsm4(unsigned* r, unsigned addr) {
    asm volatile("ldmatrix.sync.aligned.m8n8.x4.shared.b16 {%0,%1,%2,%3}, [%4];"
                 : "=r"(r[0]), "=r"(r[1]), "=r"(r[2]), "=r"(r[3]) : "r"(addr));
}

__device__ __forceinline__ void mma16816(float* d, const unsigned* a,
                                         unsigned b0, unsigned b1) {
    asm volatile(
        "mma.sync.aligned.m16n8k16.row.col.f32.bf16.bf16.f32 "
        "{%0,%1,%2,%3}, {%4,%5,%6,%7}, {%8,%9}, {%0,%1,%2,%3};"
        : "+f"(d[0]), "+f"(d[1]), "+f"(d[2]), "+f"(d[3])
        : "r"(a[0]), "r"(a[1]), "r"(a[2]), "r"(a[3]), "r"(b0), "r"(b1));
}

__device__ __forceinline__ void mma16816h(float* d, const unsigned* a,
                                          unsigned b0, unsigned b1) {
    asm volatile(
        "mma.sync.aligned.m16n8k16.row.col.f32.f16.f16.f32 "
        "{%0,%1,%2,%3}, {%4,%5,%6,%7}, {%8,%9}, {%0,%1,%2,%3};"
        : "+f"(d[0]), "+f"(d[1]), "+f"(d[2]), "+f"(d[3])
        : "r"(a[0]), "r"(a[1]), "r"(a[2]), "r"(a[3]), "r"(b0), "r"(b1));
}

__device__ __forceinline__ void split_bf16(float v, __nv_bfloat16& hi, __nv_bfloat16& lo) {
    hi = __float2bfloat16(v);
    lo = __float2bfloat16(v - __bfloat162float(hi));
}
__device__ __forceinline__ void split_fp16(float v, __half& hi, __half& lo) {
    hi = __float2half_rn(v);
    lo = __float2half_rn(v - __half2float(hi));
}

// ================= 3-pass bf16 GEMM, tile 64x128, 2 CTAs/SM (proj only) =========
#define GEMM_SMEM_BYTES (2 * 49152)

template<int ACT, bool RESID>
__global__ __launch_bounds__(256, 2) void tc_gemm(
    const __nv_bfloat16* __restrict__ A, const __nv_bfloat16* __restrict__ B,
    const float* __restrict__ bias, float* __restrict__ Cf, int K, int N)
{
    extern __shared__ __align__(1024) char smem[];
    const unsigned sbase = smem_u32(smem);
    const int tid  = threadIdx.x;
    const int wid  = tid >> 5;
    const int lane = tid & 31;
    const int K2 = 2 * K;

    const int row0 = blockIdx.y * 64;
    const int col0 = blockIdx.x * 128;

    const int m0 = (wid & 1) * 32;
    const int n0 = (wid >> 1) * 32;

    float acc[2][4][4];
#pragma unroll
    for (int i = 0; i < 2; i++)
#pragma unroll
        for (int j = 0; j < 4; j++)
#pragma unroll
            for (int q = 0; q < 4; q++) acc[i][j][q] = 0.0f;

    const int arow = tid >> 2;
    const int ac0  = (tid & 3) * 2;
    const int brow = tid >> 1;
    const int bc0  = (tid & 1) * 4;
    const __nv_bfloat16* agp = A + (size_t)(row0 + arow) * K2;
    const __nv_bfloat16* bgp = B + (size_t)(col0 + brow) * K2;

    const int NC = K / 64;

#define ISSUE_TILE(ct, s) do {                                              \
        const unsigned sb_ = sbase + (unsigned)(s) * 49152u;                \
        const int kb_ = (ct) * 64;                                          \
        _Pragma("unroll")                                                   \
        for (int i_ = 0; i_ < 2; i_++) {                                    \
            const int c_ = ac0 + i_;                                        \
            const unsigned off_ = (unsigned)(arow * 128 + ((c_ ^ (arow & 7)) << 4)); \
            cpasync16(sb_ + off_,         agp + kb_ + c_ * 8);              \
            cpasync16(sb_ + 8192u + off_, agp + K + kb_ + c_ * 8);          \
        }                                                                   \
        _Pragma("unroll")                                                   \
        for (int i_ = 0; i_ < 4; i_++) {                                    \
            const int c_ = bc0 + i_;                                        \
            const unsigned off_ = (unsigned)(brow * 128 + ((c_ ^ (brow & 7)) << 4)); \
            cpasync16(sb_ + 16384u + off_, bgp + kb_ + c_ * 8);             \
            cpasync16(sb_ + 32768u + off_, bgp + K + kb_ + c_ * 8);         \
        }                                                                   \
    } while (0)

    ISSUE_TILE(0, 0);
    cp_commit();
    if (NC > 1) { ISSUE_TILE(1, 1); }
    cp_commit();

    for (int c = 0; c < NC; c++) {
        if (c + 1 < NC) cp_wait1(); else cp_wait0();
        __syncthreads();

        const unsigned sAhi = sbase + (unsigned)(c & 1) * 49152u;
        const unsigned sAlo = sAhi + 8192u;
        const unsigned sBhi = sAhi + 16384u;
        const unsigned sBlo = sAhi + 32768u;

#pragma unroll
        for (int kk4 = 0; kk4 < 4; kk4++) {
            const int cb = kk4 * 2;
            unsigned ahi[2][4], alo[2][4], bfr[2][4];
            unsigned boff[2];
#pragma unroll
            for (int mt = 0; mt < 2; mt++) {
                const int r = m0 + mt * 16 + (lane & 15);
                const int ch = cb + (lane >> 4);
                const unsigned off = (unsigned)(r * 128 + ((ch ^ (r & 7)) << 4));
                ldsm4(ahi[mt], sAhi + off);
                ldsm4(alo[mt], sAlo + off);
            }
#pragma unroll
            for (int jp = 0; jp < 2; jp++) {
                const int rn = n0 + jp * 16 + ((lane >> 4) << 3) + (lane & 7);
                const int ch = cb + ((lane >> 3) & 1);
                boff[jp] = (unsigned)(rn * 128 + ((ch ^ (rn & 7)) << 4));
                ldsm4(bfr[jp], sBhi + boff[jp]);
            }
#pragma unroll
            for (int mt = 0; mt < 2; mt++)
#pragma unroll
                for (int nt = 0; nt < 4; nt++) {
                    mma16816(acc[mt][nt], ahi[mt],
                             bfr[nt >> 1][(nt & 1) * 2],
                             bfr[nt >> 1][(nt & 1) * 2 + 1]);
                    mma16816(acc[mt][nt], alo[mt],
                             bfr[nt >> 1][(nt & 1) * 2],
                             bfr[nt >> 1][(nt & 1) * 2 + 1]);
                }
#pragma unroll
            for (int jp = 0; jp < 2; jp++)
                ldsm4(bfr[jp], sBlo + boff[jp]);
#pragma unroll
            for (int mt = 0; mt < 2; mt++)
#pragma unroll
                for (int nt = 0; nt < 4; nt++)
                    mma16816(acc[mt][nt], ahi[mt],
                             bfr[nt >> 1][(nt & 1) * 2],
                             bfr[nt >> 1][(nt & 1) * 2 + 1]);
        }
        __syncthreads();
        if (c + 2 < NC) {
            ISSUE_TILE(c + 2, c & 1);
            cp_commit();
        }
    }
#undef ISSUE_TILE

    const int g  = lane >> 2;
    const int t4 = lane & 3;
#pragma unroll
    for (int nt = 0; nt < 4; nt++) {
        const int col = col0 + n0 + nt * 8 + 2 * t4;
        const float b0 = bias[col];
        const float b1 = bias[col + 1];
#pragma unroll
        for (int mt = 0; mt < 2; mt++) {
            const int rtop = row0 + m0 + mt * 16 + g;
#pragma unroll
            for (int half = 0; half < 2; half++) {
                const int r = rtop + half * 8;
                float v0 = acc[mt][nt][half * 2 + 0] + b0;
                float v1 = acc[mt][nt][half * 2 + 1] + b1;
                if (ACT == 1) { v0 = sigmoidf_(v0); v1 = sigmoidf_(v1); }
                float* orow = Cf + (size_t)r * N;
                if (RESID) {
                    float2 old = *(float2*)(orow + col);
                    v0 += old.x; v1 += old.y;
                }
                *(float2*)(orow + col) = make_float2(v0, v1);
            }
        }
    }
}

// ================= 2-pass fp16 GEMM, tile 64x128, 3 stages, 2 CTAs/SM ===========
// C = epilogue(Ahi·B + Alo·B + bias). Stage = Ahi8K+Alo8K+B16K = 32KB x 3 = 96KB.
#define GEMM2_SMEM_BYTES (3 * 32768)

template<int ACT, bool RESID, bool SPLIT>
__global__ __launch_bounds__(256, 2) void tc_gemm2(
    const __half* __restrict__ A, const __half* __restrict__ B,
    const float* __restrict__ bias, float* __restrict__ Cf,
    __half* __restrict__ Cs, int K, int N)
{
    extern __shared__ __align__(1024) char smem[];
    const unsigned sbase = smem_u32(smem);
    const int tid  = threadIdx.x;
    const int wid  = tid >> 5;
    const int lane = tid & 31;
    const int K2 = 2 * K;

    const int row0 = blockIdx.y * 64;
    const int col0 = blockIdx.x * 128;

    const int m0 = (wid & 1) * 32;
    const int n0 = (wid >> 1) * 32;

    float acc[2][4][4];
#pragma unroll
    for (int i = 0; i < 2; i++)
#pragma unroll
        for (int j = 0; j < 4; j++)
#pragma unroll
            for (int q = 0; q < 4; q++) acc[i][j][q] = 0.0f;

    const int arow = tid >> 2;
    const int ac0  = (tid & 3) * 2;
    const int brow = tid >> 1;
    const int bc0  = (tid & 1) * 4;
    const __half* agp = A + (size_t)(row0 + arow) * K2;
    const __half* bgp = B + (size_t)(col0 + brow) * K;

    const int NC = K / 64;

#define ISSUE_TILE2(ct, s) do {                                             \
        const unsigned sb_ = sbase + (unsigned)(s) * 32768u;                \
        const int kb_ = (ct) * 64;                                          \
        _Pragma("unroll")                                                   \
        for (int i_ = 0; i_ < 2; i_++) {                                    \
            const int c_ = ac0 + i_;                                        \
            const unsigned off_ = (unsigned)(arow * 128 + ((c_ ^ (arow & 7)) << 4)); \
            cpasync16(sb_ + off_,         agp + kb_ + c_ * 8);              \
            cpasync16(sb_ + 8192u + off_, agp + K + kb_ + c_ * 8);          \
        }                                                                   \
        _Pragma("unroll")                                                   \
        for (int i_ = 0; i_ < 4; i_++) {                                    \
            const int c_ = bc0 + i_;                                        \
            const unsigned off_ = (unsigned)(brow * 128 + ((c_ ^ (brow & 7)) << 4)); \
            cpasync16(sb_ + 16384u + off_, bgp + kb_ + c_ * 8);             \
        }                                                                   \
    } while (0)

    ISSUE_TILE2(0, 0);
    cp_commit();
    if (NC > 1) { ISSUE_TILE2(1, 1); }
    cp_commit();

    int sidx = 0;
    for (int c = 0; c < NC; c++) {
        if (c + 1 < NC) cp_wait1(); else cp_wait0();
        __syncthreads();

        if (c + 2 < NC) {
            int fs = sidx + 2; if (fs >= 3) fs -= 3;
            ISSUE_TILE2(c + 2, fs);
            cp_commit();
        }

        const unsigned sAhi = sbase + (unsigned)sidx * 32768u;
        const unsigned sAlo = sAhi + 8192u;
        const unsigned sB   = sAhi + 16384u;

#pragma unroll
        for (int kk4 = 0; kk4 < 4; kk4++) {
            const int cb = kk4 * 2;
            unsigned ahi[2][4], alo[2][4], bfr[2][4];
#pragma unroll
            for (int mt = 0; mt < 2; mt++) {
                const int r = m0 + mt * 16 + (lane & 15);
                const int ch = cb + (lane >> 4);
                const unsigned off = (unsigned)(r * 128 + ((ch ^ (r & 7)) << 4));
                ldsm4(ahi[mt], sAhi + off);
                ldsm4(alo[mt], sAlo + off);
            }
#pragma unroll
            for (int jp = 0; jp < 2; jp++) {
                const int rn = n0 + jp * 16 + ((lane >> 4) << 3) + (lane & 7);
                const int ch = cb + ((lane >> 3) & 1);
                ldsm4(bfr[jp], sB + (unsigned)(rn * 128 + ((ch ^ (rn & 7)) << 4)));
            }
#pragma unroll
            for (int mt = 0; mt < 2; mt++)
#pragma unroll
                for (int nt = 0; nt < 4; nt++) {
                    mma16816h(acc[mt][nt], ahi[mt],
                              bfr[nt >> 1][(nt & 1) * 2],
                              bfr[nt >> 1][(nt & 1) * 2 + 1]);
                    mma16816h(acc[mt][nt], alo[mt],
                              bfr[nt >> 1][(nt & 1) * 2],
                              bfr[nt >> 1][(nt & 1) * 2 + 1]);
                }
        }
        sidx++; if (sidx >= 3) sidx -= 3;
    }
#undef ISSUE_TILE2

    const int g  = lane >> 2;
    const int t4 = lane & 3;
#pragma unroll
    for (int nt = 0; nt < 4; nt++) {
        const int col = col0 + n0 + nt * 8 + 2 * t4;
        const float b0 = bias[col];
        const float b1 = bias[col + 1];
#pragma unroll
        for (int mt = 0; mt < 2; mt++) {
            const int rtop = row0 + m0 + mt * 16 + g;
#pragma unroll
            for (int half = 0; half < 2; half++) {
                const int r = rtop + half * 8;
                float v0 = acc[mt][nt][half * 2 + 0] + b0;
                float v1 = acc[mt][nt][half * 2 + 1] + b1;
                if (ACT == 1) { v0 = sigmoidf_(v0); v1 = sigmoidf_(v1); }
                else if (ACT == 2) { v0 = v0 * sigmoidf_(v0); v1 = v1 * sigmoidf_(v1); }
                if (SPLIT) {
                    __half* orow = Cs + (size_t)r * (2 * N);
                    __half h0, l0, h1, l1;
                    split_fp16(v0, h0, l0);
                    split_fp16(v1, h1, l1);
                    *(__half2*)(orow + col)     = __halves2half2(h0, h1);
                    *(__half2*)(orow + N + col) = __halves2half2(l0, l1);
                } else {
                    float* orow = Cf + (size_t)r * N;
                    if (RESID) {
                        float2 old = *(float2*)(orow + col);
                        v0 += old.x; v1 += old.y;
                    }
                    *(float2*)(orow + col) = make_float2(v0, v1);
                }
            }
        }
    }
}

// ========== batched prep: ALL weights + node activations in ONE launch ==========
// type: 0=in 1=gate 2=out 3=ff1 4=ff2 (all fp16 1-plane); z==5NL: proj (bf16 2-plane)
__global__ __launch_bounds__(256) void prep_all(
    const float* __restrict__ node,
    const float* __restrict__ W_proj, const float* __restrict__ W_in,
    const float* __restrict__ W_gate, const float* __restrict__ W_out,
    const float* __restrict__ W_ff1,  const float* __restrict__ W_ff2,
    __nv_bfloat16* __restrict__ o_node, __nv_bfloat16* __restrict__ o_proj,
    __half* __restrict__ o_in, __half* __restrict__ o_gate,
    __half* __restrict__ o_out, __half* __restrict__ o_ff1,
    __half* __restrict__ o_ff2)
{
    const int z = blockIdx.z;
    const int nidx = blockIdx.x * 32 + (threadIdx.x & 31);
    const int k0 = blockIdx.y * 128 + (threadIdx.x >> 5) * 16;

    if (z == 5 * NL + 1) {
        if (nidx >= LSEQ || k0 >= DIN) return;
        const float* xr = node + (size_t)nidx * DIN;
        __nv_bfloat16* orow = o_node + (size_t)nidx * 2 * DIN;
#pragma unroll
        for (int i = 0; i < 16; i++) {
            __nv_bfloat16 hi, lo;
            split_bf16(xr[k0 + i], hi, lo);
            orow[k0 + i]       = hi;
            orow[DIN + k0 + i] = lo;
        }
        return;
    }

    const float* W; int K, N;
    if (z == 5 * NL) { W = W_proj; K = DIN; N = DD; }
    else {
        const int l = z / 5, t = z - l * 5;
        switch (t) {
            case 0: W = W_in   + (size_t)l * DD * DD; K = DD; N = DD; break;
            case 1: W = W_gate + (size_t)l * DD * DD; K = DD; N = DD; break;
            case 2: W = W_out  + (size_t)l * DD * DD; K = DD; N = DD; break;
            case 3: W = W_ff1  + (size_t)l * DD * D2; K = DD; N = D2; break;
            default:W = W_ff2  + (size_t)l * D2 * DD; K = D2; N = DD; break;
        }
    }
    if (nidx >= N || k0 >= K) return;

    if (z < 5 * NL) {
        const int l = z / 5, t = z - l * 5;
        __half* orow;
        if (t == 0)      orow = o_in   + (size_t)l * DD * DD + (size_t)nidx * DD;
        else if (t == 1) orow = o_gate + (size_t)l * DD * DD + (size_t)nidx * DD;
        else if (t == 2) orow = o_out  + (size_t)l * DD * DD + (size_t)nidx * DD;
        else if (t == 3) orow = o_ff1  + (size_t)l * D2 * DD + (size_t)nidx * DD;
        else             orow = o_ff2  + (size_t)l * DD * D2 + (size_t)nidx * D2;
#pragma unroll
        for (int i = 0; i < 16; i++)
            orow[k0 + i] = __float2half_rn(W[(size_t)(k0 + i) * N + nidx]);
    } else {
        __nv_bfloat16* orow = o_proj + (size_t)nidx * 2 * K;
#pragma unroll
        for (int i = 0; i < 16; i++) {
            __nv_bfloat16 hi, lo;
            split_bf16(W[(size_t)(k0 + i) * N + nidx], hi, lo);
            orow[k0 + i]     = hi;
            orow[K + k0 + i] = lo;
        }
    }
}

// ================= LayerNorm -> split fp16 [L, 2*DD] ============================
__global__ __launch_bounds__(256) void ln_split_f16_kernel(
    const float* __restrict__ x, const float* __restrict__ gam,
    const float* __restrict__ bet, __half* __restrict__ out)
{
    __shared__ float red[8];
    __shared__ float bcast;
    const int tid = threadIdx.x;
    const float* xr = x + (size_t)blockIdx.x * DD;

    float v0 = xr[tid], v1 = xr[tid + 256], v2 = xr[tid + 512];
    float sum = v0 + v1 + v2;
#pragma unroll
    for (int o = 16; o > 0; o >>= 1) sum += __shfl_xor_sync(0xffffffffu, sum, o);
    if ((tid & 31) == 0) red[tid >> 5] = sum;
    __syncthreads();
    if (tid == 0) {
        float t = 0.f;
#pragma unroll
        for (int i = 0; i < 8; i++) t += red[i];
        bcast = t * (1.0f / DD);
    }
    __syncthreads();
    const float mu = bcast;
    float d0 = v0 - mu, d1 = v1 - mu, d2 = v2 - mu;
    float sq = d0 * d0 + d1 * d1 + d2 * d2;
#pragma unroll
    for (int o = 16; o > 0; o >>= 1) sq += __shfl_xor_sync(0xffffffffu, sq, o);
    __syncthreads();
    if ((tid & 31) == 0) red[tid >> 5] = sq;
    __syncthreads();
    if (tid == 0) {
        float t = 0.f;
#pragma unroll
        for (int i = 0; i < 8; i++) t += red[i];
        bcast = rsqrtf(t * (1.0f / DD) + 1e-5f);
    }
    __syncthreads();
    const float inv = bcast;

    __half* orow = out + (size_t)blockIdx.x * (2 * DD);
#pragma unroll
    for (int q = 0; q < 3; q++) {
        const int j = tid + q * 256;
        const float dv = (q == 0 ? d0 : (q == 1 ? d1 : d2));
        float v = dv * inv * gam[j] + bet[j];
        __half hi, lo;
        split_fp16(v, hi, lo);
        orow[j]      = hi;
        orow[DD + j] = lo;
    }
}

// ================= final LayerNorm (fp32 out) ===================================
__global__ __launch_bounds__(256) void ln_final_kernel(
    const float* __restrict__ x, const float* __restrict__ gam,
    const float* __restrict__ bet, float* __restrict__ out)
{
    __shared__ float red[8];
    __shared__ float bcast;
    const int tid = threadIdx.x;
    const float* xr = x + (size_t)blockIdx.x * DD;

    float v0 = xr[tid], v1 = xr[tid + 256], v2 = xr[tid + 512];
    float sum = v0 + v1 + v2;
#pragma unroll
    for (int o = 16; o > 0; o >>= 1) sum += __shfl_xor_sync(0xffffffffu, sum, o);
    if ((tid & 31) == 0) red[tid >> 5] = sum;
    __syncthreads();
    if (tid == 0) {
        float t = 0.f;
#pragma unroll
        for (int i = 0; i < 8; i++) t += red[i];
        bcast = t * (1.0f / DD);
    }
    __syncthreads();
    const float mu = bcast;
    float d0 = v0 - mu, d1 = v1 - mu, d2 = v2 - mu;
    float sq = d0 * d0 + d1 * d1 + d2 * d2;
#pragma unroll
    for (int o = 16; o > 0; o >>= 1) sq += __shfl_xor_sync(0xffffffffu, sq, o);
    __syncthreads();
    if ((tid & 31) == 0) red[tid >> 5] = sq;
    __syncthreads();
    if (tid == 0) {
        float t = 0.f;
#pragma unroll
        for (int i = 0; i < 8; i++) t += red[i];
        bcast = rsqrtf(t * (1.0f / DD) + 1e-5f);
    }
    __syncthreads();
    const float inv = bcast;

    float* orow = out + (size_t)blockIdx.x * DD;
    orow[tid]       = d0 * inv * gam[tid]       + bet[tid];
    orow[tid + 256] = d1 * inv * gam[tid + 256] + bet[tid + 256];
    orow[tid + 512] = d2 * inv * gam[tid + 512] + bet[tid + 512];
}

// ================= scan kernels =================================================
__global__ __launch_bounds__(256) void scan_chunk_kernel(
    const float* __restrict__ u, const float* __restrict__ dlogit,
    float* __restrict__ Sout)
{
    const int d = blockIdx.x * 256 + threadIdx.x;
    const int c = blockIdx.y;
    const float decay = sigmoidf_(dlogit[d]);
    const float* p = u + ((size_t)c * CLEN) * DD + d;
    float s = 0.0f;
#pragma unroll 8
    for (int t = 0; t < CLEN; t++) s = fmaf(decay, s, p[(size_t)t * DD]);
    Sout[c * DD + d] = s;
}

__global__ __launch_bounds__(768) void scan_carry_kernel(
    const float* __restrict__ Sin, const float* __restrict__ dlogit,
    float* __restrict__ carry)
{
    const int d = threadIdx.x;
    const float decay = sigmoidf_(dlogit[d]);
    float A = decay;
#pragma unroll
    for (int i = 0; i < 7; i++) A = A * A;   // decay^128
    float c = 0.0f;
    for (int k = 0; k < NCHUNK; k++) {
        carry[k * DD + d] = c;
        c = fmaf(A, c, Sin[k * DD + d]);
    }
}

// re-scan with carry, gate-multiply, emit split fp16 [L, 2*DD]
__global__ __launch_bounds__(256) void scan_apply_split_f16_kernel(
    const float* __restrict__ u, const float* __restrict__ gate,
    const float* __restrict__ dlogit, const float* __restrict__ carry,
    __half* __restrict__ out)
{
    const int d = blockIdx.x * 256 + threadIdx.x;
    const int c = blockIdx.y;
    const float decay = sigmoidf_(dlogit[d]);
    const size_t base = ((size_t)c * CLEN) * DD + d;
    float s = carry[c * DD + d];
#pragma unroll 4
    for (int t = 0; t < CLEN; t++) {
        const size_t idx = base + (size_t)t * DD;
        s = fmaf(decay, s, u[idx]);
        float v = s * gate[idx];
        __half hi, lo;
        split_fp16(v, hi, lo);
        __half* orow = out + (size_t)(c * CLEN + t) * (2 * DD);
        orow[d]      = hi;
        orow[DD + d] = lo;
    }
}

// ================= host =========================================================
extern "C" void kernel_launch(void* const* d_in, const int* in_sizes, int n_in,
                              void* d_out, int out_size)
{
    const float* node    = (const float*)d_in[0];
    const float* W_proj  = (const float*)d_in[1];
    const float* b_proj  = (const float*)d_in[2];
    const float* ln_s_g  = (const float*)d_in[3];
    const float* ln_s_b  = (const float*)d_in[4];
    const float* W_in    = (const float*)d_in[5];
    const float* b_in    = (const float*)d_in[6];
    const float* W_gate  = (const float*)d_in[7];
    const float* b_gate  = (const float*)d_in[8];
    const float* W_out   = (const float*)d_in[9];
    const float* b_out   = (const float*)d_in[10];
    const float* dlogit  = (const float*)d_in[11];
    const float* ln_f_g  = (const float*)d_in[12];
    const float* ln_f_b  = (const float*)d_in[13];
    const float* W_ff1   = (const float*)d_in[14];
    const float* b_ff1   = (const float*)d_in[15];
    const float* W_ff2   = (const float*)d_in[16];
    const float* b_ff2   = (const float*)d_in[17];
    const float* ln_o_g  = (const float*)d_in[18];
    const float* ln_o_b  = (const float*)d_in[19];

    float *x, *u, *gate, *S, *carry;
    __nv_bfloat16 *a_node, *w_proj;
    __half *a_h2, *a_sf, *a_hf, *a_t, *w_i, *w_gt, *w_ot, *w_f1, *w_f2;
    cudaGetSymbolAddress((void**)&x,     g_x);
    cudaGetSymbolAddress((void**)&u,     g_u);
    cudaGetSymbolAddress((void**)&gate,  g_gate);
    cudaGetSymbolAddress((void**)&S,     g_S);
    cudaGetSymbolAddress((void**)&carry, g_carry);
    cudaGetSymbolAddress((void**)&a_node, ab_node);
    cudaGetSymbolAddress((void**)&a_h2,   ah_h2);
    cudaGetSymbolAddress((void**)&a_sf,   ah_s);
    cudaGetSymbolAddress((void**)&a_hf,   ah_hf);
    cudaGetSymbolAddress((void**)&a_t,    ah_t);
    cudaGetSymbolAddress((void**)&w_proj, wb_proj);
    cudaGetSymbolAddress((void**)&w_i,    wh_in);
    cudaGetSymbolAddress((void**)&w_gt,   wh_gate);
    cudaGetSymbolAddress((void**)&w_ot,   wh_out);
    cudaGetSymbolAddress((void**)&w_f1,   wh_ff1);
    cudaGetSymbolAddress((void**)&w_f2,   wh_ff2);

    cudaFuncSetAttribute(tc_gemm<0, false>, cudaFuncAttributeMaxDynamicSharedMemorySize, GEMM_SMEM_BYTES);
    cudaFuncSetAttribute(tc_gemm2<0, false, false>, cudaFuncAttributeMaxDynamicSharedMemorySize, GEMM2_SMEM_BYTES);
    cudaFuncSetAttribute(tc_gemm2<1, false, false>, cudaFuncAttributeMaxDynamicSharedMemorySize, GEMM2_SMEM_BYTES);
    cudaFuncSetAttribute(tc_gemm2<2, false, true >, cudaFuncAttributeMaxDynamicSharedMemorySize, GEMM2_SMEM_BYTES);
    cudaFuncSetAttribute(tc_gemm2<0, true,  false>, cudaFuncAttributeMaxDynamicSharedMemorySize, GEMM2_SMEM_BYTES);

    const dim3 blk(256);
    const dim3 gScan(DD / 256, NCHUNK);
    const dim3 gG6  (DD / 128, LSEQ / 64);    // 64-row tiles, N=768
    const dim3 gG12 (D2 / 128, LSEQ / 64);    // 64-row tiles, N=1536

    // ---- launch 0: ALL prep (weights + node) ----
    prep_all<<<dim3(512, 12, 5 * NL + 2), blk>>>(
        node, W_proj, W_in, W_gate, W_out, W_ff1, W_ff2,
        a_node, w_proj, w_i, w_gt, w_ot, w_f1, w_f2);

    // ---- launch 1: x = node @ W_proj + b_proj (3-pass bf16) ----
    tc_gemm<0, false><<<gG6, blk, GEMM_SMEM_BYTES>>>(
        a_node, w_proj, b_proj, x, DIN, DD);

    for (int l = 0; l < NL; l++) {
        const size_t vo = (size_t)l * DD;
        const size_t v1 = (size_t)l * D2;
        const __half* wi = w_i  + (size_t)l * DD * DD;
        const __half* wg = w_gt + (size_t)l * DD * DD;
        const __half* wo = w_ot + (size_t)l * DD * DD;
        const __half* w1 = w_f1 + (size_t)l * D2 * DD;
        const __half* w2 = w_f2 + (size_t)l * DD * D2;

        ln_split_f16_kernel<<<LSEQ, blk>>>(x, ln_s_g + vo, ln_s_b + vo, a_h2);
        tc_gemm2<0, false, false><<<gG6, blk, GEMM2_SMEM_BYTES>>>(
            a_h2, wi, b_in + vo, u, nullptr, DD, DD);
        tc_gemm2<1, false, false><<<gG6, blk, GEMM2_SMEM_BYTES>>>(
            a_h2, wg, b_gate + vo, gate, nullptr, DD, DD);
        scan_chunk_kernel<<<gScan, blk>>>(u, dlogit + vo, S);
        scan_carry_kernel<<<1, DD>>>(S, dlogit + vo, carry);
        scan_apply_split_f16_kernel<<<gScan, blk>>>(u, gate, dlogit + vo, carry, a_sf);
        tc_gemm2<0, true, false><<<gG6, blk, GEMM2_SMEM_BYTES>>>(
            a_sf, wo, b_out + vo, x, nullptr, DD, DD);
        ln_split_f16_kernel<<<LSEQ, blk>>>(x, ln_f_g + vo, ln_f_b + vo, a_hf);
        tc_gemm2<2, false, true><<<gG12, blk, GEMM2_SMEM_BYTES>>>(
            a_hf, w1, b_ff1 + v1, nullptr, a_t, DD, D2);
        tc_gemm2<0, true, false><<<gG6, blk, GEMM2_SMEM_BYTES>>>(
            a_t, w2, b_ff2 + vo, x, nullptr, D2, DD);
    }

    ln_final_kernel<<<LSEQ, blk>>>(x, ln_o_g, ln_o_b, (float*)d_out);
}

// round 12
// speedup vs baseline: 4.4311x; 1.3291x over previous
#include <cuda_runtime.h>
#include <cuda_bf16.h>
#include <cuda_fp16.h>
#include <math.h>

#define LSEQ 16384
#define DIN  256
#define DD   768
#define D2   1536
#define NL   8
#define NCHUNK 128
#define CLEN   128

// ---------------- fp32 scratch ----------------
__device__ float g_x[(size_t)LSEQ * DD];
__device__ float g_u[(size_t)LSEQ * DD];
__device__ float g_gate[(size_t)LSEQ * DD];
__device__ float g_S[NCHUNK * DD];
__device__ float g_carry[NCHUNK * DD];

// ---- bf16 split activations [hi|lo] stride 2K (proj only) ----
__device__ __nv_bfloat16 ab_node[(size_t)LSEQ * 2 * DIN];
// ---- fp16 single-plane activations ----
__device__ __half ah_h2[(size_t)LSEQ * DD];   // ln_s output (in + gate GEMMs)
__device__ __half ah_s [(size_t)LSEQ * DD];   // scan output (out GEMM)
__device__ __half ah_hf[(size_t)LSEQ * DD];   // ln_f output (ff1)
__device__ __half ah_t [(size_t)LSEQ * D2];   // silu(ff1) output (ff2)

// ---- bf16 split weights [N rows, 2K] [hi|lo] (proj only) ----
__device__ __nv_bfloat16 wb_proj[(size_t)DD * 2 * DIN];
// ---- fp16 single-plane weights [N rows, K] ----
__device__ __half wh_in  [(size_t)NL * DD * DD];
__device__ __half wh_gate[(size_t)NL * DD * DD];
__device__ __half wh_out [(size_t)NL * DD * DD];
__device__ __half wh_ff1 [(size_t)NL * D2 * DD];
__device__ __half wh_ff2 [(size_t)NL * DD * D2];

// ================= helpers =================
__device__ __forceinline__ float sigmoidf_(float z) {
    return 1.0f / (1.0f + __expf(-z));
}

__device__ __forceinline__ unsigned smem_u32(const void* p) {
    unsigned a;
    asm("{ .reg .u64 t; cvta.to.shared.u64 t, %1; cvt.u32.u64 %0, t; }"
        : "=r"(a) : "l"(p));
    return a;
}

__device__ __forceinline__ void cpasync16(unsigned s, const void* g) {
    asm volatile("cp.async.cg.shared.global [%0], [%1], 16;"
                 :: "r"(s), "l"(g) : "memory");
}
__device__ __forceinline__ void cp_commit() {
    asm volatile("cp.async.commit_group;" ::: "memory");
}
__device__ __forceinline__ void cp_wait1() {
    asm volatile("cp.async.wait_group 1;" ::: "memory");
}
__device__ __forceinline__ void cp_wait0() {
    asm volatile("cp.async.wait_group 0;" ::: "memory");
}

__device__ __forceinline__ void ldsm4(unsigned* r, unsigned addr) {
    asm volatile("ldmatrix.sync.aligned.m8n8.x4.shared.b16 {%0,%1,%2,%3}, [%4];"
                 : "=r"(r[0]), "=r"(r[1]), "=r"(r[2]), "=r"(r[3]) : "r"(addr));
}

__device__ __forceinline__ void mma16816(float* d, const unsigned* a,
                                         unsigned b0, unsigned b1) {
    asm volatile(
        "mma.sync.aligned.m16n8k16.row.col.f32.bf16.bf16.f32 "
        "{%0,%1,%2,%3}, {%4,%5,%6,%7}, {%8,%9}, {%0,%1,%2,%3};"
        : "+f"(d[0]), "+f"(d[1]), "+f"(d[2]), "+f"(d[3])
        : "r"(a[0]), "r"(a[1]), "r"(a[2]), "r"(a[3]), "r"(b0), "r"(b1));
}

__device__ __forceinline__ void mma16816h(float* d, const unsigned* a,
                                          unsigned b0, unsigned b1) {
    asm volatile(
        "mma.sync.aligned.m16n8k16.row.col.f32.f16.f16.f32 "
        "{%0,%1,%2,%3}, {%4,%5,%6,%7}, {%8,%9}, {%0,%1,%2,%3};"
        : "+f"(d[0]), "+f"(d[1]), "+f"(d[2]), "+f"(d[3])
        : "r"(a[0]), "r"(a[1]), "r"(a[2]), "r"(a[3]), "r"(b0), "r"(b1));
}

__device__ __forceinline__ void split_bf16(float v, __nv_bfloat16& hi, __nv_bfloat16& lo) {
    hi = __float2bfloat16(v);
    lo = __float2bfloat16(v - __bfloat162float(hi));
}

// ================= 3-pass bf16 GEMM, tile 64x128, 2 CTAs/SM (proj only) =========
#define GEMM_SMEM_BYTES (2 * 49152)

template<int ACT, bool RESID>
__global__ __launch_bounds__(256, 2) void tc_gemm(
    const __nv_bfloat16* __restrict__ A, const __nv_bfloat16* __restrict__ B,
    const float* __restrict__ bias, float* __restrict__ Cf, int K, int N)
{
    extern __shared__ __align__(1024) char smem[];
    const unsigned sbase = smem_u32(smem);
    const int tid  = threadIdx.x;
    const int wid  = tid >> 5;
    const int lane = tid & 31;
    const int K2 = 2 * K;

    const int row0 = blockIdx.y * 64;
    const int col0 = blockIdx.x * 128;

    const int m0 = (wid & 1) * 32;
    const int n0 = (wid >> 1) * 32;

    float acc[2][4][4];
#pragma unroll
    for (int i = 0; i < 2; i++)
#pragma unroll
        for (int j = 0; j < 4; j++)
#pragma unroll
            for (int q = 0; q < 4; q++) acc[i][j][q] = 0.0f;

    const int arow = tid >> 2;
    const int ac0  = (tid & 3) * 2;
    const int brow = tid >> 1;
    const int bc0  = (tid & 1) * 4;
    const __nv_bfloat16* agp = A + (size_t)(row0 + arow) * K2;
    const __nv_bfloat16* bgp = B + (size_t)(col0 + brow) * K2;

    const int NC = K / 64;

#define ISSUE_TILE(ct, s) do {                                              \
        const unsigned sb_ = sbase + (unsigned)(s) * 49152u;                \
        const int kb_ = (ct) * 64;                                          \
        _Pragma("unroll")                                                   \
        for (int i_ = 0; i_ < 2; i_++) {                                    \
            const int c_ = ac0 + i_;                                        \
            const unsigned off_ = (unsigned)(arow * 128 + ((c_ ^ (arow & 7)) << 4)); \
            cpasync16(sb_ + off_,         agp + kb_ + c_ * 8);              \
            cpasync16(sb_ + 8192u + off_, agp + K + kb_ + c_ * 8);          \
        }                                                                   \
        _Pragma("unroll")                                                   \
        for (int i_ = 0; i_ < 4; i_++) {                                    \
            const int c_ = bc0 + i_;                                        \
            const unsigned off_ = (unsigned)(brow * 128 + ((c_ ^ (brow & 7)) << 4)); \
            cpasync16(sb_ + 16384u + off_, bgp + kb_ + c_ * 8);             \
            cpasync16(sb_ + 32768u + off_, bgp + K + kb_ + c_ * 8);         \
        }                                                                   \
    } while (0)

    ISSUE_TILE(0, 0);
    cp_commit();
    if (NC > 1) { ISSUE_TILE(1, 1); }
    cp_commit();

    for (int c = 0; c < NC; c++) {
        if (c + 1 < NC) cp_wait1(); else cp_wait0();
        __syncthreads();

        const unsigned sAhi = sbase + (unsigned)(c & 1) * 49152u;
        const unsigned sAlo = sAhi + 8192u;
        const unsigned sBhi = sAhi + 16384u;
        const unsigned sBlo = sAhi + 32768u;

#pragma unroll
        for (int kk4 = 0; kk4 < 4; kk4++) {
            const int cb = kk4 * 2;
            unsigned ahi[2][4], alo[2][4], bfr[2][4];
            unsigned boff[2];
#pragma unroll
            for (int mt = 0; mt < 2; mt++) {
                const int r = m0 + mt * 16 + (lane & 15);
                const int ch = cb + (lane >> 4);
                const unsigned off = (unsigned)(r * 128 + ((ch ^ (r & 7)) << 4));
                ldsm4(ahi[mt], sAhi + off);
                ldsm4(alo[mt], sAlo + off);
            }
#pragma unroll
            for (int jp = 0; jp < 2; jp++) {
                const int rn = n0 + jp * 16 + ((lane >> 4) << 3) + (lane & 7);
                const int ch = cb + ((lane >> 3) & 1);
                boff[jp] = (unsigned)(rn * 128 + ((ch ^ (rn & 7)) << 4));
                ldsm4(bfr[jp], sBhi + boff[jp]);
            }
#pragma unroll
            for (int mt = 0; mt < 2; mt++)
#pragma unroll
                for (int nt = 0; nt < 4; nt++) {
                    mma16816(acc[mt][nt], ahi[mt],
                             bfr[nt >> 1][(nt & 1) * 2],
                             bfr[nt >> 1][(nt & 1) * 2 + 1]);
                    mma16816(acc[mt][nt], alo[mt],
                             bfr[nt >> 1][(nt & 1) * 2],
                             bfr[nt >> 1][(nt & 1) * 2 + 1]);
                }
#pragma unroll
            for (int jp = 0; jp < 2; jp++)
                ldsm4(bfr[jp], sBlo + boff[jp]);
#pragma unroll
            for (int mt = 0; mt < 2; mt++)
#pragma unroll
                for (int nt = 0; nt < 4; nt++)
                    mma16816(acc[mt][nt], ahi[mt],
                             bfr[nt >> 1][(nt & 1) * 2],
                             bfr[nt >> 1][(nt & 1) * 2 + 1]);
        }
        __syncthreads();
        if (c + 2 < NC) {
            ISSUE_TILE(c + 2, c & 1);
            cp_commit();
        }
    }
#undef ISSUE_TILE

    const int g  = lane >> 2;
    const int t4 = lane & 3;
#pragma unroll
    for (int nt = 0; nt < 4; nt++) {
        const int col = col0 + n0 + nt * 8 + 2 * t4;
        const float b0 = bias[col];
        const float b1 = bias[col + 1];
#pragma unroll
        for (int mt = 0; mt < 2; mt++) {
            const int rtop = row0 + m0 + mt * 16 + g;
#pragma unroll
            for (int half = 0; half < 2; half++) {
                const int r = rtop + half * 8;
                float v0 = acc[mt][nt][half * 2 + 0] + b0;
                float v1 = acc[mt][nt][half * 2 + 1] + b1;
                if (ACT == 1) { v0 = sigmoidf_(v0); v1 = sigmoidf_(v1); }
                float* orow = Cf + (size_t)r * N;
                if (RESID) {
                    float2 old = *(float2*)(orow + col);
                    v0 += old.x; v1 += old.y;
                }
                *(float2*)(orow + col) = make_float2(v0, v1);
            }
        }
    }
}

// ================= 1-pass fp16 GEMM, tile 64x128, 3 stages, 2 CTAs/SM ===========
// C = epilogue(A·B^T + bias).  A [M,K] fp16 single-plane; B [N,K] fp16.
// Stage = A 8KB + B 16KB = 24KB x 3 = 72KB.  8 warps 2Mx4N, warp 32x32.
// ACT: 0 none, 1 sigmoid, 2 silu. RESID: Cf += v. HOUT: single fp16 to Cs.
#define GEMM1_SMEM_BYTES (3 * 24576)

template<int ACT, bool RESID, bool HOUT>
__global__ __launch_bounds__(256, 2) void tc_gemm1(
    const __half* __restrict__ A, const __half* __restrict__ B,
    const float* __restrict__ bias, float* __restrict__ Cf,
    __half* __restrict__ Cs, int K, int N)
{
    extern __shared__ __align__(1024) char smem[];
    const unsigned sbase = smem_u32(smem);
    const int tid  = threadIdx.x;
    const int wid  = tid >> 5;
    const int lane = tid & 31;

    const int row0 = blockIdx.y * 64;
    const int col0 = blockIdx.x * 128;

    const int m0 = (wid & 1) * 32;
    const int n0 = (wid >> 1) * 32;

    float acc[2][4][4];
#pragma unroll
    for (int i = 0; i < 2; i++)
#pragma unroll
        for (int j = 0; j < 4; j++)
#pragma unroll
            for (int q = 0; q < 4; q++) acc[i][j][q] = 0.0f;

    const int arow = tid >> 2;        // 0..63
    const int ac0  = (tid & 3) * 2;   // 2 chunks each
    const int brow = tid >> 1;        // 0..127
    const int bc0  = (tid & 1) * 4;   // 4 chunks each
    const __half* agp = A + (size_t)(row0 + arow) * K;
    const __half* bgp = B + (size_t)(col0 + brow) * K;

    const int NC = K / 64;

#define ISSUE_TILE1(ct, s) do {                                             \
        const unsigned sb_ = sbase + (unsigned)(s) * 24576u;                \
        const int kb_ = (ct) * 64;                                          \
        _Pragma("unroll")                                                   \
        for (int i_ = 0; i_ < 2; i_++) {                                    \
            const int c_ = ac0 + i_;                                        \
            const unsigned off_ = (unsigned)(arow * 128 + ((c_ ^ (arow & 7)) << 4)); \
            cpasync16(sb_ + off_, agp + kb_ + c_ * 8);                      \
        }                                                                   \
        _Pragma("unroll")                                                   \
        for (int i_ = 0; i_ < 4; i_++) {                                    \
            const int c_ = bc0 + i_;                                        \
            const unsigned off_ = (unsigned)(brow * 128 + ((c_ ^ (brow & 7)) << 4)); \
            cpasync16(sb_ + 8192u + off_, bgp + kb_ + c_ * 8);              \
        }                                                                   \
    } while (0)

    ISSUE_TILE1(0, 0);
    cp_commit();
    if (NC > 1) { ISSUE_TILE1(1, 1); }
    cp_commit();

    int sidx = 0;
    for (int c = 0; c < NC; c++) {
        if (c + 1 < NC) cp_wait1(); else cp_wait0();
        __syncthreads();

        if (c + 2 < NC) {
            int fs = sidx + 2; if (fs >= 3) fs -= 3;
            ISSUE_TILE1(c + 2, fs);
            cp_commit();
        }

        const unsigned sA = sbase + (unsigned)sidx * 24576u;
        const unsigned sB = sA + 8192u;

#pragma unroll
        for (int kk4 = 0; kk4 < 4; kk4++) {
            const int cb = kk4 * 2;
            unsigned afr[2][4], bfr[2][4];
#pragma unroll
            for (int mt = 0; mt < 2; mt++) {
                const int r = m0 + mt * 16 + (lane & 15);
                const int ch = cb + (lane >> 4);
                ldsm4(afr[mt], sA + (unsigned)(r * 128 + ((ch ^ (r & 7)) << 4)));
            }
#pragma unroll
            for (int jp = 0; jp < 2; jp++) {
                const int rn = n0 + jp * 16 + ((lane >> 4) << 3) + (lane & 7);
                const int ch = cb + ((lane >> 3) & 1);
                ldsm4(bfr[jp], sB + (unsigned)(rn * 128 + ((ch ^ (rn & 7)) << 4)));
            }
#pragma unroll
            for (int mt = 0; mt < 2; mt++)
#pragma unroll
                for (int nt = 0; nt < 4; nt++)
                    mma16816h(acc[mt][nt], afr[mt],
                              bfr[nt >> 1][(nt & 1) * 2],
                              bfr[nt >> 1][(nt & 1) * 2 + 1]);
        }
        sidx++; if (sidx >= 3) sidx -= 3;
    }
#undef ISSUE_TILE1

    const int g  = lane >> 2;
    const int t4 = lane & 3;
#pragma unroll
    for (int nt = 0; nt < 4; nt++) {
        const int col = col0 + n0 + nt * 8 + 2 * t4;
        const float b0 = bias[col];
        const float b1 = bias[col + 1];
#pragma unroll
        for (int mt = 0; mt < 2; mt++) {
            const int rtop = row0 + m0 + mt * 16 + g;
#pragma unroll
            for (int half = 0; half < 2; half++) {
                const int r = rtop + half * 8;
                float v0 = acc[mt][nt][half * 2 + 0] + b0;
                float v1 = acc[mt][nt][half * 2 + 1] + b1;
                if (ACT == 1) { v0 = sigmoidf_(v0); v1 = sigmoidf_(v1); }
                else if (ACT == 2) { v0 = v0 * sigmoidf_(v0); v1 = v1 * sigmoidf_(v1); }
                if (HOUT) {
                    __half* orow = Cs + (size_t)r * N;
                    *(__half2*)(orow + col) =
                        __halves2half2(__float2half_rn(v0), __float2half_rn(v1));
                } else {
                    float* orow = Cf + (size_t)r * N;
                    if (RESID) {
                        float2 old = *(float2*)(orow + col);
                        v0 += old.x; v1 += old.y;
                    }
                    *(float2*)(orow + col) = make_float2(v0, v1);
                }
            }
        }
    }
}

// ========== batched prep: ALL weights + node activations in ONE launch ==========
__global__ __launch_bounds__(256) void prep_all(
    const float* __restrict__ node,
    const float* __restrict__ W_proj, const float* __restrict__ W_in,
    const float* __restrict__ W_gate, const float* __restrict__ W_out,
    const float* __restrict__ W_ff1,  const float* __restrict__ W_ff2,
    __nv_bfloat16* __restrict__ o_node, __nv_bfloat16* __restrict__ o_proj,
    __half* __restrict__ o_in, __half* __restrict__ o_gate,
    __half* __restrict__ o_out, __half* __restrict__ o_ff1,
    __half* __restrict__ o_ff2)
{
    const int z = blockIdx.z;
    const int nidx = blockIdx.x * 32 + (threadIdx.x & 31);
    const int k0 = blockIdx.y * 128 + (threadIdx.x >> 5) * 16;

    if (z == 5 * NL + 1) {
        if (nidx >= LSEQ || k0 >= DIN) return;
        const float* xr = node + (size_t)nidx * DIN;
        __nv_bfloat16* orow = o_node + (size_t)nidx * 2 * DIN;
#pragma unroll
        for (int i = 0; i < 16; i++) {
            __nv_bfloat16 hi, lo;
            split_bf16(xr[k0 + i], hi, lo);
            orow[k0 + i]       = hi;
            orow[DIN + k0 + i] = lo;
        }
        return;
    }

    const float* W; int K, N;
    if (z == 5 * NL) { W = W_proj; K = DIN; N = DD; }
    else {
        const int l = z / 5, t = z - l * 5;
        switch (t) {
            case 0: W = W_in   + (size_t)l * DD * DD; K = DD; N = DD; break;
            case 1: W = W_gate + (size_t)l * DD * DD; K = DD; N = DD; break;
            case 2: W = W_out  + (size_t)l * DD * DD; K = DD; N = DD; break;
            case 3: W = W_ff1  + (size_t)l * DD * D2; K = DD; N = D2; break;
            default:W = W_ff2  + (size_t)l * D2 * DD; K = D2; N = DD; break;
        }
    }
    if (nidx >= N || k0 >= K) return;

    if (z < 5 * NL) {
        const int l = z / 5, t = z - l * 5;
        __half* orow;
        if (t == 0)      orow = o_in   + (size_t)l * DD * DD + (size_t)nidx * DD;
        else if (t == 1) orow = o_gate + (size_t)l * DD * DD + (size_t)nidx * DD;
        else if (t == 2) orow = o_out  + (size_t)l * DD * DD + (size_t)nidx * DD;
        else if (t == 3) orow = o_ff1  + (size_t)l * D2 * DD + (size_t)nidx * DD;
        else             orow = o_ff2  + (size_t)l * DD * D2 + (size_t)nidx * D2;
#pragma unroll
        for (int i = 0; i < 16; i++)
            orow[k0 + i] = __float2half_rn(W[(size_t)(k0 + i) * N + nidx]);
    } else {
        __nv_bfloat16* orow = o_proj + (size_t)nidx * 2 * K;
#pragma unroll
        for (int i = 0; i < 16; i++) {
            __nv_bfloat16 hi, lo;
            split_bf16(W[(size_t)(k0 + i) * N + nidx], hi, lo);
            orow[k0 + i]     = hi;
            orow[K + k0 + i] = lo;
        }
    }
}

// ================= LayerNorm -> single fp16 [L, DD] =============================
__global__ __launch_bounds__(256) void ln_f16_kernel(
    const float* __restrict__ x, const float* __restrict__ gam,
    const float* __restrict__ bet, __half* __restrict__ out)
{
    __shared__ float red[8];
    __shared__ float bcast;
    const int tid = threadIdx.x;
    const float* xr = x + (size_t)blockIdx.x * DD;

    float v0 = xr[tid], v1 = xr[tid + 256], v2 = xr[tid + 512];
    float sum = v0 + v1 + v2;
#pragma unroll
    for (int o = 16; o > 0; o >>= 1) sum += __shfl_xor_sync(0xffffffffu, sum, o);
    if ((tid & 31) == 0) red[tid >> 5] = sum;
    __syncthreads();
    if (tid == 0) {
        float t = 0.f;
#pragma unroll
        for (int i = 0; i < 8; i++) t += red[i];
        bcast = t * (1.0f / DD);
    }
    __syncthreads();
    const float mu = bcast;
    float d0 = v0 - mu, d1 = v1 - mu, d2 = v2 - mu;
    float sq = d0 * d0 + d1 * d1 + d2 * d2;
#pragma unroll
    for (int o = 16; o > 0; o >>= 1) sq += __shfl_xor_sync(0xffffffffu, sq, o);
    __syncthreads();
    if ((tid & 31) == 0) red[tid >> 5] = sq;
    __syncthreads();
    if (tid == 0) {
        float t = 0.f;
#pragma unroll
        for (int i = 0; i < 8; i++) t += red[i];
        bcast = rsqrtf(t * (1.0f / DD) + 1e-5f);
    }
    __syncthreads();
    const float inv = bcast;

    __half* orow = out + (size_t)blockIdx.x * DD;
    orow[tid]       = __float2half_rn(d0 * inv * gam[tid]       + bet[tid]);
    orow[tid + 256] = __float2half_rn(d1 * inv * gam[tid + 256] + bet[tid + 256]);
    orow[tid + 512] = __float2half_rn(d2 * inv * gam[tid + 512] + bet[tid + 512]);
}

// ================= final LayerNorm (fp32 out) ===================================
__global__ __launch_bounds__(256) void ln_final_kernel(
    const float* __restrict__ x, const float* __restrict__ gam,
    const float* __restrict__ bet, float* __restrict__ out)
{
    __shared__ float red[8];
    __shared__ float bcast;
    const int tid = threadIdx.x;
    const float* xr = x + (size_t)blockIdx.x * DD;

    float v0 = xr[tid], v1 = xr[tid + 256], v2 = xr[tid + 512];
    float sum = v0 + v1 + v2;
#pragma unroll
    for (int o = 16; o > 0; o >>= 1) sum += __shfl_xor_sync(0xffffffffu, sum, o);
    if ((tid & 31) == 0) red[tid >> 5] = sum;
    __syncthreads();
    if (tid == 0) {
        float t = 0.f;
#pragma unroll
        for (int i = 0; i < 8; i++) t += red[i];
        bcast = t * (1.0f / DD);
    }
    __syncthreads();
    const float mu = bcast;
    float d0 = v0 - mu, d1 = v1 - mu, d2 = v2 - mu;
    float sq = d0 * d0 + d1 * d1 + d2 * d2;
#pragma unroll
    for (int o = 16; o > 0; o >>= 1) sq += __shfl_xor_sync(0xffffffffu, sq, o);
    __syncthreads();
    if ((tid & 31) == 0) red[tid >> 5] = sq;
    __syncthreads();
    if (tid == 0) {
        float t = 0.f;
#pragma unroll
        for (int i = 0; i < 8; i++) t += red[i];
        bcast = rsqrtf(t * (1.0f / DD) + 1e-5f);
    }
    __syncthreads();
    const float inv = bcast;

    float* orow = out + (size_t)blockIdx.x * DD;
    orow[tid]       = d0 * inv * gam[tid]       + bet[tid];
    orow[tid + 256] = d1 * inv * gam[tid + 256] + bet[tid + 256];
    orow[tid + 512] = d2 * inv * gam[tid + 512] + bet[tid + 512];
}

// ================= scan kernels =================================================
__global__ __launch_bounds__(256) void scan_chunk_kernel(
    const float* __restrict__ u, const float* __restrict__ dlogit,
    float* __restrict__ Sout)
{
    const int d = blockIdx.x * 256 + threadIdx.x;
    const int c = blockIdx.y;
    const float decay = sigmoidf_(dlogit[d]);
    const float* p = u + ((size_t)c * CLEN) * DD + d;
    float s = 0.0f;
#pragma unroll 8
    for (int t = 0; t < CLEN; t++) s = fmaf(decay, s, p[(size_t)t * DD]);
    Sout[c * DD + d] = s;
}

__global__ __launch_bounds__(768) void scan_carry_kernel(
    const float* __restrict__ Sin, const float* __restrict__ dlogit,
    float* __restrict__ carry)
{
    const int d = threadIdx.x;
    const float decay = sigmoidf_(dlogit[d]);
    float A = decay;
#pragma unroll
    for (int i = 0; i < 7; i++) A = A * A;   // decay^128
    float c = 0.0f;
    for (int k = 0; k < NCHUNK; k++) {
        carry[k * DD + d] = c;
        c = fmaf(A, c, Sin[k * DD + d]);
    }
}

// re-scan with carry, gate-multiply, emit single fp16 [L, DD]
__global__ __launch_bounds__(256) void scan_apply_f16_kernel(
    const float* __restrict__ u, const float* __restrict__ gate,
    const float* __restrict__ dlogit, const float* __restrict__ carry,
    __half* __restrict__ out)
{
    const int d = blockIdx.x * 256 + threadIdx.x;
    const int c = blockIdx.y;
    const float decay = sigmoidf_(dlogit[d]);
    const size_t base = ((size_t)c * CLEN) * DD + d;
    float s = carry[c * DD + d];
#pragma unroll 4
    for (int t = 0; t < CLEN; t++) {
        const size_t idx = base + (size_t)t * DD;
        s = fmaf(decay, s, u[idx]);
        out[idx] = __float2half_rn(s * gate[idx]);
    }
}

// ================= host =========================================================
extern "C" void kernel_launch(void* const* d_in, const int* in_sizes, int n_in,
                              void* d_out, int out_size)
{
    const float* node    = (const float*)d_in[0];
    const float* W_proj  = (const float*)d_in[1];
    const float* b_proj  = (const float*)d_in[2];
    const float* ln_s_g  = (const float*)d_in[3];
    const float* ln_s_b  = (const float*)d_in[4];
    const float* W_in    = (const float*)d_in[5];
    const float* b_in    = (const float*)d_in[6];
    const float* W_gate  = (const float*)d_in[7];
    const float* b_gate  = (const float*)d_in[8];
    const float* W_out   = (const float*)d_in[9];
    const float* b_out   = (const float*)d_in[10];
    const float* dlogit  = (const float*)d_in[11];
    const float* ln_f_g  = (const float*)d_in[12];
    const float* ln_f_b  = (const float*)d_in[13];
    const float* W_ff1   = (const float*)d_in[14];
    const float* b_ff1   = (const float*)d_in[15];
    const float* W_ff2   = (const float*)d_in[16];
    const float* b_ff2   = (const float*)d_in[17];
    const float* ln_o_g  = (const float*)d_in[18];
    const float* ln_o_b  = (const float*)d_in[19];

    float *x, *u, *gate, *S, *carry;
    __nv_bfloat16 *a_node, *w_proj;
    __half *a_h2, *a_sf, *a_hf, *a_t, *w_i, *w_gt, *w_ot, *w_f1, *w_f2;
    cudaGetSymbolAddress((void**)&x,     g_x);
    cudaGetSymbolAddress((void**)&u,     g_u);
    cudaGetSymbolAddress((void**)&gate,  g_gate);
    cudaGetSymbolAddress((void**)&S,     g_S);
    cudaGetSymbolAddress((void**)&carry, g_carry);
    cudaGetSymbolAddress((void**)&a_node, ab_node);
    cudaGetSymbolAddress((void**)&a_h2,   ah_h2);
    cudaGetSymbolAddress((void**)&a_sf,   ah_s);
    cudaGetSymbolAddress((void**)&a_hf,   ah_hf);
    cudaGetSymbolAddress((void**)&a_t,    ah_t);
    cudaGetSymbolAddress((void**)&w_proj, wb_proj);
    cudaGetSymbolAddress((void**)&w_i,    wh_in);
    cudaGetSymbolAddress((void**)&w_gt,   wh_gate);
    cudaGetSymbolAddress((void**)&w_ot,   wh_out);
    cudaGetSymbolAddress((void**)&w_f1,   wh_ff1);
    cudaGetSymbolAddress((void**)&w_f2,   wh_ff2);

    cudaFuncSetAttribute(tc_gemm<0, false>, cudaFuncAttributeMaxDynamicSharedMemorySize, GEMM_SMEM_BYTES);
    cudaFuncSetAttribute(tc_gemm1<0, false, false>, cudaFuncAttributeMaxDynamicSharedMemorySize, GEMM1_SMEM_BYTES);
    cudaFuncSetAttribute(tc_gemm1<1, false, false>, cudaFuncAttributeMaxDynamicSharedMemorySize, GEMM1_SMEM_BYTES);
    cudaFuncSetAttribute(tc_gemm1<2, false, true >, cudaFuncAttributeMaxDynamicSharedMemorySize, GEMM1_SMEM_BYTES);
    cudaFuncSetAttribute(tc_gemm1<0, true,  false>, cudaFuncAttributeMaxDynamicSharedMemorySize, GEMM1_SMEM_BYTES);

    const dim3 blk(256);
    const dim3 gScan(DD / 256, NCHUNK);
    const dim3 gG6  (DD / 128, LSEQ / 64);    // 64-row tiles, N=768
    const dim3 gG12 (D2 / 128, LSEQ / 64);    // 64-row tiles, N=1536

    // ---- launch 0: ALL prep (weights + node) ----
    prep_all<<<dim3(512, 12, 5 * NL + 2), blk>>>(
        node, W_proj, W_in, W_gate, W_out, W_ff1, W_ff2,
        a_node, w_proj, w_i, w_gt, w_ot, w_f1, w_f2);

    // ---- launch 1: x = node @ W_proj + b_proj (3-pass bf16) ----
    tc_gemm<0, false><<<gG6, blk, GEMM_SMEM_BYTES>>>(
        a_node, w_proj, b_proj, x, DIN, DD);

    for (int l = 0; l < NL; l++) {
        const size_t vo = (size_t)l * DD;
        const size_t v1 = (size_t)l * D2;
        const __half* wi = w_i  + (size_t)l * DD * DD;
        const __half* wg = w_gt + (size_t)l * DD * DD;
        const __half* wo = w_ot + (size_t)l * DD * DD;
        const __half* w1 = w_f1 + (size_t)l * D2 * DD;
        const __half* w2 = w_f2 + (size_t)l * DD * D2;

        ln_f16_kernel<<<LSEQ, blk>>>(x, ln_s_g + vo, ln_s_b + vo, a_h2);
        tc_gemm1<0, false, false><<<gG6, blk, GEMM1_SMEM_BYTES>>>(
            a_h2, wi, b_in + vo, u, nullptr, DD, DD);
        tc_gemm1<1, false, false><<<gG6, blk, GEMM1_SMEM_BYTES>>>(
            a_h2, wg, b_gate + vo, gate, nullptr, DD, DD);
        scan_chunk_kernel<<<gScan, blk>>>(u, dlogit + vo, S);
        scan_carry_kernel<<<1, DD>>>(S, dlogit + vo, carry);
        scan_apply_f16_kernel<<<gScan, blk>>>(u, gate, dlogit + vo, carry, a_sf);
        tc_gemm1<0, true, false><<<gG6, blk, GEMM1_SMEM_BYTES>>>(
            a_sf, wo, b_out + vo, x, nullptr, DD, DD);
        ln_f16_kernel<<<LSEQ, blk>>>(x, ln_f_g + vo, ln_f_b + vo, a_hf);
        tc_gemm1<2, false, true><<<gG12, blk, GEMM1_SMEM_BYTES>>>(
            a_hf, w1, b_ff1 + v1, nullptr, a_t, DD, D2);
        tc_gemm1<0, true, false><<<gG6, blk, GEMM1_SMEM_BYTES>>>(
            a_t, w2, b_ff2 + vo, x, nullptr, D2, DD);
    }

    ln_final_kernel<<<LSEQ, blk>>>(x, ln_o_g, ln_o_b, (float*)d_out);
}